// round 6
// baseline (speedup 1.0000x reference)
#include <cuda_runtime.h>
#include <math.h>
#include <stdint.h>

// ---------------------------------------------------------------------------
// Problem constants
// ---------------------------------------------------------------------------
constexpr int B    = 4;
constexpr int N    = 2048;
constexpr int D    = 1024;
constexpr int E    = 24;
constexpr int H    = 8;
constexpr int HD   = 128;
constexpr int BN_TOK = B * N;          // 8192 tokens
constexpr int NSLOT  = BN_TOK * H;     // 65536 (token,slot) pairs

// Grouped-GEMM tiling
constexpr int TQ = 128;                // rows per expert tile
constexpr int NT_MAX = NSLOT / TQ + E; // 536 max tiles

// ---------------------------------------------------------------------------
// Scratch (device globals — no allocations allowed)
// ---------------------------------------------------------------------------
__device__ float g_kT[HD * BN_TOK];            // 4 MB  K^T: [hd][token]
__device__ float g_v[BN_TOK * HD];             // 4 MB
__device__ float g_q[NSLOT * HD];              // 32 MB  [slot][hd], slot=token*8+h
__device__ float g_attno[NSLOT * HD];          // 32 MB
__device__ float g_ws[(size_t)NSLOT * D];      // 268 MB combine scratch [slot][D]
__device__ int   g_topi[NSLOT];
__device__ float g_gates[NSLOT];
__device__ float g_aux[2 * E + 1];
// expert bucketing
__device__ int g_ecnt[E];
__device__ int g_eoff[E + 1];
__device__ int g_ecursor[E];
__device__ int g_slots[NSLOT];
__device__ int g_tile_e[NT_MAX];
__device__ int g_tile_r0[NT_MAX];
__device__ int g_ntiles;

// ---------------------------------------------------------------------------
// tf32 mma helpers
// ---------------------------------------------------------------------------
__device__ __forceinline__ void mma_tf32(float* d, const uint32_t* a, const uint32_t* b) {
    asm volatile(
        "mma.sync.aligned.m16n8k8.row.col.f32.tf32.tf32.f32 "
        "{%0,%1,%2,%3}, {%4,%5,%6,%7}, {%8,%9}, {%0,%1,%2,%3};\n"
        : "+f"(d[0]), "+f"(d[1]), "+f"(d[2]), "+f"(d[3])
        : "r"(a[0]), "r"(a[1]), "r"(a[2]), "r"(a[3]), "r"(b[0]), "r"(b[1]));
}
__device__ __forceinline__ uint32_t fu(float x) { return __float_as_uint(x); }
__device__ __forceinline__ float tf32_hi(float x) {
    uint32_t u;
    asm("cvt.rna.tf32.f32 %0, %1;" : "=r"(u) : "f"(x));
    return __uint_as_float(u);
}
__device__ __forceinline__ void split4(const float* a, uint32_t* ah, uint32_t* al) {
#pragma unroll
    for (int j = 0; j < 4; j++) {
        float h = tf32_hi(a[j]);
        ah[j] = fu(h);
        al[j] = fu(a[j] - h);
    }
}
__device__ __forceinline__ void split2(float b0, float b1, uint32_t* bh, uint32_t* bl) {
    float h0 = tf32_hi(b0), h1 = tf32_hi(b1);
    bh[0] = fu(h0); bh[1] = fu(h1);
    bl[0] = fu(b0 - h0); bl[1] = fu(b1 - h1);
}
__device__ __forceinline__ void mma3(float* d, const uint32_t* ah, const uint32_t* al,
                                     const uint32_t* bh, const uint32_t* bl) {
    mma_tf32(d, al, bh);
    mma_tf32(d, ah, bl);
    mma_tf32(d, ah, bh);
}

// ---------------------------------------------------------------------------
// Kernel 0: zero aux + expert histogram
// ---------------------------------------------------------------------------
__global__ void init_aux_kernel() {
    int tid = threadIdx.x;
    if (tid < 2 * E + 1) g_aux[tid] = 0.f;
    if (tid < E) g_ecnt[tid] = 0;
}

// ---------------------------------------------------------------------------
// Kernel 1: gating
// ---------------------------------------------------------------------------
__global__ __launch_bounds__(256) void gating_kernel(
    const float* __restrict__ x, const int* __restrict__ task_bh,
    const float* __restrict__ Wg)
{
    __shared__ float s_aux[2 * E + 1];
    __shared__ int   s_ecnt[E];
    int tid = threadIdx.x;
    if (tid < 2 * E + 1) s_aux[tid] = 0.f;
    if (tid < E) s_ecnt[tid] = 0;
    __syncthreads();

    int warp = tid >> 5, lane = tid & 31;
    int t = blockIdx.x * 8 + warp;
    int b = t >> 11;
    int task = task_bh[b];
    const float* xrow = x + (size_t)t * D;
    const float* wg   = Wg + (size_t)task * D * E;

    float acc[E];
#pragma unroll
    for (int e = 0; e < E; e++) acc[e] = 0.f;

    for (int i = lane; i < D; i += 32) {
        float xv = xrow[i];
        const float4* w4 = reinterpret_cast<const float4*>(wg + (size_t)i * E);
#pragma unroll
        for (int j = 0; j < 6; j++) {
            float4 v = w4[j];
            acc[4*j+0] += xv * v.x; acc[4*j+1] += xv * v.y;
            acc[4*j+2] += xv * v.z; acc[4*j+3] += xv * v.w;
        }
    }
#pragma unroll
    for (int e = 0; e < E; e++) {
#pragma unroll
        for (int off = 16; off >= 1; off >>= 1)
            acc[e] += __shfl_xor_sync(0xffffffffu, acc[e], off);
    }
    float mx = acc[0];
#pragma unroll
    for (int e = 1; e < E; e++) mx = fmaxf(mx, acc[e]);
    float p[E]; float s = 0.f;
#pragma unroll
    for (int e = 0; e < E; e++) { p[e] = __expf(acc[e] - mx); s += p[e]; }
    float inv_s = 1.f / s;
    float lse = mx + __logf(s);

    if (lane < E) atomicAdd(&s_aux[E + lane], p[lane] * inv_s);
    if (lane == 0) {
        atomicAdd(&s_aux[2 * E], lse * lse);
        float tv[H]; int ti[H]; float gsum = 0.f;
#pragma unroll
        for (int h = 0; h < H; h++) {
            float best = -1.f; int bi = 0;
#pragma unroll
            for (int e = 0; e < E; e++)
                if (p[e] > best) { best = p[e]; bi = e; }
            tv[h] = best * inv_s; ti[h] = bi; p[bi] = -2.f;
            gsum += tv[h];
            atomicAdd(&s_aux[bi], 1.0f);
            atomicAdd(&s_ecnt[bi], 1);
        }
        float ig = 1.f / gsum;
#pragma unroll
        for (int h = 0; h < H; h++) {
            g_topi[t * H + h]  = ti[h];
            g_gates[t * H + h] = tv[h] * ig;
        }
    }
    __syncthreads();
    if (tid < 2 * E + 1) atomicAdd(&g_aux[tid], s_aux[tid]);
    if (tid < E) atomicAdd(&g_ecnt[tid], s_ecnt[tid]);
}

// ---------------------------------------------------------------------------
// Kernel 2: serial scan over experts → offsets + tile table
// ---------------------------------------------------------------------------
__global__ void scan_kernel() {
    if (threadIdx.x == 0) {
        int off = 0, nt = 0;
        for (int e = 0; e < E; e++) {
            g_eoff[e] = off;
            g_ecursor[e] = 0;
            int c = g_ecnt[e];
            for (int r = 0; r < c; r += TQ) {
                g_tile_e[nt]  = e;
                g_tile_r0[nt] = off + r;
                nt++;
            }
            off += c;
        }
        g_eoff[E] = off;
        g_ntiles = nt;
    }
}

// ---------------------------------------------------------------------------
// Kernel 3: scatter slot ids into expert buckets
// ---------------------------------------------------------------------------
__global__ void scatter_kernel() {
    int i = blockIdx.x * 256 + threadIdx.x;
    int e = g_topi[i];
    int pos = atomicAdd(&g_ecursor[e], 1);
    g_slots[g_eoff[e] + pos] = i;
}

// ---------------------------------------------------------------------------
// Kernel 4: kv = x @ Wkv + bkv  → g_kT (transposed), g_v
// ---------------------------------------------------------------------------
__global__ __launch_bounds__(256) void kv_kernel(
    const float* __restrict__ x, const float* __restrict__ Wkv,
    const float* __restrict__ bkv)
{
    __shared__ float As[64][17];
    __shared__ float Bs[16][64];
    int tid = threadIdx.x;
    int tx = tid & 15, ty = tid >> 4;
    int t0 = blockIdx.x * 64;
    int n0 = blockIdx.y * 64;

    float acc[4][4] = {};

    for (int k0 = 0; k0 < D; k0 += 16) {
#pragma unroll
        for (int i = 0; i < 4; i++) {
            int idx = tid + i * 256;
            int r = idx >> 4, kk = idx & 15;
            As[r][kk] = x[(size_t)(t0 + r) * D + k0 + kk];
        }
#pragma unroll
        for (int i = 0; i < 4; i++) {
            int idx = tid + i * 256;
            int kr = idx >> 6, nn = idx & 63;
            Bs[kr][nn] = Wkv[(size_t)(k0 + kr) * (2 * HD) + n0 + nn];
        }
        __syncthreads();
#pragma unroll
        for (int kk = 0; kk < 16; kk++) {
            float a[4];
#pragma unroll
            for (int i = 0; i < 4; i++) a[i] = As[ty * 4 + i][kk];
            float4 bv = *reinterpret_cast<const float4*>(&Bs[kk][tx * 4]);
            float bb[4] = {bv.x, bv.y, bv.z, bv.w};
#pragma unroll
            for (int i = 0; i < 4; i++)
#pragma unroll
                for (int j = 0; j < 4; j++)
                    acc[i][j] += a[i] * bb[j];
        }
        __syncthreads();
    }
#pragma unroll
    for (int i = 0; i < 4; i++) {
        int t = t0 + ty * 4 + i;
#pragma unroll
        for (int j = 0; j < 4; j++) {
            int c = n0 + tx * 4 + j;
            float v = acc[i][j] + bkv[c];
            if (c < HD) g_kT[(size_t)c * BN_TOK + t] = v;
            else        g_v[(size_t)t * HD + (c - HD)] = v;
        }
    }
}

// ---------------------------------------------------------------------------
// Kernel 5: grouped q GEMM — 3xTF32 (feeds exp; keep compensated)
// ---------------------------------------------------------------------------
constexpr int GBK = 32;
constexpr int AS_STR = 36;
constexpr int BS_STR = 136;

__global__ __launch_bounds__(256, 2) void qgemm_kernel(
    const float* __restrict__ x, const float* __restrict__ Wq)
{
    __shared__ float As[TQ * AS_STR];
    __shared__ float Bs[GBK * BS_STR];
    __shared__ int   s_tok[TQ];
    __shared__ int   s_slot[TQ];

    int t = blockIdx.x;
    if (t >= g_ntiles) return;
    int e = g_tile_e[t], r0 = g_tile_r0[t];
    int rend = g_eoff[e + 1];
    int tid = threadIdx.x;

    if (tid < TQ) {
        int gr = r0 + tid;
        if (gr >= rend) gr = r0;
        int s = g_slots[gr];
        s_slot[tid] = s;
        s_tok[tid]  = s >> 3;
    }
    __syncthreads();

    int warp = tid >> 5, lane = tid & 31;
    int g = lane >> 2, tg = lane & 3;
    int r_a = warp * 16 + g, r_b = r_a + 8;
    const float* wq = Wq + (size_t)e * D * HD;

    float acc[16][4] = {};

    for (int k0 = 0; k0 < D; k0 += GBK) {
#pragma unroll
        for (int i = 0; i < 4; i++) {
            int f4 = tid + i * 256;
            int r = f4 >> 3, c = (f4 & 7) * 4;
            *reinterpret_cast<float4*>(As + r * AS_STR + c) =
                *reinterpret_cast<const float4*>(x + (size_t)s_tok[r] * D + k0 + c);
        }
#pragma unroll
        for (int i = 0; i < 4; i++) {
            int f4 = tid + i * 256;
            int kr = f4 >> 5, c = (f4 & 31) * 4;
            *reinterpret_cast<float4*>(Bs + kr * BS_STR + c) =
                *reinterpret_cast<const float4*>(wq + (size_t)(k0 + kr) * HD + c);
        }
        __syncthreads();
#pragma unroll
        for (int ks = 0; ks < 4; ks++) {
            int krow = 8 * ks + tg;
            float a_raw[4] = { As[r_a * AS_STR + krow], As[r_b * AS_STR + krow],
                               As[r_a * AS_STR + krow + 4], As[r_b * AS_STR + krow + 4] };
            uint32_t ah[4], al[4];
            split4(a_raw, ah, al);
            const float* b0p = Bs + krow * BS_STR + g;
            const float* b1p = b0p + 4 * BS_STR;
#pragma unroll
            for (int nc = 0; nc < 16; nc++) {
                uint32_t bh[2], bl[2];
                split2(b0p[8 * nc], b1p[8 * nc], bh, bl);
                mma3(acc[nc], ah, al, bh, bl);
            }
        }
        __syncthreads();
    }

    bool va = (r0 + r_a < rend), vb = (r0 + r_b < rend);
    float* da = g_q + (size_t)s_slot[r_a] * HD;
    float* db = g_q + (size_t)s_slot[r_b] * HD;
#pragma unroll
    for (int nc = 0; nc < 16; nc++) {
        int c = 8 * nc + 2 * tg;
        if (va) *reinterpret_cast<float2*>(da + c) = make_float2(acc[nc][0], acc[nc][1]);
        if (vb) *reinterpret_cast<float2*>(db + c) = make_float2(acc[nc][2], acc[nc][3]);
    }
}

// ---------------------------------------------------------------------------
// Kernel 6: flash attention — QT=64 q rows, KT=32 kv cols, 256 threads.
// warp w: row-group (w&3) [16 rows], half (w>>2).
//   QK: warp computes S[16 rows][16 kv] (its kv half),   3xTF32
//   PV: warp computes O[16 rows][64 hd] (its hd half),   1xTF32
// smem ~80KB → 2 CTAs/SM → 4 warps/SMSP.
// ---------------------------------------------------------------------------
constexpr int QT = 64;
constexpr int KT = 32;
constexpr int QS_STRIDE = 132;   // Qs [row 64][hd 128+pad]
constexpr int KS_STRIDE = 40;    // Ks [hd 128][kv 32+pad]  (K^T)
constexpr int VS_STRIDE = 136;   // Vs [kv 32][hd 128+pad]
constexpr int PS_STRIDE = 36;    // Ps [row 64][kv 32+pad]

__global__ __launch_bounds__(256, 2) void attn_kernel()
{
    extern __shared__ float sm[];
    float* Qs    = sm;                       // 64*132   = 8448
    float* Ks    = Qs + QT * QS_STRIDE;      // 128*40   = 5120
    float* Vs    = Ks + HD * KS_STRIDE;      // 32*136   = 4352
    float* Ps    = Vs + KT * VS_STRIDE;      // 64*36    = 2304
    float* sRedM = Ps + QT * PS_STRIDE;      // 64*2     = 128
    float* sRedS = sRedM + QT * 2;           // 64*2     = 128

    int tid  = threadIdx.x;
    int warp = tid >> 5, lane = tid & 31;
    int g = lane >> 2, tg = lane & 3;
    int wg   = warp & 3;      // row group
    int half = warp >> 2;     // kv half (QK) / hd half (PV)
    int n0 = blockIdx.x * QT;
    int h  = blockIdx.y;
    int b  = blockIdx.z;
    int bN0 = b * N;
    const float scale = 0.08838834764831845f;   // 1/sqrt(128)

    // load Q (pre-scaled) once: 64 rows x 128
    for (int idx = tid; idx < QT * (HD / 4); idx += 256) {
        int r = idx >> 5, kq = (idx & 31) * 4;
        float4 qv = *reinterpret_cast<const float4*>(
            g_q + (((size_t)(bN0 + n0 + r)) * H + h) * HD + kq);
        qv.x *= scale; qv.y *= scale; qv.z *= scale; qv.w *= scale;
        *reinterpret_cast<float4*>(Qs + r * QS_STRIDE + kq) = qv;
    }

    const int r_a = wg * 16 + g;      // 0..63
    const int r_b = r_a + 8;

    float o[8][4];
#pragma unroll
    for (int nc = 0; nc < 8; nc++)
#pragma unroll
        for (int j = 0; j < 4; j++) o[nc][j] = 0.f;
    float m_a = -1e30f, m_b = -1e30f, l_a = 0.f, l_b = 0.f;

    for (int m0 = 0; m0 < N; m0 += KT) {
        __syncthreads();   // prev tile fully consumed (also covers Q load)
        // K^T tile: Ks[hd][kv 32]
        for (int idx = tid; idx < HD * (KT / 4); idx += 256) {
            int k = idx >> 3, mq = (idx & 7) * 4;
            *reinterpret_cast<float4*>(Ks + k * KS_STRIDE + mq) =
                *reinterpret_cast<const float4*>(g_kT + (size_t)k * BN_TOK + bN0 + m0 + mq);
        }
        // V tile: Vs[kv 32][hd 128], cvt to tf32 at store (PV is 1x)
        for (int idx = tid; idx < KT * (HD / 4); idx += 256) {
            int mr = idx >> 5, kq = (idx & 31) * 4;
            float4 vv = *reinterpret_cast<const float4*>(
                g_v + ((size_t)(bN0 + m0 + mr)) * HD + kq);
            vv.x = tf32_hi(vv.x); vv.y = tf32_hi(vv.y);
            vv.z = tf32_hi(vv.z); vv.w = tf32_hi(vv.w);
            *reinterpret_cast<float4*>(Vs + mr * VS_STRIDE + kq) = vv;
        }
        __syncthreads();

        // ---- S = Q K^T : 16 rows x 16 kv (2 nc) per warp, 3xtf32 ----
        float sc[2][4];
#pragma unroll
        for (int nc = 0; nc < 2; nc++)
#pragma unroll
            for (int j = 0; j < 4; j++) sc[nc][j] = 0.f;

#pragma unroll
        for (int ks = 0; ks < 16; ks++) {
            const float* qa0 = Qs + r_a * QS_STRIDE + 8 * ks + tg;
            const float* qa1 = Qs + r_b * QS_STRIDE + 8 * ks + tg;
            float a_raw[4] = { qa0[0], qa1[0], qa0[4], qa1[4] };
            uint32_t ah[4], al[4];
            split4(a_raw, ah, al);
            const float* kb0 = Ks + (8 * ks + tg) * KS_STRIDE + half * 16 + g;
            const float* kb1 = kb0 + 4 * KS_STRIDE;
#pragma unroll
            for (int nc = 0; nc < 2; nc++) {
                uint32_t bh[2], bl[2];
                split2(kb0[8 * nc], kb1[8 * nc], bh, bl);
                mma3(sc[nc], ah, al, bh, bl);
            }
        }

        // ---- partial row max over this warp's 16 kv cols ----
        float pm_a = fmaxf(fmaxf(sc[0][0], sc[0][1]), fmaxf(sc[1][0], sc[1][1]));
        float pm_b = fmaxf(fmaxf(sc[0][2], sc[0][3]), fmaxf(sc[1][2], sc[1][3]));
#pragma unroll
        for (int off = 1; off <= 2; off <<= 1) {
            pm_a = fmaxf(pm_a, __shfl_xor_sync(0xffffffffu, pm_a, off));
            pm_b = fmaxf(pm_b, __shfl_xor_sync(0xffffffffu, pm_b, off));
        }
        if (tg == 0) {
            sRedM[r_a * 2 + half] = pm_a;
            sRedM[r_b * 2 + half] = pm_b;
        }
        __syncthreads();
        float lm_a = fmaxf(pm_a, sRedM[r_a * 2 + (half ^ 1)]);
        float lm_b = fmaxf(pm_b, sRedM[r_b * 2 + (half ^ 1)]);

        float mn_a = fmaxf(m_a, lm_a), mn_b = fmaxf(m_b, lm_b);
        float al_a = __expf(m_a - mn_a), al_b = __expf(m_b - mn_b);
        m_a = mn_a; m_b = mn_b;

        // ---- exp, write P (tf32-rounded), partial row sums ----
        float rs_a = 0.f, rs_b = 0.f;
#pragma unroll
        for (int nc = 0; nc < 2; nc++) {
            float p0 = __expf(sc[nc][0] - mn_a);
            float p1 = __expf(sc[nc][1] - mn_a);
            float p2 = __expf(sc[nc][2] - mn_b);
            float p3 = __expf(sc[nc][3] - mn_b);
            rs_a += p0 + p1; rs_b += p2 + p3;
            int c = half * 16 + 8 * nc + 2 * tg;
            *reinterpret_cast<float2*>(Ps + r_a * PS_STRIDE + c) =
                make_float2(tf32_hi(p0), tf32_hi(p1));
            *reinterpret_cast<float2*>(Ps + r_b * PS_STRIDE + c) =
                make_float2(tf32_hi(p2), tf32_hi(p3));
        }
#pragma unroll
        for (int off = 1; off <= 2; off <<= 1) {
            rs_a += __shfl_xor_sync(0xffffffffu, rs_a, off);
            rs_b += __shfl_xor_sync(0xffffffffu, rs_b, off);
        }
        if (tg == 0) {
            sRedS[r_a * 2 + half] = rs_a;
            sRedS[r_b * 2 + half] = rs_b;
        }
        __syncthreads();   // P complete + sums visible
        rs_a += sRedS[r_a * 2 + (half ^ 1)];
        rs_b += sRedS[r_b * 2 + (half ^ 1)];
        l_a = l_a * al_a + rs_a;
        l_b = l_b * al_b + rs_b;
#pragma unroll
        for (int nc = 0; nc < 8; nc++) {
            o[nc][0] *= al_a; o[nc][1] *= al_a;
            o[nc][2] *= al_b; o[nc][3] *= al_b;
        }

        // ---- O += P V : warp's 64 hd cols, 1xtf32 ----
#pragma unroll
        for (int ks = 0; ks < 4; ks++) {
            const float* pa0 = Ps + r_a * PS_STRIDE + 8 * ks + tg;
            const float* pa1 = Ps + r_b * PS_STRIDE + 8 * ks + tg;
            uint32_t a[4] = { fu(pa0[0]), fu(pa1[0]), fu(pa0[4]), fu(pa1[4]) };
            const float* vb0 = Vs + (8 * ks + tg) * VS_STRIDE + half * 64 + g;
            const float* vb1 = vb0 + 4 * VS_STRIDE;
#pragma unroll
            for (int nc = 0; nc < 8; nc++) {
                uint32_t bb[2] = { fu(vb0[8 * nc]), fu(vb1[8 * nc]) };
                mma_tf32(o[nc], a, bb);
            }
        }
    }

    float inv_a = 1.f / l_a, inv_b = 1.f / l_b;
    float* dsta = g_attno + (((size_t)(bN0 + n0 + r_a)) * H + h) * HD + half * 64;
    float* dstb = g_attno + (((size_t)(bN0 + n0 + r_b)) * H + h) * HD + half * 64;
#pragma unroll
    for (int nc = 0; nc < 8; nc++) {
        *reinterpret_cast<float2*>(dsta + 8 * nc + 2 * tg) =
            make_float2(o[nc][0] * inv_a, o[nc][1] * inv_a);
        *reinterpret_cast<float2*>(dstb + 8 * nc + 2 * tg) =
            make_float2(o[nc][2] * inv_b, o[nc][3] * inv_b);
    }
}

// ---------------------------------------------------------------------------
// Kernel 7: grouped combine GEMM — single-pass tf32 (linear output path)
// ---------------------------------------------------------------------------
__global__ __launch_bounds__(256, 2) void cgemm_kernel(const float* __restrict__ Wo)
{
    __shared__ float As[TQ * AS_STR];
    __shared__ float Bs[GBK * BS_STR];
    __shared__ int   s_slot[TQ];
    __shared__ float s_gate[TQ];

    int t = blockIdx.x;
    if (t >= g_ntiles) return;
    int n0 = blockIdx.y * 128;
    int e = g_tile_e[t], r0 = g_tile_r0[t];
    int rend = g_eoff[e + 1];
    int tid = threadIdx.x;

    if (tid < TQ) {
        int gr = r0 + tid;
        if (gr >= rend) gr = r0;
        int s = g_slots[gr];
        s_slot[tid] = s;
        s_gate[tid] = g_gates[s];
    }
    __syncthreads();

    int warp = tid >> 5, lane = tid & 31;
    int g = lane >> 2, tg = lane & 3;
    int r_a = warp * 16 + g, r_b = r_a + 8;
    const float* wo = Wo + (size_t)e * HD * D;

    float acc[16][4] = {};

    for (int k0 = 0; k0 < HD; k0 += GBK) {
#pragma unroll
        for (int i = 0; i < 4; i++) {
            int f4 = tid + i * 256;
            int r = f4 >> 3, c = (f4 & 7) * 4;
            float4 av = *reinterpret_cast<const float4*>(
                g_attno + (size_t)s_slot[r] * HD + k0 + c);
            av.x = tf32_hi(av.x); av.y = tf32_hi(av.y);
            av.z = tf32_hi(av.z); av.w = tf32_hi(av.w);
            *reinterpret_cast<float4*>(As + r * AS_STR + c) = av;
        }
#pragma unroll
        for (int i = 0; i < 4; i++) {
            int f4 = tid + i * 256;
            int kr = f4 >> 5, c = (f4 & 31) * 4;
            float4 bv = *reinterpret_cast<const float4*>(
                wo + (size_t)(k0 + kr) * D + n0 + c);
            bv.x = tf32_hi(bv.x); bv.y = tf32_hi(bv.y);
            bv.z = tf32_hi(bv.z); bv.w = tf32_hi(bv.w);
            *reinterpret_cast<float4*>(Bs + kr * BS_STR + c) = bv;
        }
        __syncthreads();
#pragma unroll
        for (int ks = 0; ks < 4; ks++) {
            int krow = 8 * ks + tg;
            uint32_t a[4] = { fu(As[r_a * AS_STR + krow]), fu(As[r_b * AS_STR + krow]),
                              fu(As[r_a * AS_STR + krow + 4]), fu(As[r_b * AS_STR + krow + 4]) };
            const float* b0p = Bs + krow * BS_STR + g;
            const float* b1p = b0p + 4 * BS_STR;
#pragma unroll
            for (int nc = 0; nc < 16; nc++) {
                uint32_t bb[2] = { fu(b0p[8 * nc]), fu(b1p[8 * nc]) };
                mma_tf32(acc[nc], a, bb);
            }
        }
        __syncthreads();
    }

    bool va = (r0 + r_a < rend), vb = (r0 + r_b < rend);
    float ga = s_gate[r_a], gb = s_gate[r_b];
    float* da = g_ws + (size_t)s_slot[r_a] * D + n0;
    float* db = g_ws + (size_t)s_slot[r_b] * D + n0;
#pragma unroll
    for (int nc = 0; nc < 16; nc++) {
        int c = 8 * nc + 2 * tg;
        if (va) *reinterpret_cast<float2*>(da + c) = make_float2(acc[nc][0] * ga, acc[nc][1] * ga);
        if (vb) *reinterpret_cast<float2*>(db + c) = make_float2(acc[nc][2] * gb, acc[nc][3] * gb);
    }
}

// ---------------------------------------------------------------------------
// Kernel 8: reduce 8 slot rows per token → y
// ---------------------------------------------------------------------------
__global__ __launch_bounds__(256) void reduce_kernel(float* __restrict__ y)
{
    int t = blockIdx.x;
    int c = threadIdx.x * 4;
    float4 s = make_float4(0.f, 0.f, 0.f, 0.f);
#pragma unroll
    for (int h = 0; h < H; h++) {
        float4 v = *reinterpret_cast<const float4*>(g_ws + ((size_t)(t * H + h)) * D + c);
        s.x += v.x; s.y += v.y; s.z += v.z; s.w += v.w;
    }
    *reinterpret_cast<float4*>(y + (size_t)t * D + c) = s;
}

// ---------------------------------------------------------------------------
// Kernel 9: finalize aux loss
// ---------------------------------------------------------------------------
__global__ void aux_final_kernel(float* __restrict__ out) {
    if (threadIdx.x == 0) {
        const float inv_bn = 1.0f / (float)BN_TOK;
        float sw = 0.f;
        for (int e = 0; e < E; e++)
            sw += (g_aux[e] * inv_bn) * (g_aux[E + e] * inv_bn);
        float aux = 0.1f * (float)E * sw + 0.001f * (g_aux[2 * E] * inv_bn);
        out[(size_t)BN_TOK * D] = aux;
    }
}

// ---------------------------------------------------------------------------
// Launch
// ---------------------------------------------------------------------------
extern "C" void kernel_launch(void* const* d_in, const int* in_sizes, int n_in,
                              void* d_out, int out_size)
{
    const float* x    = (const float*)d_in[0];
    const int* task_bh = (const int*)d_in[1];
    const float* Wg   = (const float*)d_in[2];
    const float* Wq   = (const float*)d_in[3];
    const float* Wo   = (const float*)d_in[4];
    const float* Wkv  = (const float*)d_in[5];
    const float* bkv  = (const float*)d_in[6];
    float* out = (float*)d_out;

    const int attn_smem = (QT * QS_STRIDE + HD * KS_STRIDE + KT * VS_STRIDE +
                           QT * PS_STRIDE + 2 * QT * 2) * 4;
    cudaFuncSetAttribute(attn_kernel, cudaFuncAttributeMaxDynamicSharedMemorySize, attn_smem);

    init_aux_kernel<<<1, 64>>>();
    gating_kernel<<<BN_TOK / 8, 256>>>(x, task_bh, Wg);
    scan_kernel<<<1, 32>>>();
    scatter_kernel<<<NSLOT / 256, 256>>>();
    kv_kernel<<<dim3(BN_TOK / 64, (2 * HD) / 64), 256>>>(x, Wkv, bkv);
    qgemm_kernel<<<NT_MAX, 256>>>(x, Wq);
    attn_kernel<<<dim3(N / QT, H, B), 256, attn_smem>>>();
    cgemm_kernel<<<dim3(NT_MAX, 8), 256>>>(Wo);
    reduce_kernel<<<BN_TOK, 256>>>(out);
    aux_final_kernel<<<1, 32>>>(out);
}

// round 7
// speedup vs baseline: 1.1270x; 1.1270x over previous
#include <cuda_runtime.h>
#include <cuda_fp16.h>
#include <math.h>
#include <stdint.h>

// ---------------------------------------------------------------------------
// Problem constants
// ---------------------------------------------------------------------------
constexpr int B    = 4;
constexpr int N    = 2048;
constexpr int D    = 1024;
constexpr int E    = 24;
constexpr int H    = 8;
constexpr int HD   = 128;
constexpr int BN_TOK = B * N;          // 8192 tokens
constexpr int NSLOT  = BN_TOK * H;     // 65536 (token,slot) pairs

// Grouped-GEMM tiling
constexpr int TQ = 128;                // rows per expert tile
constexpr int NT_MAX = NSLOT / TQ + E; // 536 max tiles

// ---------------------------------------------------------------------------
// Scratch (device globals — no allocations allowed)
// ---------------------------------------------------------------------------
__device__ float g_kT[HD * BN_TOK];            // 4 MB  K^T: [hd][token]
__device__ float g_v[BN_TOK * HD];             // 4 MB
__device__ float g_q[NSLOT * HD];              // 32 MB  [slot][hd], slot=token*8+h
__device__ float g_attno[NSLOT * HD];          // 32 MB
__device__ float g_ws[(size_t)NSLOT * D];      // 268 MB combine scratch [slot][D]
__device__ int   g_topi[NSLOT];
__device__ float g_gates[NSLOT];
__device__ float g_aux[2 * E + 1];
// expert bucketing
__device__ int g_ecnt[E];
__device__ int g_eoff[E + 1];
__device__ int g_ecursor[E];
__device__ int g_slots[NSLOT];
__device__ int g_tile_e[NT_MAX];
__device__ int g_tile_r0[NT_MAX];
__device__ int g_ntiles;

// ---------------------------------------------------------------------------
// mma helpers
// ---------------------------------------------------------------------------
__device__ __forceinline__ void mma_tf32(float* d, const uint32_t* a, const uint32_t* b) {
    asm volatile(
        "mma.sync.aligned.m16n8k8.row.col.f32.tf32.tf32.f32 "
        "{%0,%1,%2,%3}, {%4,%5,%6,%7}, {%8,%9}, {%0,%1,%2,%3};\n"
        : "+f"(d[0]), "+f"(d[1]), "+f"(d[2]), "+f"(d[3])
        : "r"(a[0]), "r"(a[1]), "r"(a[2]), "r"(a[3]), "r"(b[0]), "r"(b[1]));
}
__device__ __forceinline__ void mma_f16(float* d, const uint32_t* a, const uint32_t* b) {
    asm volatile(
        "mma.sync.aligned.m16n8k16.row.col.f32.f16.f16.f32 "
        "{%0,%1,%2,%3}, {%4,%5,%6,%7}, {%8,%9}, {%0,%1,%2,%3};\n"
        : "+f"(d[0]), "+f"(d[1]), "+f"(d[2]), "+f"(d[3])
        : "r"(a[0]), "r"(a[1]), "r"(a[2]), "r"(a[3]), "r"(b[0]), "r"(b[1]));
}
__device__ __forceinline__ uint32_t fu(float x) { return __float_as_uint(x); }
__device__ __forceinline__ float tf32_hi(float x) {
    uint32_t u;
    asm("cvt.rna.tf32.f32 %0, %1;" : "=r"(u) : "f"(x));
    return __uint_as_float(u);
}
__device__ __forceinline__ void split4(const float* a, uint32_t* ah, uint32_t* al) {
#pragma unroll
    for (int j = 0; j < 4; j++) {
        float h = tf32_hi(a[j]);
        ah[j] = fu(h);
        al[j] = fu(a[j] - h);
    }
}
__device__ __forceinline__ void split2(float b0, float b1, uint32_t* bh, uint32_t* bl) {
    float h0 = tf32_hi(b0), h1 = tf32_hi(b1);
    bh[0] = fu(h0); bh[1] = fu(h1);
    bl[0] = fu(b0 - h0); bl[1] = fu(b1 - h1);
}
__device__ __forceinline__ void mma3(float* d, const uint32_t* ah, const uint32_t* al,
                                     const uint32_t* bh, const uint32_t* bl) {
    mma_tf32(d, al, bh);
    mma_tf32(d, ah, bl);
    mma_tf32(d, ah, bh);
}

// ---------------------------------------------------------------------------
// Kernel 0: zero aux + expert histogram
// ---------------------------------------------------------------------------
__global__ void init_aux_kernel() {
    int tid = threadIdx.x;
    if (tid < 2 * E + 1) g_aux[tid] = 0.f;
    if (tid < E) g_ecnt[tid] = 0;
}

// ---------------------------------------------------------------------------
// Kernel 1: gating
// ---------------------------------------------------------------------------
__global__ __launch_bounds__(256) void gating_kernel(
    const float* __restrict__ x, const int* __restrict__ task_bh,
    const float* __restrict__ Wg)
{
    __shared__ float s_aux[2 * E + 1];
    __shared__ int   s_ecnt[E];
    int tid = threadIdx.x;
    if (tid < 2 * E + 1) s_aux[tid] = 0.f;
    if (tid < E) s_ecnt[tid] = 0;
    __syncthreads();

    int warp = tid >> 5, lane = tid & 31;
    int t = blockIdx.x * 8 + warp;
    int b = t >> 11;
    int task = task_bh[b];
    const float* xrow = x + (size_t)t * D;
    const float* wg   = Wg + (size_t)task * D * E;

    float acc[E];
#pragma unroll
    for (int e = 0; e < E; e++) acc[e] = 0.f;

    for (int i = lane; i < D; i += 32) {
        float xv = xrow[i];
        const float4* w4 = reinterpret_cast<const float4*>(wg + (size_t)i * E);
#pragma unroll
        for (int j = 0; j < 6; j++) {
            float4 v = w4[j];
            acc[4*j+0] += xv * v.x; acc[4*j+1] += xv * v.y;
            acc[4*j+2] += xv * v.z; acc[4*j+3] += xv * v.w;
        }
    }
#pragma unroll
    for (int e = 0; e < E; e++) {
#pragma unroll
        for (int off = 16; off >= 1; off >>= 1)
            acc[e] += __shfl_xor_sync(0xffffffffu, acc[e], off);
    }
    float mx = acc[0];
#pragma unroll
    for (int e = 1; e < E; e++) mx = fmaxf(mx, acc[e]);
    float p[E]; float s = 0.f;
#pragma unroll
    for (int e = 0; e < E; e++) { p[e] = __expf(acc[e] - mx); s += p[e]; }
    float inv_s = 1.f / s;
    float lse = mx + __logf(s);

    if (lane < E) atomicAdd(&s_aux[E + lane], p[lane] * inv_s);
    if (lane == 0) {
        atomicAdd(&s_aux[2 * E], lse * lse);
        float tv[H]; int ti[H]; float gsum = 0.f;
#pragma unroll
        for (int h = 0; h < H; h++) {
            float best = -1.f; int bi = 0;
#pragma unroll
            for (int e = 0; e < E; e++)
                if (p[e] > best) { best = p[e]; bi = e; }
            tv[h] = best * inv_s; ti[h] = bi; p[bi] = -2.f;
            gsum += tv[h];
            atomicAdd(&s_aux[bi], 1.0f);
            atomicAdd(&s_ecnt[bi], 1);
        }
        float ig = 1.f / gsum;
#pragma unroll
        for (int h = 0; h < H; h++) {
            g_topi[t * H + h]  = ti[h];
            g_gates[t * H + h] = tv[h] * ig;
        }
    }
    __syncthreads();
    if (tid < 2 * E + 1) atomicAdd(&g_aux[tid], s_aux[tid]);
    if (tid < E) atomicAdd(&g_ecnt[tid], s_ecnt[tid]);
}

// ---------------------------------------------------------------------------
// Kernel 2: serial scan over experts → offsets + tile table
// ---------------------------------------------------------------------------
__global__ void scan_kernel() {
    if (threadIdx.x == 0) {
        int off = 0, nt = 0;
        for (int e = 0; e < E; e++) {
            g_eoff[e] = off;
            g_ecursor[e] = 0;
            int c = g_ecnt[e];
            for (int r = 0; r < c; r += TQ) {
                g_tile_e[nt]  = e;
                g_tile_r0[nt] = off + r;
                nt++;
            }
            off += c;
        }
        g_eoff[E] = off;
        g_ntiles = nt;
    }
}

// ---------------------------------------------------------------------------
// Kernel 3: scatter slot ids into expert buckets
// ---------------------------------------------------------------------------
__global__ void scatter_kernel() {
    int i = blockIdx.x * 256 + threadIdx.x;
    int e = g_topi[i];
    int pos = atomicAdd(&g_ecursor[e], 1);
    g_slots[g_eoff[e] + pos] = i;
}

// ---------------------------------------------------------------------------
// Kernel 4: kv = x @ Wkv + bkv  → g_kT (transposed), g_v
// ---------------------------------------------------------------------------
__global__ __launch_bounds__(256) void kv_kernel(
    const float* __restrict__ x, const float* __restrict__ Wkv,
    const float* __restrict__ bkv)
{
    __shared__ float As[64][17];
    __shared__ float Bs[16][64];
    int tid = threadIdx.x;
    int tx = tid & 15, ty = tid >> 4;
    int t0 = blockIdx.x * 64;
    int n0 = blockIdx.y * 64;

    float acc[4][4] = {};

    for (int k0 = 0; k0 < D; k0 += 16) {
#pragma unroll
        for (int i = 0; i < 4; i++) {
            int idx = tid + i * 256;
            int r = idx >> 4, kk = idx & 15;
            As[r][kk] = x[(size_t)(t0 + r) * D + k0 + kk];
        }
#pragma unroll
        for (int i = 0; i < 4; i++) {
            int idx = tid + i * 256;
            int kr = idx >> 6, nn = idx & 63;
            Bs[kr][nn] = Wkv[(size_t)(k0 + kr) * (2 * HD) + n0 + nn];
        }
        __syncthreads();
#pragma unroll
        for (int kk = 0; kk < 16; kk++) {
            float a[4];
#pragma unroll
            for (int i = 0; i < 4; i++) a[i] = As[ty * 4 + i][kk];
            float4 bv = *reinterpret_cast<const float4*>(&Bs[kk][tx * 4]);
            float bb[4] = {bv.x, bv.y, bv.z, bv.w};
#pragma unroll
            for (int i = 0; i < 4; i++)
#pragma unroll
                for (int j = 0; j < 4; j++)
                    acc[i][j] += a[i] * bb[j];
        }
        __syncthreads();
    }
#pragma unroll
    for (int i = 0; i < 4; i++) {
        int t = t0 + ty * 4 + i;
#pragma unroll
        for (int j = 0; j < 4; j++) {
            int c = n0 + tx * 4 + j;
            float v = acc[i][j] + bkv[c];
            if (c < HD) g_kT[(size_t)c * BN_TOK + t] = v;
            else        g_v[(size_t)t * HD + (c - HD)] = v;
        }
    }
}

// ---------------------------------------------------------------------------
// Kernel 5: grouped q GEMM — 3xTF32 (feeds exp; keep compensated)
// ---------------------------------------------------------------------------
constexpr int GBK = 32;
constexpr int AS_STR = 36;
constexpr int BS_STR = 136;

__global__ __launch_bounds__(256, 2) void qgemm_kernel(
    const float* __restrict__ x, const float* __restrict__ Wq)
{
    __shared__ float As[TQ * AS_STR];
    __shared__ float Bs[GBK * BS_STR];
    __shared__ int   s_tok[TQ];
    __shared__ int   s_slot[TQ];

    int t = blockIdx.x;
    if (t >= g_ntiles) return;
    int e = g_tile_e[t], r0 = g_tile_r0[t];
    int rend = g_eoff[e + 1];
    int tid = threadIdx.x;

    if (tid < TQ) {
        int gr = r0 + tid;
        if (gr >= rend) gr = r0;
        int s = g_slots[gr];
        s_slot[tid] = s;
        s_tok[tid]  = s >> 3;
    }
    __syncthreads();

    int warp = tid >> 5, lane = tid & 31;
    int g = lane >> 2, tg = lane & 3;
    int r_a = warp * 16 + g, r_b = r_a + 8;
    const float* wq = Wq + (size_t)e * D * HD;

    float acc[16][4] = {};

    for (int k0 = 0; k0 < D; k0 += GBK) {
#pragma unroll
        for (int i = 0; i < 4; i++) {
            int f4 = tid + i * 256;
            int r = f4 >> 3, c = (f4 & 7) * 4;
            *reinterpret_cast<float4*>(As + r * AS_STR + c) =
                *reinterpret_cast<const float4*>(x + (size_t)s_tok[r] * D + k0 + c);
        }
#pragma unroll
        for (int i = 0; i < 4; i++) {
            int f4 = tid + i * 256;
            int kr = f4 >> 5, c = (f4 & 31) * 4;
            *reinterpret_cast<float4*>(Bs + kr * BS_STR + c) =
                *reinterpret_cast<const float4*>(wq + (size_t)(k0 + kr) * HD + c);
        }
        __syncthreads();
#pragma unroll
        for (int ks = 0; ks < 4; ks++) {
            int krow = 8 * ks + tg;
            float a_raw[4] = { As[r_a * AS_STR + krow], As[r_b * AS_STR + krow],
                               As[r_a * AS_STR + krow + 4], As[r_b * AS_STR + krow + 4] };
            uint32_t ah[4], al[4];
            split4(a_raw, ah, al);
            const float* b0p = Bs + krow * BS_STR + g;
            const float* b1p = b0p + 4 * BS_STR;
#pragma unroll
            for (int nc = 0; nc < 16; nc++) {
                uint32_t bh[2], bl[2];
                split2(b0p[8 * nc], b1p[8 * nc], bh, bl);
                mma3(acc[nc], ah, al, bh, bl);
            }
        }
        __syncthreads();
    }

    bool va = (r0 + r_a < rend), vb = (r0 + r_b < rend);
    float* da = g_q + (size_t)s_slot[r_a] * HD;
    float* db = g_q + (size_t)s_slot[r_b] * HD;
#pragma unroll
    for (int nc = 0; nc < 16; nc++) {
        int c = 8 * nc + 2 * tg;
        if (va) *reinterpret_cast<float2*>(da + c) = make_float2(acc[nc][0], acc[nc][1]);
        if (vb) *reinterpret_cast<float2*>(db + c) = make_float2(acc[nc][2], acc[nc][3]);
    }
}

// ---------------------------------------------------------------------------
// Kernel 6: flash attention (R5 skeleton) — QK^T 3xTF32 in log2 domain,
// exp via ex2.approx.f16x2 (MUFU halved), P fp16, PV via mma.m16n8k16.f16.
// block = 256 threads (8 warps), q-tile 128 rows, KV-tile 64.
// ---------------------------------------------------------------------------
constexpr int QT = 128;
constexpr int KT = 64;
constexpr int QS_STRIDE = 132;   // Qs [row][hd]          (f32)
constexpr int KS_STRIDE = 72;    // Ks [hd][kv]   (K^T)   (f32)
constexpr int VT2_STR   = 36;    // VhT2 [hd][kv-pair]    (half2 words)
constexpr int PS2_STR   = 36;    // Ps2  [row][kv-pair]   (half2 words)

__global__ __launch_bounds__(256, 1) void attn_kernel()
{
    extern __shared__ float sm[];
    float*   Qs   = sm;                         // 128*132 f32
    float*   Ks   = Qs + QT * QS_STRIDE;        // 128*72  f32
    __half2* VhT2 = reinterpret_cast<__half2*>(Ks + HD * KS_STRIDE);  // 128*36 words
    __half2* Ps2  = VhT2 + HD * VT2_STR;        // 128*36 words

    int tid  = threadIdx.x;
    int warp = tid >> 5, lane = tid & 31;
    int g = lane >> 2, tg = lane & 3;
    int n0 = blockIdx.x * QT;
    int h  = blockIdx.y;
    int b  = blockIdx.z;
    int bN0 = b * N;
    // scale * log2(e): softmax computed in log2 domain
    const float qsc = 0.08838834764831845f * 1.44269504088896340736f;

    // load Q (pre-scaled to log2 domain) once
    for (int idx = tid; idx < QT * (HD / 4); idx += 256) {
        int r = idx >> 5, kq = (idx & 31) * 4;
        float4 qv = *reinterpret_cast<const float4*>(
            g_q + (((size_t)(bN0 + n0 + r)) * H + h) * HD + kq);
        qv.x *= qsc; qv.y *= qsc; qv.z *= qsc; qv.w *= qsc;
        *reinterpret_cast<float4*>(Qs + r * QS_STRIDE + kq) = qv;
    }

    const int r_a = warp * 16 + g;
    const int r_b = r_a + 8;

    float o[16][4];
#pragma unroll
    for (int nc = 0; nc < 16; nc++)
#pragma unroll
        for (int j = 0; j < 4; j++) o[nc][j] = 0.f;
    float m_a = -1e30f, m_b = -1e30f, l_a = 0.f, l_b = 0.f;

    for (int m0 = 0; m0 < N; m0 += KT) {
        __syncthreads();   // prev tile consumed (also covers initial Q load)
        // K^T tile: Ks[k][m] (f32)
        for (int idx = tid; idx < HD * (KT / 4); idx += 256) {
            int k = idx >> 4, mq = (idx & 15) * 4;
            *reinterpret_cast<float4*>(Ks + k * KS_STRIDE + mq) =
                *reinterpret_cast<const float4*>(g_kT + (size_t)k * BN_TOK + bN0 + m0 + mq);
        }
        // V tile transposed to half2: VhT2[hd][kvpair] = (V[2p][hd], V[2p+1][hd])
        for (int idx = tid; idx < (KT / 2) * (HD / 4); idx += 256) {
            int p  = idx & 31;             // kv pair 0..31
            int kq = (idx >> 5) * 4;       // hd quad
            float4 fa = *reinterpret_cast<const float4*>(
                g_v + ((size_t)(bN0 + m0 + 2 * p)) * HD + kq);
            float4 fb = *reinterpret_cast<const float4*>(
                g_v + ((size_t)(bN0 + m0 + 2 * p + 1)) * HD + kq);
            VhT2[(kq + 0) * VT2_STR + p] = __floats2half2_rn(fa.x, fb.x);
            VhT2[(kq + 1) * VT2_STR + p] = __floats2half2_rn(fa.y, fb.y);
            VhT2[(kq + 2) * VT2_STR + p] = __floats2half2_rn(fa.z, fb.z);
            VhT2[(kq + 3) * VT2_STR + p] = __floats2half2_rn(fa.w, fb.w);
        }
        __syncthreads();

        // ---- S = Q K^T : 16 x 64 per warp, 3xtf32 (log2 domain) ----
        float sc[8][4];
#pragma unroll
        for (int nc = 0; nc < 8; nc++)
#pragma unroll
            for (int j = 0; j < 4; j++) sc[nc][j] = 0.f;

#pragma unroll
        for (int ks = 0; ks < 16; ks++) {
            const float* qa0 = Qs + r_a * QS_STRIDE + 8 * ks + tg;
            const float* qa1 = Qs + r_b * QS_STRIDE + 8 * ks + tg;
            float a_raw[4] = { qa0[0], qa1[0], qa0[4], qa1[4] };
            uint32_t ah[4], al[4];
            split4(a_raw, ah, al);
            const float* kb0 = Ks + (8 * ks + tg) * KS_STRIDE + g;
            const float* kb1 = kb0 + 4 * KS_STRIDE;
#pragma unroll
            for (int nc = 0; nc < 8; nc++) {
                uint32_t bh[2], bl[2];
                split2(kb0[8 * nc], kb1[8 * nc], bh, bl);
                mma3(sc[nc], ah, al, bh, bl);
            }
        }

        // ---- online softmax (log2 domain, f16x2 ex2) ----
        float lm_a = -1e30f, lm_b = -1e30f;
#pragma unroll
        for (int nc = 0; nc < 8; nc++) {
            lm_a = fmaxf(lm_a, fmaxf(sc[nc][0], sc[nc][1]));
            lm_b = fmaxf(lm_b, fmaxf(sc[nc][2], sc[nc][3]));
        }
#pragma unroll
        for (int off = 1; off <= 2; off <<= 1) {
            lm_a = fmaxf(lm_a, __shfl_xor_sync(0xffffffffu, lm_a, off));
            lm_b = fmaxf(lm_b, __shfl_xor_sync(0xffffffffu, lm_b, off));
        }
        float mn_a = fmaxf(m_a, lm_a), mn_b = fmaxf(m_b, lm_b);
        float al_a = exp2f(m_a - mn_a), al_b = exp2f(m_b - mn_b);
        m_a = mn_a; m_b = mn_b;

        float rs_a = 0.f, rs_b = 0.f;
#pragma unroll
        for (int nc = 0; nc < 8; nc++) {
            __half2 ha = h2exp2(__floats2half2_rn(sc[nc][0] - mn_a, sc[nc][1] - mn_a));
            __half2 hb = h2exp2(__floats2half2_rn(sc[nc][2] - mn_b, sc[nc][3] - mn_b));
            int cp = 4 * nc + tg;
            Ps2[r_a * PS2_STR + cp] = ha;
            Ps2[r_b * PS2_STR + cp] = hb;
            float2 fa = __half22float2(ha);
            float2 fb = __half22float2(hb);
            rs_a += fa.x + fa.y;
            rs_b += fb.x + fb.y;
        }
#pragma unroll
        for (int off = 1; off <= 2; off <<= 1) {
            rs_a += __shfl_xor_sync(0xffffffffu, rs_a, off);
            rs_b += __shfl_xor_sync(0xffffffffu, rs_b, off);
        }
        l_a = l_a * al_a + rs_a;
        l_b = l_b * al_b + rs_b;
#pragma unroll
        for (int nc = 0; nc < 16; nc++) {
            o[nc][0] *= al_a; o[nc][1] *= al_a;
            o[nc][2] *= al_b; o[nc][3] *= al_b;
        }

        // ---- O += P V : fp16 m16n8k16, per-warp-private Ps2, no sync ----
#pragma unroll
        for (int ks = 0; ks < 4; ks++) {
            const __half2* pa0 = Ps2 + r_a * PS2_STR + 8 * ks + tg;
            const __half2* pa1 = Ps2 + r_b * PS2_STR + 8 * ks + tg;
            uint32_t a[4];
            a[0] = *reinterpret_cast<const uint32_t*>(pa0);
            a[1] = *reinterpret_cast<const uint32_t*>(pa1);
            a[2] = *reinterpret_cast<const uint32_t*>(pa0 + 4);
            a[3] = *reinterpret_cast<const uint32_t*>(pa1 + 4);
#pragma unroll
            for (int nc = 0; nc < 16; nc++) {
                const __half2* vb = VhT2 + (8 * nc + g) * VT2_STR + 8 * ks + tg;
                uint32_t bb[2];
                bb[0] = *reinterpret_cast<const uint32_t*>(vb);
                bb[1] = *reinterpret_cast<const uint32_t*>(vb + 4);
                mma_f16(o[nc], a, bb);
            }
        }
    }

    float inv_a = 1.f / l_a, inv_b = 1.f / l_b;
    float* dsta = g_attno + (((size_t)(bN0 + n0 + r_a)) * H + h) * HD;
    float* dstb = g_attno + (((size_t)(bN0 + n0 + r_b)) * H + h) * HD;
#pragma unroll
    for (int nc = 0; nc < 16; nc++) {
        *reinterpret_cast<float2*>(dsta + 8 * nc + 2 * tg) =
            make_float2(o[nc][0] * inv_a, o[nc][1] * inv_a);
        *reinterpret_cast<float2*>(dstb + 8 * nc + 2 * tg) =
            make_float2(o[nc][2] * inv_b, o[nc][3] * inv_b);
    }
}

// ---------------------------------------------------------------------------
// Kernel 7: grouped combine GEMM — single-pass tf32 (linear output path)
// ---------------------------------------------------------------------------
__global__ __launch_bounds__(256, 2) void cgemm_kernel(const float* __restrict__ Wo)
{
    __shared__ float As[TQ * AS_STR];
    __shared__ float Bs[GBK * BS_STR];
    __shared__ int   s_slot[TQ];
    __shared__ float s_gate[TQ];

    int t = blockIdx.x;
    if (t >= g_ntiles) return;
    int n0 = blockIdx.y * 128;
    int e = g_tile_e[t], r0 = g_tile_r0[t];
    int rend = g_eoff[e + 1];
    int tid = threadIdx.x;

    if (tid < TQ) {
        int gr = r0 + tid;
        if (gr >= rend) gr = r0;
        int s = g_slots[gr];
        s_slot[tid] = s;
        s_gate[tid] = g_gates[s];
    }
    __syncthreads();

    int warp = tid >> 5, lane = tid & 31;
    int g = lane >> 2, tg = lane & 3;
    int r_a = warp * 16 + g, r_b = r_a + 8;
    const float* wo = Wo + (size_t)e * HD * D;

    float acc[16][4] = {};

    for (int k0 = 0; k0 < HD; k0 += GBK) {
#pragma unroll
        for (int i = 0; i < 4; i++) {
            int f4 = tid + i * 256;
            int r = f4 >> 3, c = (f4 & 7) * 4;
            float4 av = *reinterpret_cast<const float4*>(
                g_attno + (size_t)s_slot[r] * HD + k0 + c);
            av.x = tf32_hi(av.x); av.y = tf32_hi(av.y);
            av.z = tf32_hi(av.z); av.w = tf32_hi(av.w);
            *reinterpret_cast<float4*>(As + r * AS_STR + c) = av;
        }
#pragma unroll
        for (int i = 0; i < 4; i++) {
            int f4 = tid + i * 256;
            int kr = f4 >> 5, c = (f4 & 31) * 4;
            float4 bv = *reinterpret_cast<const float4*>(
                wo + (size_t)(k0 + kr) * D + n0 + c);
            bv.x = tf32_hi(bv.x); bv.y = tf32_hi(bv.y);
            bv.z = tf32_hi(bv.z); bv.w = tf32_hi(bv.w);
            *reinterpret_cast<float4*>(Bs + kr * BS_STR + c) = bv;
        }
        __syncthreads();
#pragma unroll
        for (int ks = 0; ks < 4; ks++) {
            int krow = 8 * ks + tg;
            uint32_t a[4] = { fu(As[r_a * AS_STR + krow]), fu(As[r_b * AS_STR + krow]),
                              fu(As[r_a * AS_STR + krow + 4]), fu(As[r_b * AS_STR + krow + 4]) };
            const float* b0p = Bs + krow * BS_STR + g;
            const float* b1p = b0p + 4 * BS_STR;
#pragma unroll
            for (int nc = 0; nc < 16; nc++) {
                uint32_t bb[2] = { fu(b0p[8 * nc]), fu(b1p[8 * nc]) };
                mma_tf32(acc[nc], a, bb);
            }
        }
        __syncthreads();
    }

    bool va = (r0 + r_a < rend), vb = (r0 + r_b < rend);
    float ga = s_gate[r_a], gb = s_gate[r_b];
    float* da = g_ws + (size_t)s_slot[r_a] * D + n0;
    float* db = g_ws + (size_t)s_slot[r_b] * D + n0;
#pragma unroll
    for (int nc = 0; nc < 16; nc++) {
        int c = 8 * nc + 2 * tg;
        if (va) *reinterpret_cast<float2*>(da + c) = make_float2(acc[nc][0] * ga, acc[nc][1] * ga);
        if (vb) *reinterpret_cast<float2*>(db + c) = make_float2(acc[nc][2] * gb, acc[nc][3] * gb);
    }
}

// ---------------------------------------------------------------------------
// Kernel 8: reduce 8 slot rows per token → y
// ---------------------------------------------------------------------------
__global__ __launch_bounds__(256) void reduce_kernel(float* __restrict__ y)
{
    int t = blockIdx.x;
    int c = threadIdx.x * 4;
    float4 s = make_float4(0.f, 0.f, 0.f, 0.f);
#pragma unroll
    for (int h = 0; h < H; h++) {
        float4 v = *reinterpret_cast<const float4*>(g_ws + ((size_t)(t * H + h)) * D + c);
        s.x += v.x; s.y += v.y; s.z += v.z; s.w += v.w;
    }
    *reinterpret_cast<float4*>(y + (size_t)t * D + c) = s;
}

// ---------------------------------------------------------------------------
// Kernel 9: finalize aux loss
// ---------------------------------------------------------------------------
__global__ void aux_final_kernel(float* __restrict__ out) {
    if (threadIdx.x == 0) {
        const float inv_bn = 1.0f / (float)BN_TOK;
        float sw = 0.f;
        for (int e = 0; e < E; e++)
            sw += (g_aux[e] * inv_bn) * (g_aux[E + e] * inv_bn);
        float aux = 0.1f * (float)E * sw + 0.001f * (g_aux[2 * E] * inv_bn);
        out[(size_t)BN_TOK * D] = aux;
    }
}

// ---------------------------------------------------------------------------
// Launch
// ---------------------------------------------------------------------------
extern "C" void kernel_launch(void* const* d_in, const int* in_sizes, int n_in,
                              void* d_out, int out_size)
{
    const float* x    = (const float*)d_in[0];
    const int* task_bh = (const int*)d_in[1];
    const float* Wg   = (const float*)d_in[2];
    const float* Wq   = (const float*)d_in[3];
    const float* Wo   = (const float*)d_in[4];
    const float* Wkv  = (const float*)d_in[5];
    const float* bkv  = (const float*)d_in[6];
    float* out = (float*)d_out;

    const int attn_smem = (QT * QS_STRIDE + HD * KS_STRIDE) * 4 +
                          (HD * VT2_STR + QT * PS2_STR) * 4;
    cudaFuncSetAttribute(attn_kernel, cudaFuncAttributeMaxDynamicSharedMemorySize, attn_smem);

    init_aux_kernel<<<1, 64>>>();
    gating_kernel<<<BN_TOK / 8, 256>>>(x, task_bh, Wg);
    scan_kernel<<<1, 32>>>();
    scatter_kernel<<<NSLOT / 256, 256>>>();
    kv_kernel<<<dim3(BN_TOK / 64, (2 * HD) / 64), 256>>>(x, Wkv, bkv);
    qgemm_kernel<<<NT_MAX, 256>>>(x, Wq);
    attn_kernel<<<dim3(N / QT, H, B), 256, attn_smem>>>();
    cgemm_kernel<<<dim3(NT_MAX, 8), 256>>>(Wo);
    reduce_kernel<<<BN_TOK, 256>>>(out);
    aux_final_kernel<<<1, 32>>>(out);
}

// round 8
// speedup vs baseline: 1.3235x; 1.1743x over previous
#include <cuda_runtime.h>
#include <cuda_fp16.h>
#include <math.h>
#include <stdint.h>

// ---------------------------------------------------------------------------
// Problem constants
// ---------------------------------------------------------------------------
constexpr int B    = 4;
constexpr int N    = 2048;
constexpr int D    = 1024;
constexpr int E    = 24;
constexpr int H    = 8;
constexpr int HD   = 128;
constexpr int BN_TOK = B * N;          // 8192 tokens
constexpr int NSLOT  = BN_TOK * H;     // 65536 (token,slot) pairs

// Grouped-GEMM tiling
constexpr int TQ = 128;                // rows per expert tile
constexpr int NT_MAX = NSLOT / TQ + E; // 536 max tiles

// ---------------------------------------------------------------------------
// Scratch (device globals — no allocations allowed)
// ---------------------------------------------------------------------------
__device__ float g_kT[HD * BN_TOK];            // 4 MB  K^T: [hd][token]
__device__ float g_v[BN_TOK * HD];             // 4 MB
__device__ float g_q[NSLOT * HD];              // 32 MB  [slot][hd], slot=token*8+h
__device__ float g_attno[NSLOT * HD];          // 32 MB
__device__ float g_ws[(size_t)NSLOT * D];      // 268 MB combine scratch [slot][D]
__device__ int   g_topi[NSLOT];
__device__ float g_gates[NSLOT];
__device__ float g_aux[2 * E + 1];
// expert bucketing
__device__ int g_ecnt[E];
__device__ int g_eoff[E + 1];
__device__ int g_ecursor[E];
__device__ int g_slots[NSLOT];
__device__ int g_tile_e[NT_MAX];
__device__ int g_tile_r0[NT_MAX];
__device__ int g_ntiles;

// ---------------------------------------------------------------------------
// mma helpers
// ---------------------------------------------------------------------------
__device__ __forceinline__ void mma_tf32(float* d, const uint32_t* a, const uint32_t* b) {
    asm volatile(
        "mma.sync.aligned.m16n8k8.row.col.f32.tf32.tf32.f32 "
        "{%0,%1,%2,%3}, {%4,%5,%6,%7}, {%8,%9}, {%0,%1,%2,%3};\n"
        : "+f"(d[0]), "+f"(d[1]), "+f"(d[2]), "+f"(d[3])
        : "r"(a[0]), "r"(a[1]), "r"(a[2]), "r"(a[3]), "r"(b[0]), "r"(b[1]));
}
__device__ __forceinline__ void mma_f16(float* d, const uint32_t* a, const uint32_t* b) {
    asm volatile(
        "mma.sync.aligned.m16n8k16.row.col.f32.f16.f16.f32 "
        "{%0,%1,%2,%3}, {%4,%5,%6,%7}, {%8,%9}, {%0,%1,%2,%3};\n"
        : "+f"(d[0]), "+f"(d[1]), "+f"(d[2]), "+f"(d[3])
        : "r"(a[0]), "r"(a[1]), "r"(a[2]), "r"(a[3]), "r"(b[0]), "r"(b[1]));
}
__device__ __forceinline__ uint32_t fu(float x) { return __float_as_uint(x); }
__device__ __forceinline__ float tf32_hi(float x) {
    uint32_t u;
    asm("cvt.rna.tf32.f32 %0, %1;" : "=r"(u) : "f"(x));
    return __uint_as_float(u);
}
__device__ __forceinline__ void split4(const float* a, uint32_t* ah, uint32_t* al) {
#pragma unroll
    for (int j = 0; j < 4; j++) {
        float h = tf32_hi(a[j]);
        ah[j] = fu(h);
        al[j] = fu(a[j] - h);
    }
}
__device__ __forceinline__ void split2(float b0, float b1, uint32_t* bh, uint32_t* bl) {
    float h0 = tf32_hi(b0), h1 = tf32_hi(b1);
    bh[0] = fu(h0); bh[1] = fu(h1);
    bl[0] = fu(b0 - h0); bl[1] = fu(b1 - h1);
}
__device__ __forceinline__ void mma3(float* d, const uint32_t* ah, const uint32_t* al,
                                     const uint32_t* bh, const uint32_t* bl) {
    mma_tf32(d, al, bh);
    mma_tf32(d, ah, bl);
    mma_tf32(d, ah, bh);
}
// split a float pair into f16 hi + f16 lo*1024
__device__ __forceinline__ void h2split(float x, float y, __half2& hi, __half2& lo) {
    hi = __floats2half2_rn(x, y);
    float2 hf = __half22float2(hi);
    lo = __floats2half2_rn((x - hf.x) * 1024.f, (y - hf.y) * 1024.f);
}

// ---------------------------------------------------------------------------
// Kernel 0: zero aux + expert histogram
// ---------------------------------------------------------------------------
__global__ void init_aux_kernel() {
    int tid = threadIdx.x;
    if (tid < 2 * E + 1) g_aux[tid] = 0.f;
    if (tid < E) g_ecnt[tid] = 0;
}

// ---------------------------------------------------------------------------
// Kernel 1: gating
// ---------------------------------------------------------------------------
__global__ __launch_bounds__(256) void gating_kernel(
    const float* __restrict__ x, const int* __restrict__ task_bh,
    const float* __restrict__ Wg)
{
    __shared__ float s_aux[2 * E + 1];
    __shared__ int   s_ecnt[E];
    int tid = threadIdx.x;
    if (tid < 2 * E + 1) s_aux[tid] = 0.f;
    if (tid < E) s_ecnt[tid] = 0;
    __syncthreads();

    int warp = tid >> 5, lane = tid & 31;
    int t = blockIdx.x * 8 + warp;
    int b = t >> 11;
    int task = task_bh[b];
    const float* xrow = x + (size_t)t * D;
    const float* wg   = Wg + (size_t)task * D * E;

    float acc[E];
#pragma unroll
    for (int e = 0; e < E; e++) acc[e] = 0.f;

    for (int i = lane; i < D; i += 32) {
        float xv = xrow[i];
        const float4* w4 = reinterpret_cast<const float4*>(wg + (size_t)i * E);
#pragma unroll
        for (int j = 0; j < 6; j++) {
            float4 v = w4[j];
            acc[4*j+0] += xv * v.x; acc[4*j+1] += xv * v.y;
            acc[4*j+2] += xv * v.z; acc[4*j+3] += xv * v.w;
        }
    }
#pragma unroll
    for (int e = 0; e < E; e++) {
#pragma unroll
        for (int off = 16; off >= 1; off >>= 1)
            acc[e] += __shfl_xor_sync(0xffffffffu, acc[e], off);
    }
    float mx = acc[0];
#pragma unroll
    for (int e = 1; e < E; e++) mx = fmaxf(mx, acc[e]);
    float p[E]; float s = 0.f;
#pragma unroll
    for (int e = 0; e < E; e++) { p[e] = __expf(acc[e] - mx); s += p[e]; }
    float inv_s = 1.f / s;
    float lse = mx + __logf(s);

    if (lane < E) atomicAdd(&s_aux[E + lane], p[lane] * inv_s);
    if (lane == 0) {
        atomicAdd(&s_aux[2 * E], lse * lse);
        float tv[H]; int ti[H]; float gsum = 0.f;
#pragma unroll
        for (int h = 0; h < H; h++) {
            float best = -1.f; int bi = 0;
#pragma unroll
            for (int e = 0; e < E; e++)
                if (p[e] > best) { best = p[e]; bi = e; }
            tv[h] = best * inv_s; ti[h] = bi; p[bi] = -2.f;
            gsum += tv[h];
            atomicAdd(&s_aux[bi], 1.0f);
            atomicAdd(&s_ecnt[bi], 1);
        }
        float ig = 1.f / gsum;
#pragma unroll
        for (int h = 0; h < H; h++) {
            g_topi[t * H + h]  = ti[h];
            g_gates[t * H + h] = tv[h] * ig;
        }
    }
    __syncthreads();
    if (tid < 2 * E + 1) atomicAdd(&g_aux[tid], s_aux[tid]);
    if (tid < E) atomicAdd(&g_ecnt[tid], s_ecnt[tid]);
}

// ---------------------------------------------------------------------------
// Kernel 2: serial scan over experts → offsets + tile table
// ---------------------------------------------------------------------------
__global__ void scan_kernel() {
    if (threadIdx.x == 0) {
        int off = 0, nt = 0;
        for (int e = 0; e < E; e++) {
            g_eoff[e] = off;
            g_ecursor[e] = 0;
            int c = g_ecnt[e];
            for (int r = 0; r < c; r += TQ) {
                g_tile_e[nt]  = e;
                g_tile_r0[nt] = off + r;
                nt++;
            }
            off += c;
        }
        g_eoff[E] = off;
        g_ntiles = nt;
    }
}

// ---------------------------------------------------------------------------
// Kernel 3: scatter slot ids into expert buckets
// ---------------------------------------------------------------------------
__global__ void scatter_kernel() {
    int i = blockIdx.x * 256 + threadIdx.x;
    int e = g_topi[i];
    int pos = atomicAdd(&g_ecursor[e], 1);
    g_slots[g_eoff[e] + pos] = i;
}

// ---------------------------------------------------------------------------
// Kernel 4: kv = x @ Wkv + bkv  → g_kT (transposed), g_v
// ---------------------------------------------------------------------------
__global__ __launch_bounds__(256) void kv_kernel(
    const float* __restrict__ x, const float* __restrict__ Wkv,
    const float* __restrict__ bkv)
{
    __shared__ float As[64][17];
    __shared__ float Bs[16][64];
    int tid = threadIdx.x;
    int tx = tid & 15, ty = tid >> 4;
    int t0 = blockIdx.x * 64;
    int n0 = blockIdx.y * 64;

    float acc[4][4] = {};

    for (int k0 = 0; k0 < D; k0 += 16) {
#pragma unroll
        for (int i = 0; i < 4; i++) {
            int idx = tid + i * 256;
            int r = idx >> 4, kk = idx & 15;
            As[r][kk] = x[(size_t)(t0 + r) * D + k0 + kk];
        }
#pragma unroll
        for (int i = 0; i < 4; i++) {
            int idx = tid + i * 256;
            int kr = idx >> 6, nn = idx & 63;
            Bs[kr][nn] = Wkv[(size_t)(k0 + kr) * (2 * HD) + n0 + nn];
        }
        __syncthreads();
#pragma unroll
        for (int kk = 0; kk < 16; kk++) {
            float a[4];
#pragma unroll
            for (int i = 0; i < 4; i++) a[i] = As[ty * 4 + i][kk];
            float4 bv = *reinterpret_cast<const float4*>(&Bs[kk][tx * 4]);
            float bb[4] = {bv.x, bv.y, bv.z, bv.w};
#pragma unroll
            for (int i = 0; i < 4; i++)
#pragma unroll
                for (int j = 0; j < 4; j++)
                    acc[i][j] += a[i] * bb[j];
        }
        __syncthreads();
    }
#pragma unroll
    for (int i = 0; i < 4; i++) {
        int t = t0 + ty * 4 + i;
#pragma unroll
        for (int j = 0; j < 4; j++) {
            int c = n0 + tx * 4 + j;
            float v = acc[i][j] + bkv[c];
            if (c < HD) g_kT[(size_t)c * BN_TOK + t] = v;
            else        g_v[(size_t)t * HD + (c - HD)] = v;
        }
    }
}

// ---------------------------------------------------------------------------
// Kernel 5: grouped q GEMM — 3xTF32 (feeds exp; keep compensated)
// ---------------------------------------------------------------------------
constexpr int GBK = 32;
constexpr int AS_STR = 36;
constexpr int BS_STR = 136;

__global__ __launch_bounds__(256, 2) void qgemm_kernel(
    const float* __restrict__ x, const float* __restrict__ Wq)
{
    __shared__ float As[TQ * AS_STR];
    __shared__ float Bs[GBK * BS_STR];
    __shared__ int   s_tok[TQ];
    __shared__ int   s_slot[TQ];

    int t = blockIdx.x;
    if (t >= g_ntiles) return;
    int e = g_tile_e[t], r0 = g_tile_r0[t];
    int rend = g_eoff[e + 1];
    int tid = threadIdx.x;

    if (tid < TQ) {
        int gr = r0 + tid;
        if (gr >= rend) gr = r0;
        int s = g_slots[gr];
        s_slot[tid] = s;
        s_tok[tid]  = s >> 3;
    }
    __syncthreads();

    int warp = tid >> 5, lane = tid & 31;
    int g = lane >> 2, tg = lane & 3;
    int r_a = warp * 16 + g, r_b = r_a + 8;
    const float* wq = Wq + (size_t)e * D * HD;

    float acc[16][4] = {};

    for (int k0 = 0; k0 < D; k0 += GBK) {
#pragma unroll
        for (int i = 0; i < 4; i++) {
            int f4 = tid + i * 256;
            int r = f4 >> 3, c = (f4 & 7) * 4;
            *reinterpret_cast<float4*>(As + r * AS_STR + c) =
                *reinterpret_cast<const float4*>(x + (size_t)s_tok[r] * D + k0 + c);
        }
#pragma unroll
        for (int i = 0; i < 4; i++) {
            int f4 = tid + i * 256;
            int kr = f4 >> 5, c = (f4 & 31) * 4;
            *reinterpret_cast<float4*>(Bs + kr * BS_STR + c) =
                *reinterpret_cast<const float4*>(wq + (size_t)(k0 + kr) * HD + c);
        }
        __syncthreads();
#pragma unroll
        for (int ks = 0; ks < 4; ks++) {
            int krow = 8 * ks + tg;
            float a_raw[4] = { As[r_a * AS_STR + krow], As[r_b * AS_STR + krow],
                               As[r_a * AS_STR + krow + 4], As[r_b * AS_STR + krow + 4] };
            uint32_t ah[4], al[4];
            split4(a_raw, ah, al);
            const float* b0p = Bs + krow * BS_STR + g;
            const float* b1p = b0p + 4 * BS_STR;
#pragma unroll
            for (int nc = 0; nc < 16; nc++) {
                uint32_t bh[2], bl[2];
                split2(b0p[8 * nc], b1p[8 * nc], bh, bl);
                mma3(acc[nc], ah, al, bh, bl);
            }
        }
        __syncthreads();
    }

    bool va = (r0 + r_a < rend), vb = (r0 + r_b < rend);
    float* da = g_q + (size_t)s_slot[r_a] * HD;
    float* db = g_q + (size_t)s_slot[r_b] * HD;
#pragma unroll
    for (int nc = 0; nc < 16; nc++) {
        int c = 8 * nc + 2 * tg;
        if (va) *reinterpret_cast<float2*>(da + c) = make_float2(acc[nc][0], acc[nc][1]);
        if (vb) *reinterpret_cast<float2*>(db + c) = make_float2(acc[nc][2], acc[nc][3]);
    }
}

// ---------------------------------------------------------------------------
// Kernel 6: flash attention — QK^T via f16 error-compensated mma.m16n8k16
// (Q,K pre-split into f16 hi + lo*2^10 at smem store; inner loop pure LDS+HMMA),
// softmax in log2 domain with ex2.approx.f16x2, P fp16, PV fp16 mma.
// block = 256 threads (8 warps), q-tile 128 rows, KV-tile 64.
// ---------------------------------------------------------------------------
constexpr int QT = 128;
constexpr int KT = 64;
constexpr int QH_STR  = 68;   // Qhi/Qlo [row 128][hd-pair 64 + pad]   (half2)
constexpr int KH_STR  = 72;   // Khi/Klo [hd-pair 64][kv 64 + pad]     (half2)
constexpr int VT2_STR = 36;   // VhT2 [hd 128][kv-pair 32 + pad]       (half2)
constexpr int PS2_STR = 36;   // Ps2  [row 128][kv-pair 32 + pad]      (half2)
constexpr float LO_SC  = 1024.f;
constexpr float LO_INV = 1.f / 1024.f;

__global__ __launch_bounds__(256, 1) void attn_kernel()
{
    extern __shared__ __half2 smh[];
    __half2* Qhi  = smh;                     // 128*68
    __half2* Qlo  = Qhi  + QT * QH_STR;      // 128*68
    __half2* Khi  = Qlo  + QT * QH_STR;      // 64*72
    __half2* Klo  = Khi  + 64 * KH_STR;      // 64*72
    __half2* VhT2 = Klo  + 64 * KH_STR;      // 128*36
    __half2* Ps2  = VhT2 + HD * VT2_STR;     // 128*36

    int tid  = threadIdx.x;
    int warp = tid >> 5, lane = tid & 31;
    int g = lane >> 2, tg = lane & 3;
    int n0 = blockIdx.x * QT;
    int h  = blockIdx.y;
    int b  = blockIdx.z;
    int bN0 = b * N;
    // scale * log2(e): softmax computed in log2 domain
    const float qsc = 0.08838834764831845f * 1.44269504088896340736f;

    // load Q once: scale, split into f16 hi / lo*2^10
    for (int idx = tid; idx < QT * (HD / 4); idx += 256) {
        int r = idx >> 5, kq = (idx & 31) * 4;
        float4 qv = *reinterpret_cast<const float4*>(
            g_q + (((size_t)(bN0 + n0 + r)) * H + h) * HD + kq);
        qv.x *= qsc; qv.y *= qsc; qv.z *= qsc; qv.w *= qsc;
        __half2 h0, l0, h1, l1;
        h2split(qv.x, qv.y, h0, l0);
        h2split(qv.z, qv.w, h1, l1);
        int p0 = kq >> 1;
        Qhi[r * QH_STR + p0]     = h0;
        Qhi[r * QH_STR + p0 + 1] = h1;
        Qlo[r * QH_STR + p0]     = l0;
        Qlo[r * QH_STR + p0 + 1] = l1;
    }

    const int r_a = warp * 16 + g;
    const int r_b = r_a + 8;

    float o[16][4];
#pragma unroll
    for (int nc = 0; nc < 16; nc++)
#pragma unroll
        for (int j = 0; j < 4; j++) o[nc][j] = 0.f;
    float m_a = -1e30f, m_b = -1e30f, l_a = 0.f, l_b = 0.f;

    for (int m0 = 0; m0 < N; m0 += KT) {
        __syncthreads();   // prev tile consumed (also covers initial Q load)
        // K tile: pair-major Khi/Klo[p][m] = half2(K[m][2p], K[m][2p+1])
        // 64 pairs x 16 m-quads; 16 threads per pair row (coalesced on m)
        for (int idx = tid; idx < 64 * 16; idx += 256) {
            int p  = idx >> 4;
            int mq = (idx & 15) * 4;
            const float* kr0 = g_kT + (size_t)(2 * p)     * BN_TOK + bN0 + m0 + mq;
            const float* kr1 = g_kT + (size_t)(2 * p + 1) * BN_TOK + bN0 + m0 + mq;
            float4 fa = *reinterpret_cast<const float4*>(kr0);
            float4 fb = *reinterpret_cast<const float4*>(kr1);
            __half2 hh, ll;
            h2split(fa.x, fb.x, hh, ll);
            Khi[p * KH_STR + mq + 0] = hh; Klo[p * KH_STR + mq + 0] = ll;
            h2split(fa.y, fb.y, hh, ll);
            Khi[p * KH_STR + mq + 1] = hh; Klo[p * KH_STR + mq + 1] = ll;
            h2split(fa.z, fb.z, hh, ll);
            Khi[p * KH_STR + mq + 2] = hh; Klo[p * KH_STR + mq + 2] = ll;
            h2split(fa.w, fb.w, hh, ll);
            Khi[p * KH_STR + mq + 3] = hh; Klo[p * KH_STR + mq + 3] = ll;
        }
        // V tile transposed to half2: VhT2[hd][kvpair] = (V[2p][hd], V[2p+1][hd])
        for (int idx = tid; idx < (KT / 2) * (HD / 4); idx += 256) {
            int p  = idx & 31;             // kv pair 0..31
            int kq = (idx >> 5) * 4;       // hd quad
            float4 fa = *reinterpret_cast<const float4*>(
                g_v + ((size_t)(bN0 + m0 + 2 * p)) * HD + kq);
            float4 fb = *reinterpret_cast<const float4*>(
                g_v + ((size_t)(bN0 + m0 + 2 * p + 1)) * HD + kq);
            VhT2[(kq + 0) * VT2_STR + p] = __floats2half2_rn(fa.x, fb.x);
            VhT2[(kq + 1) * VT2_STR + p] = __floats2half2_rn(fa.y, fb.y);
            VhT2[(kq + 2) * VT2_STR + p] = __floats2half2_rn(fa.z, fb.z);
            VhT2[(kq + 3) * VT2_STR + p] = __floats2half2_rn(fa.w, fb.w);
        }
        __syncthreads();

        // ---- S = Q K^T : 16 x 64 per warp, f16 compensated, k16 steps ----
        float scc[8][4] = {};
        float scl[8][4] = {};
#pragma unroll
        for (int ks = 0; ks < 8; ks++) {
            const __half2* qh0 = Qhi + r_a * QH_STR + 8 * ks + tg;
            const __half2* qh1 = Qhi + r_b * QH_STR + 8 * ks + tg;
            const __half2* ql0 = Qlo + r_a * QH_STR + 8 * ks + tg;
            const __half2* ql1 = Qlo + r_b * QH_STR + 8 * ks + tg;
            uint32_t ah[4] = { *reinterpret_cast<const uint32_t*>(qh0),
                               *reinterpret_cast<const uint32_t*>(qh1),
                               *reinterpret_cast<const uint32_t*>(qh0 + 4),
                               *reinterpret_cast<const uint32_t*>(qh1 + 4) };
            uint32_t al[4] = { *reinterpret_cast<const uint32_t*>(ql0),
                               *reinterpret_cast<const uint32_t*>(ql1),
                               *reinterpret_cast<const uint32_t*>(ql0 + 4),
                               *reinterpret_cast<const uint32_t*>(ql1 + 4) };
            const __half2* kh0 = Khi + (8 * ks + tg) * KH_STR + g;
            const __half2* kh1 = Khi + (8 * ks + 4 + tg) * KH_STR + g;
            const __half2* kl0 = Klo + (8 * ks + tg) * KH_STR + g;
            const __half2* kl1 = Klo + (8 * ks + 4 + tg) * KH_STR + g;
#pragma unroll
            for (int nc = 0; nc < 8; nc++) {
                uint32_t bh[2] = { *reinterpret_cast<const uint32_t*>(kh0 + 8 * nc),
                                   *reinterpret_cast<const uint32_t*>(kh1 + 8 * nc) };
                uint32_t bl[2] = { *reinterpret_cast<const uint32_t*>(kl0 + 8 * nc),
                                   *reinterpret_cast<const uint32_t*>(kl1 + 8 * nc) };
                mma_f16(scc[nc], ah, bh);
                mma_f16(scl[nc], al, bh);
                mma_f16(scl[nc], ah, bl);
            }
        }
        // combine: S = hi·hi + 2^-10 * cross
#pragma unroll
        for (int nc = 0; nc < 8; nc++)
#pragma unroll
            for (int j = 0; j < 4; j++)
                scc[nc][j] += scl[nc][j] * LO_INV;

        // ---- online softmax (log2 domain, f16x2 ex2) ----
        float lm_a = -1e30f, lm_b = -1e30f;
#pragma unroll
        for (int nc = 0; nc < 8; nc++) {
            lm_a = fmaxf(lm_a, fmaxf(scc[nc][0], scc[nc][1]));
            lm_b = fmaxf(lm_b, fmaxf(scc[nc][2], scc[nc][3]));
        }
#pragma unroll
        for (int off = 1; off <= 2; off <<= 1) {
            lm_a = fmaxf(lm_a, __shfl_xor_sync(0xffffffffu, lm_a, off));
            lm_b = fmaxf(lm_b, __shfl_xor_sync(0xffffffffu, lm_b, off));
        }
        float mn_a = fmaxf(m_a, lm_a), mn_b = fmaxf(m_b, lm_b);
        float al_a = exp2f(m_a - mn_a), al_b = exp2f(m_b - mn_b);
        m_a = mn_a; m_b = mn_b;

        float rs_a = 0.f, rs_b = 0.f;
#pragma unroll
        for (int nc = 0; nc < 8; nc++) {
            __half2 ha = h2exp2(__floats2half2_rn(scc[nc][0] - mn_a, scc[nc][1] - mn_a));
            __half2 hb = h2exp2(__floats2half2_rn(scc[nc][2] - mn_b, scc[nc][3] - mn_b));
            int cp = 4 * nc + tg;
            Ps2[r_a * PS2_STR + cp] = ha;
            Ps2[r_b * PS2_STR + cp] = hb;
            float2 fa = __half22float2(ha);
            float2 fb = __half22float2(hb);
            rs_a += fa.x + fa.y;
            rs_b += fb.x + fb.y;
        }
#pragma unroll
        for (int off = 1; off <= 2; off <<= 1) {
            rs_a += __shfl_xor_sync(0xffffffffu, rs_a, off);
            rs_b += __shfl_xor_sync(0xffffffffu, rs_b, off);
        }
        l_a = l_a * al_a + rs_a;
        l_b = l_b * al_b + rs_b;
#pragma unroll
        for (int nc = 0; nc < 16; nc++) {
            o[nc][0] *= al_a; o[nc][1] *= al_a;
            o[nc][2] *= al_b; o[nc][3] *= al_b;
        }

        // ---- O += P V : fp16 m16n8k16, per-warp-private Ps2, no sync ----
#pragma unroll
        for (int ks = 0; ks < 4; ks++) {
            const __half2* pa0 = Ps2 + r_a * PS2_STR + 8 * ks + tg;
            const __half2* pa1 = Ps2 + r_b * PS2_STR + 8 * ks + tg;
            uint32_t a[4];
            a[0] = *reinterpret_cast<const uint32_t*>(pa0);
            a[1] = *reinterpret_cast<const uint32_t*>(pa1);
            a[2] = *reinterpret_cast<const uint32_t*>(pa0 + 4);
            a[3] = *reinterpret_cast<const uint32_t*>(pa1 + 4);
#pragma unroll
            for (int nc = 0; nc < 16; nc++) {
                const __half2* vb = VhT2 + (8 * nc + g) * VT2_STR + 8 * ks + tg;
                uint32_t bb[2];
                bb[0] = *reinterpret_cast<const uint32_t*>(vb);
                bb[1] = *reinterpret_cast<const uint32_t*>(vb + 4);
                mma_f16(o[nc], a, bb);
            }
        }
    }

    float inv_a = 1.f / l_a, inv_b = 1.f / l_b;
    float* dsta = g_attno + (((size_t)(bN0 + n0 + r_a)) * H + h) * HD;
    float* dstb = g_attno + (((size_t)(bN0 + n0 + r_b)) * H + h) * HD;
#pragma unroll
    for (int nc = 0; nc < 16; nc++) {
        *reinterpret_cast<float2*>(dsta + 8 * nc + 2 * tg) =
            make_float2(o[nc][0] * inv_a, o[nc][1] * inv_a);
        *reinterpret_cast<float2*>(dstb + 8 * nc + 2 * tg) =
            make_float2(o[nc][2] * inv_b, o[nc][3] * inv_b);
    }
}

// ---------------------------------------------------------------------------
// Kernel 7: grouped combine GEMM — single-pass tf32 (linear output path)
// ---------------------------------------------------------------------------
__global__ __launch_bounds__(256, 2) void cgemm_kernel(const float* __restrict__ Wo)
{
    __shared__ float As[TQ * AS_STR];
    __shared__ float Bs[GBK * BS_STR];
    __shared__ int   s_slot[TQ];
    __shared__ float s_gate[TQ];

    int t = blockIdx.x;
    if (t >= g_ntiles) return;
    int n0 = blockIdx.y * 128;
    int e = g_tile_e[t], r0 = g_tile_r0[t];
    int rend = g_eoff[e + 1];
    int tid = threadIdx.x;

    if (tid < TQ) {
        int gr = r0 + tid;
        if (gr >= rend) gr = r0;
        int s = g_slots[gr];
        s_slot[tid] = s;
        s_gate[tid] = g_gates[s];
    }
    __syncthreads();

    int warp = tid >> 5, lane = tid & 31;
    int g = lane >> 2, tg = lane & 3;
    int r_a = warp * 16 + g, r_b = r_a + 8;
    const float* wo = Wo + (size_t)e * HD * D;

    float acc[16][4] = {};

    for (int k0 = 0; k0 < HD; k0 += GBK) {
#pragma unroll
        for (int i = 0; i < 4; i++) {
            int f4 = tid + i * 256;
            int r = f4 >> 3, c = (f4 & 7) * 4;
            float4 av = *reinterpret_cast<const float4*>(
                g_attno + (size_t)s_slot[r] * HD + k0 + c);
            av.x = tf32_hi(av.x); av.y = tf32_hi(av.y);
            av.z = tf32_hi(av.z); av.w = tf32_hi(av.w);
            *reinterpret_cast<float4*>(As + r * AS_STR + c) = av;
        }
#pragma unroll
        for (int i = 0; i < 4; i++) {
            int f4 = tid + i * 256;
            int kr = f4 >> 5, c = (f4 & 31) * 4;
            float4 bv = *reinterpret_cast<const float4*>(
                wo + (size_t)(k0 + kr) * D + n0 + c);
            bv.x = tf32_hi(bv.x); bv.y = tf32_hi(bv.y);
            bv.z = tf32_hi(bv.z); bv.w = tf32_hi(bv.w);
            *reinterpret_cast<float4*>(Bs + kr * BS_STR + c) = bv;
        }
        __syncthreads();
#pragma unroll
        for (int ks = 0; ks < 4; ks++) {
            int krow = 8 * ks + tg;
            uint32_t a[4] = { fu(As[r_a * AS_STR + krow]), fu(As[r_b * AS_STR + krow]),
                              fu(As[r_a * AS_STR + krow + 4]), fu(As[r_b * AS_STR + krow + 4]) };
            const float* b0p = Bs + krow * BS_STR + g;
            const float* b1p = b0p + 4 * BS_STR;
#pragma unroll
            for (int nc = 0; nc < 16; nc++) {
                uint32_t bb[2] = { fu(b0p[8 * nc]), fu(b1p[8 * nc]) };
                mma_tf32(acc[nc], a, bb);
            }
        }
        __syncthreads();
    }

    bool va = (r0 + r_a < rend), vb = (r0 + r_b < rend);
    float ga = s_gate[r_a], gb = s_gate[r_b];
    float* da = g_ws + (size_t)s_slot[r_a] * D + n0;
    float* db = g_ws + (size_t)s_slot[r_b] * D + n0;
#pragma unroll
    for (int nc = 0; nc < 16; nc++) {
        int c = 8 * nc + 2 * tg;
        if (va) *reinterpret_cast<float2*>(da + c) = make_float2(acc[nc][0] * ga, acc[nc][1] * ga);
        if (vb) *reinterpret_cast<float2*>(db + c) = make_float2(acc[nc][2] * gb, acc[nc][3] * gb);
    }
}

// ---------------------------------------------------------------------------
// Kernel 8: reduce 8 slot rows per token → y
// ---------------------------------------------------------------------------
__global__ __launch_bounds__(256) void reduce_kernel(float* __restrict__ y)
{
    int t = blockIdx.x;
    int c = threadIdx.x * 4;
    float4 s = make_float4(0.f, 0.f, 0.f, 0.f);
#pragma unroll
    for (int h = 0; h < H; h++) {
        float4 v = *reinterpret_cast<const float4*>(g_ws + ((size_t)(t * H + h)) * D + c);
        s.x += v.x; s.y += v.y; s.z += v.z; s.w += v.w;
    }
    *reinterpret_cast<float4*>(y + (size_t)t * D + c) = s;
}

// ---------------------------------------------------------------------------
// Kernel 9: finalize aux loss
// ---------------------------------------------------------------------------
__global__ void aux_final_kernel(float* __restrict__ out) {
    if (threadIdx.x == 0) {
        const float inv_bn = 1.0f / (float)BN_TOK;
        float sw = 0.f;
        for (int e = 0; e < E; e++)
            sw += (g_aux[e] * inv_bn) * (g_aux[E + e] * inv_bn);
        float aux = 0.1f * (float)E * sw + 0.001f * (g_aux[2 * E] * inv_bn);
        out[(size_t)BN_TOK * D] = aux;
    }
}

// ---------------------------------------------------------------------------
// Launch
// ---------------------------------------------------------------------------
extern "C" void kernel_launch(void* const* d_in, const int* in_sizes, int n_in,
                              void* d_out, int out_size)
{
    const float* x    = (const float*)d_in[0];
    const int* task_bh = (const int*)d_in[1];
    const float* Wg   = (const float*)d_in[2];
    const float* Wq   = (const float*)d_in[3];
    const float* Wo   = (const float*)d_in[4];
    const float* Wkv  = (const float*)d_in[5];
    const float* bkv  = (const float*)d_in[6];
    float* out = (float*)d_out;

    const int attn_smem = (2 * QT * QH_STR + 2 * 64 * KH_STR +
                           HD * VT2_STR + QT * PS2_STR) * 4;
    cudaFuncSetAttribute(attn_kernel, cudaFuncAttributeMaxDynamicSharedMemorySize, attn_smem);

    init_aux_kernel<<<1, 64>>>();
    gating_kernel<<<BN_TOK / 8, 256>>>(x, task_bh, Wg);
    scan_kernel<<<1, 32>>>();
    scatter_kernel<<<NSLOT / 256, 256>>>();
    kv_kernel<<<dim3(BN_TOK / 64, (2 * HD) / 64), 256>>>(x, Wkv, bkv);
    qgemm_kernel<<<NT_MAX, 256>>>(x, Wq);
    attn_kernel<<<dim3(N / QT, H, B), 256, attn_smem>>>();
    cgemm_kernel<<<dim3(NT_MAX, 8), 256>>>(Wo);
    reduce_kernel<<<BN_TOK, 256>>>(out);
    aux_final_kernel<<<1, 32>>>(out);
}

// round 9
// speedup vs baseline: 1.4212x; 1.0738x over previous
#include <cuda_runtime.h>
#include <cuda_fp16.h>
#include <math.h>
#include <stdint.h>

// ---------------------------------------------------------------------------
// Problem constants
// ---------------------------------------------------------------------------
constexpr int B    = 4;
constexpr int N    = 2048;
constexpr int D    = 1024;
constexpr int E    = 24;
constexpr int H    = 8;
constexpr int HD   = 128;
constexpr int BN_TOK = B * N;          // 8192 tokens
constexpr int NSLOT  = BN_TOK * H;     // 65536 (token,slot) pairs

// Grouped-GEMM tiling
constexpr int TQ = 128;                // rows per expert tile
constexpr int NT_MAX = NSLOT / TQ + E; // 536 max tiles

// ---------------------------------------------------------------------------
// Scratch (device globals — no allocations allowed)
// ---------------------------------------------------------------------------
__device__ float g_kT[HD * BN_TOK];            // 4 MB  K^T: [hd][token]
__device__ float g_v[BN_TOK * HD];             // 4 MB
__device__ float g_q[NSLOT * HD];              // 32 MB  [slot][hd], slot=token*8+h
__device__ float g_attno[NSLOT * HD];          // 32 MB
__device__ float g_ws[(size_t)NSLOT * D];      // 268 MB combine scratch [slot][D]
__device__ int   g_topi[NSLOT];
__device__ float g_gates[NSLOT];
__device__ float g_aux[2 * E + 1];
// expert bucketing
__device__ int g_ecnt[E];
__device__ int g_eoff[E + 1];
__device__ int g_ecursor[E];
__device__ int g_slots[NSLOT];
__device__ int g_tile_e[NT_MAX];
__device__ int g_tile_r0[NT_MAX];
__device__ int g_ntiles;

// ---------------------------------------------------------------------------
// mma helpers
// ---------------------------------------------------------------------------
__device__ __forceinline__ void mma_tf32(float* d, const uint32_t* a, const uint32_t* b) {
    asm volatile(
        "mma.sync.aligned.m16n8k8.row.col.f32.tf32.tf32.f32 "
        "{%0,%1,%2,%3}, {%4,%5,%6,%7}, {%8,%9}, {%0,%1,%2,%3};\n"
        : "+f"(d[0]), "+f"(d[1]), "+f"(d[2]), "+f"(d[3])
        : "r"(a[0]), "r"(a[1]), "r"(a[2]), "r"(a[3]), "r"(b[0]), "r"(b[1]));
}
__device__ __forceinline__ void mma_f16(float* d, const uint32_t* a, const uint32_t* b) {
    asm volatile(
        "mma.sync.aligned.m16n8k16.row.col.f32.f16.f16.f32 "
        "{%0,%1,%2,%3}, {%4,%5,%6,%7}, {%8,%9}, {%0,%1,%2,%3};\n"
        : "+f"(d[0]), "+f"(d[1]), "+f"(d[2]), "+f"(d[3])
        : "r"(a[0]), "r"(a[1]), "r"(a[2]), "r"(a[3]), "r"(b[0]), "r"(b[1]));
}
__device__ __forceinline__ uint32_t fu(float x) { return __float_as_uint(x); }
__device__ __forceinline__ float tf32_hi(float x) {
    uint32_t u;
    asm("cvt.rna.tf32.f32 %0, %1;" : "=r"(u) : "f"(x));
    return __uint_as_float(u);
}
// split a float pair into f16 hi + f16 lo*1024
__device__ __forceinline__ void h2split(float x, float y, __half2& hi, __half2& lo) {
    hi = __floats2half2_rn(x, y);
    float2 hf = __half22float2(hi);
    lo = __floats2half2_rn((x - hf.x) * 1024.f, (y - hf.y) * 1024.f);
}
constexpr float LO_INV = 1.f / 1024.f;

// ---------------------------------------------------------------------------
// Kernel 0: zero aux + expert histogram
// ---------------------------------------------------------------------------
__global__ void init_aux_kernel() {
    int tid = threadIdx.x;
    if (tid < 2 * E + 1) g_aux[tid] = 0.f;
    if (tid < E) g_ecnt[tid] = 0;
}

// ---------------------------------------------------------------------------
// Kernel 1: gating
// ---------------------------------------------------------------------------
__global__ __launch_bounds__(256) void gating_kernel(
    const float* __restrict__ x, const int* __restrict__ task_bh,
    const float* __restrict__ Wg)
{
    __shared__ float s_aux[2 * E + 1];
    __shared__ int   s_ecnt[E];
    int tid = threadIdx.x;
    if (tid < 2 * E + 1) s_aux[tid] = 0.f;
    if (tid < E) s_ecnt[tid] = 0;
    __syncthreads();

    int warp = tid >> 5, lane = tid & 31;
    int t = blockIdx.x * 8 + warp;
    int b = t >> 11;
    int task = task_bh[b];
    const float* xrow = x + (size_t)t * D;
    const float* wg   = Wg + (size_t)task * D * E;

    float acc[E];
#pragma unroll
    for (int e = 0; e < E; e++) acc[e] = 0.f;

    for (int i = lane; i < D; i += 32) {
        float xv = xrow[i];
        const float4* w4 = reinterpret_cast<const float4*>(wg + (size_t)i * E);
#pragma unroll
        for (int j = 0; j < 6; j++) {
            float4 v = w4[j];
            acc[4*j+0] += xv * v.x; acc[4*j+1] += xv * v.y;
            acc[4*j+2] += xv * v.z; acc[4*j+3] += xv * v.w;
        }
    }
#pragma unroll
    for (int e = 0; e < E; e++) {
#pragma unroll
        for (int off = 16; off >= 1; off >>= 1)
            acc[e] += __shfl_xor_sync(0xffffffffu, acc[e], off);
    }
    float mx = acc[0];
#pragma unroll
    for (int e = 1; e < E; e++) mx = fmaxf(mx, acc[e]);
    float p[E]; float s = 0.f;
#pragma unroll
    for (int e = 0; e < E; e++) { p[e] = __expf(acc[e] - mx); s += p[e]; }
    float inv_s = 1.f / s;
    float lse = mx + __logf(s);

    if (lane < E) atomicAdd(&s_aux[E + lane], p[lane] * inv_s);
    if (lane == 0) {
        atomicAdd(&s_aux[2 * E], lse * lse);
        float tv[H]; int ti[H]; float gsum = 0.f;
#pragma unroll
        for (int h = 0; h < H; h++) {
            float best = -1.f; int bi = 0;
#pragma unroll
            for (int e = 0; e < E; e++)
                if (p[e] > best) { best = p[e]; bi = e; }
            tv[h] = best * inv_s; ti[h] = bi; p[bi] = -2.f;
            gsum += tv[h];
            atomicAdd(&s_aux[bi], 1.0f);
            atomicAdd(&s_ecnt[bi], 1);
        }
        float ig = 1.f / gsum;
#pragma unroll
        for (int h = 0; h < H; h++) {
            g_topi[t * H + h]  = ti[h];
            g_gates[t * H + h] = tv[h] * ig;
        }
    }
    __syncthreads();
    if (tid < 2 * E + 1) atomicAdd(&g_aux[tid], s_aux[tid]);
    if (tid < E) atomicAdd(&g_ecnt[tid], s_ecnt[tid]);
}

// ---------------------------------------------------------------------------
// Kernel 2: serial scan over experts → offsets + tile table
// ---------------------------------------------------------------------------
__global__ void scan_kernel() {
    if (threadIdx.x == 0) {
        int off = 0, nt = 0;
        for (int e = 0; e < E; e++) {
            g_eoff[e] = off;
            g_ecursor[e] = 0;
            int c = g_ecnt[e];
            for (int r = 0; r < c; r += TQ) {
                g_tile_e[nt]  = e;
                g_tile_r0[nt] = off + r;
                nt++;
            }
            off += c;
        }
        g_eoff[E] = off;
        g_ntiles = nt;
    }
}

// ---------------------------------------------------------------------------
// Kernel 3: scatter slot ids into expert buckets
// ---------------------------------------------------------------------------
__global__ void scatter_kernel() {
    int i = blockIdx.x * 256 + threadIdx.x;
    int e = g_topi[i];
    int pos = atomicAdd(&g_ecursor[e], 1);
    g_slots[g_eoff[e] + pos] = i;
}

// ---------------------------------------------------------------------------
// Kernel 4: kv = x @ Wkv + bkv  → g_kT (transposed), g_v
// ---------------------------------------------------------------------------
__global__ __launch_bounds__(256) void kv_kernel(
    const float* __restrict__ x, const float* __restrict__ Wkv,
    const float* __restrict__ bkv)
{
    __shared__ float As[64][17];
    __shared__ float Bs[16][64];
    int tid = threadIdx.x;
    int tx = tid & 15, ty = tid >> 4;
    int t0 = blockIdx.x * 64;
    int n0 = blockIdx.y * 64;

    float acc[4][4] = {};

    for (int k0 = 0; k0 < D; k0 += 16) {
#pragma unroll
        for (int i = 0; i < 4; i++) {
            int idx = tid + i * 256;
            int r = idx >> 4, kk = idx & 15;
            As[r][kk] = x[(size_t)(t0 + r) * D + k0 + kk];
        }
#pragma unroll
        for (int i = 0; i < 4; i++) {
            int idx = tid + i * 256;
            int kr = idx >> 6, nn = idx & 63;
            Bs[kr][nn] = Wkv[(size_t)(k0 + kr) * (2 * HD) + n0 + nn];
        }
        __syncthreads();
#pragma unroll
        for (int kk = 0; kk < 16; kk++) {
            float a[4];
#pragma unroll
            for (int i = 0; i < 4; i++) a[i] = As[ty * 4 + i][kk];
            float4 bv = *reinterpret_cast<const float4*>(&Bs[kk][tx * 4]);
            float bb[4] = {bv.x, bv.y, bv.z, bv.w};
#pragma unroll
            for (int i = 0; i < 4; i++)
#pragma unroll
                for (int j = 0; j < 4; j++)
                    acc[i][j] += a[i] * bb[j];
        }
        __syncthreads();
    }
#pragma unroll
    for (int i = 0; i < 4; i++) {
        int t = t0 + ty * 4 + i;
#pragma unroll
        for (int j = 0; j < 4; j++) {
            int c = n0 + tx * 4 + j;
            float v = acc[i][j] + bkv[c];
            if (c < HD) g_kT[(size_t)c * BN_TOK + t] = v;
            else        g_v[(size_t)t * HD + (c - HD)] = v;
        }
    }
}

// ---------------------------------------------------------------------------
// Kernel 5: grouped q GEMM — f16 error-compensated mma (hi + lo*2^10),
// 512 threads: warp = (row-group 0..7, col-half 0..1); M=128, N=128, K=1024.
// Inner loop is pure LDS + HMMA; split done once at smem store.
// ---------------------------------------------------------------------------
constexpr int QG_K  = 64;    // floats per k-chunk (32 pairs)
constexpr int QA_STR = 36;   // Ahi/Alo [row 128][kpair 32 + pad]  (half2)
constexpr int QB_STR = 136;  // Bhi/Blo [kpair 32][n 128 + pad]    (half2)

__global__ __launch_bounds__(512, 1) void qgemm_kernel(
    const float* __restrict__ x, const float* __restrict__ Wq)
{
    extern __shared__ __half2 qsm[];
    __half2* Ahi = qsm;                    // 128*36
    __half2* Alo = Ahi + TQ * QA_STR;      // 128*36
    __half2* Bhi = Alo + TQ * QA_STR;      // 32*136
    __half2* Blo = Bhi + 32 * QB_STR;      // 32*136
    int* s_tok  = reinterpret_cast<int*>(Blo + 32 * QB_STR);   // 128
    int* s_slot = s_tok + TQ;                                   // 128

    int t = blockIdx.x;
    if (t >= g_ntiles) return;
    int e = g_tile_e[t], r0 = g_tile_r0[t];
    int rend = g_eoff[e + 1];
    int tid = threadIdx.x;

    if (tid < TQ) {
        int gr = r0 + tid;
        if (gr >= rend) gr = r0;       // padded rows duplicate row0 (not written back)
        int s = g_slots[gr];
        s_slot[tid] = s;
        s_tok[tid]  = s >> 3;
    }
    __syncthreads();

    int warp = tid >> 5, lane = tid & 31;
    int g = lane >> 2, tg = lane & 3;
    int rg = warp & 7, ch = warp >> 3;     // row-group, col-half
    int r_a = rg * 16 + g, r_b = r_a + 8;
    const float* wq = Wq + (size_t)e * D * HD;

    float scc[8][4] = {};
    float scl[8][4] = {};

    for (int k0 = 0; k0 < D; k0 += QG_K) {
        // A: 128 rows x 64 k (gathered), split to f16 hi/lo
        for (int idx = tid; idx < TQ * (QG_K / 4); idx += 512) {
            int r = idx >> 4, kq = (idx & 15) * 4;
            float4 av = *reinterpret_cast<const float4*>(
                x + (size_t)s_tok[r] * D + k0 + kq);
            __half2 h0, l0, h1, l1;
            h2split(av.x, av.y, h0, l0);
            h2split(av.z, av.w, h1, l1);
            int p0 = kq >> 1;
            Ahi[r * QA_STR + p0]     = h0;
            Ahi[r * QA_STR + p0 + 1] = h1;
            Alo[r * QA_STR + p0]     = l0;
            Alo[r * QA_STR + p0 + 1] = l1;
        }
        // B: pair-major [kpair 32][n 128]: half2(Wq[2p][n], Wq[2p+1][n])
        for (int idx = tid; idx < 32 * 32; idx += 512) {
            int p  = idx >> 5;
            int nq = (idx & 31) * 4;
            const float* w0 = wq + (size_t)(k0 + 2 * p)     * HD + nq;
            const float* w1 = wq + (size_t)(k0 + 2 * p + 1) * HD + nq;
            float4 fa = *reinterpret_cast<const float4*>(w0);
            float4 fb = *reinterpret_cast<const float4*>(w1);
            __half2 hh, ll;
            h2split(fa.x, fb.x, hh, ll);
            Bhi[p * QB_STR + nq + 0] = hh; Blo[p * QB_STR + nq + 0] = ll;
            h2split(fa.y, fb.y, hh, ll);
            Bhi[p * QB_STR + nq + 1] = hh; Blo[p * QB_STR + nq + 1] = ll;
            h2split(fa.z, fb.z, hh, ll);
            Bhi[p * QB_STR + nq + 2] = hh; Blo[p * QB_STR + nq + 2] = ll;
            h2split(fa.w, fb.w, hh, ll);
            Bhi[p * QB_STR + nq + 3] = hh; Blo[p * QB_STR + nq + 3] = ll;
        }
        __syncthreads();

#pragma unroll
        for (int ks = 0; ks < 4; ks++) {
            const __half2* ah0 = Ahi + r_a * QA_STR + 8 * ks + tg;
            const __half2* ah1 = Ahi + r_b * QA_STR + 8 * ks + tg;
            const __half2* al0 = Alo + r_a * QA_STR + 8 * ks + tg;
            const __half2* al1 = Alo + r_b * QA_STR + 8 * ks + tg;
            uint32_t ah[4] = { *reinterpret_cast<const uint32_t*>(ah0),
                               *reinterpret_cast<const uint32_t*>(ah1),
                               *reinterpret_cast<const uint32_t*>(ah0 + 4),
                               *reinterpret_cast<const uint32_t*>(ah1 + 4) };
            uint32_t al[4] = { *reinterpret_cast<const uint32_t*>(al0),
                               *reinterpret_cast<const uint32_t*>(al1),
                               *reinterpret_cast<const uint32_t*>(al0 + 4),
                               *reinterpret_cast<const uint32_t*>(al1 + 4) };
            const __half2* bh0 = Bhi + (8 * ks + tg) * QB_STR + ch * 64 + g;
            const __half2* bh1 = Bhi + (8 * ks + 4 + tg) * QB_STR + ch * 64 + g;
            const __half2* bl0 = Blo + (8 * ks + tg) * QB_STR + ch * 64 + g;
            const __half2* bl1 = Blo + (8 * ks + 4 + tg) * QB_STR + ch * 64 + g;
#pragma unroll
            for (int nc = 0; nc < 8; nc++) {
                uint32_t bh[2] = { *reinterpret_cast<const uint32_t*>(bh0 + 8 * nc),
                                   *reinterpret_cast<const uint32_t*>(bh1 + 8 * nc) };
                uint32_t bl[2] = { *reinterpret_cast<const uint32_t*>(bl0 + 8 * nc),
                                   *reinterpret_cast<const uint32_t*>(bl1 + 8 * nc) };
                mma_f16(scc[nc], ah, bh);
                mma_f16(scl[nc], al, bh);
                mma_f16(scl[nc], ah, bl);
            }
        }
        __syncthreads();
    }

    bool va = (r0 + r_a < rend), vb = (r0 + r_b < rend);
    float* da = g_q + (size_t)s_slot[r_a] * HD + ch * 64;
    float* db = g_q + (size_t)s_slot[r_b] * HD + ch * 64;
#pragma unroll
    for (int nc = 0; nc < 8; nc++) {
        int c = 8 * nc + 2 * tg;
        float o0 = scc[nc][0] + scl[nc][0] * LO_INV;
        float o1 = scc[nc][1] + scl[nc][1] * LO_INV;
        float o2 = scc[nc][2] + scl[nc][2] * LO_INV;
        float o3 = scc[nc][3] + scl[nc][3] * LO_INV;
        if (va) *reinterpret_cast<float2*>(da + c) = make_float2(o0, o1);
        if (vb) *reinterpret_cast<float2*>(db + c) = make_float2(o2, o3);
    }
}

// ---------------------------------------------------------------------------
// Kernel 6: flash attention — QK^T via f16 error-compensated mma.m16n8k16,
// softmax in log2 domain with ex2.approx.f16x2, P fp16, PV fp16 mma.
// block = 256 threads (8 warps), q-tile 128 rows, KV-tile 64.
// ---------------------------------------------------------------------------
constexpr int QT = 128;
constexpr int KT = 64;
constexpr int QH_STR  = 68;   // Qhi/Qlo [row 128][hd-pair 64 + pad]   (half2)
constexpr int KH_STR  = 72;   // Khi/Klo [hd-pair 64][kv 64 + pad]     (half2)
constexpr int VT2_STR = 36;   // VhT2 [hd 128][kv-pair 32 + pad]       (half2)
constexpr int PS2_STR = 36;   // Ps2  [row 128][kv-pair 32 + pad]      (half2)

__global__ __launch_bounds__(256, 1) void attn_kernel()
{
    extern __shared__ __half2 smh[];
    __half2* Qhi  = smh;                     // 128*68
    __half2* Qlo  = Qhi  + QT * QH_STR;      // 128*68
    __half2* Khi  = Qlo  + QT * QH_STR;      // 64*72
    __half2* Klo  = Khi  + 64 * KH_STR;      // 64*72
    __half2* VhT2 = Klo  + 64 * KH_STR;      // 128*36
    __half2* Ps2  = VhT2 + HD * VT2_STR;     // 128*36

    int tid  = threadIdx.x;
    int warp = tid >> 5, lane = tid & 31;
    int g = lane >> 2, tg = lane & 3;
    int n0 = blockIdx.x * QT;
    int h  = blockIdx.y;
    int b  = blockIdx.z;
    int bN0 = b * N;
    // scale * log2(e): softmax computed in log2 domain
    const float qsc = 0.08838834764831845f * 1.44269504088896340736f;

    // load Q once: scale, split into f16 hi / lo*2^10
    for (int idx = tid; idx < QT * (HD / 4); idx += 256) {
        int r = idx >> 5, kq = (idx & 31) * 4;
        float4 qv = *reinterpret_cast<const float4*>(
            g_q + (((size_t)(bN0 + n0 + r)) * H + h) * HD + kq);
        qv.x *= qsc; qv.y *= qsc; qv.z *= qsc; qv.w *= qsc;
        __half2 h0, l0, h1, l1;
        h2split(qv.x, qv.y, h0, l0);
        h2split(qv.z, qv.w, h1, l1);
        int p0 = kq >> 1;
        Qhi[r * QH_STR + p0]     = h0;
        Qhi[r * QH_STR + p0 + 1] = h1;
        Qlo[r * QH_STR + p0]     = l0;
        Qlo[r * QH_STR + p0 + 1] = l1;
    }

    const int r_a = warp * 16 + g;
    const int r_b = r_a + 8;

    float o[16][4];
#pragma unroll
    for (int nc = 0; nc < 16; nc++)
#pragma unroll
        for (int j = 0; j < 4; j++) o[nc][j] = 0.f;
    float m_a = -1e30f, m_b = -1e30f, l_a = 0.f, l_b = 0.f;

    for (int m0 = 0; m0 < N; m0 += KT) {
        __syncthreads();   // prev tile consumed (also covers initial Q load)
        // K tile: pair-major Khi/Klo[p][m] = half2(K[m][2p], K[m][2p+1])
        for (int idx = tid; idx < 64 * 16; idx += 256) {
            int p  = idx >> 4;
            int mq = (idx & 15) * 4;
            const float* kr0 = g_kT + (size_t)(2 * p)     * BN_TOK + bN0 + m0 + mq;
            const float* kr1 = g_kT + (size_t)(2 * p + 1) * BN_TOK + bN0 + m0 + mq;
            float4 fa = *reinterpret_cast<const float4*>(kr0);
            float4 fb = *reinterpret_cast<const float4*>(kr1);
            __half2 hh, ll;
            h2split(fa.x, fb.x, hh, ll);
            Khi[p * KH_STR + mq + 0] = hh; Klo[p * KH_STR + mq + 0] = ll;
            h2split(fa.y, fb.y, hh, ll);
            Khi[p * KH_STR + mq + 1] = hh; Klo[p * KH_STR + mq + 1] = ll;
            h2split(fa.z, fb.z, hh, ll);
            Khi[p * KH_STR + mq + 2] = hh; Klo[p * KH_STR + mq + 2] = ll;
            h2split(fa.w, fb.w, hh, ll);
            Khi[p * KH_STR + mq + 3] = hh; Klo[p * KH_STR + mq + 3] = ll;
        }
        // V tile transposed to half2: VhT2[hd][kvpair] = (V[2p][hd], V[2p+1][hd])
        for (int idx = tid; idx < (KT / 2) * (HD / 4); idx += 256) {
            int p  = idx & 31;             // kv pair 0..31
            int kq = (idx >> 5) * 4;       // hd quad
            float4 fa = *reinterpret_cast<const float4*>(
                g_v + ((size_t)(bN0 + m0 + 2 * p)) * HD + kq);
            float4 fb = *reinterpret_cast<const float4*>(
                g_v + ((size_t)(bN0 + m0 + 2 * p + 1)) * HD + kq);
            VhT2[(kq + 0) * VT2_STR + p] = __floats2half2_rn(fa.x, fb.x);
            VhT2[(kq + 1) * VT2_STR + p] = __floats2half2_rn(fa.y, fb.y);
            VhT2[(kq + 2) * VT2_STR + p] = __floats2half2_rn(fa.z, fb.z);
            VhT2[(kq + 3) * VT2_STR + p] = __floats2half2_rn(fa.w, fb.w);
        }
        __syncthreads();

        // ---- S = Q K^T : 16 x 64 per warp, f16 compensated, k16 steps ----
        float scc[8][4] = {};
        float scl[8][4] = {};
#pragma unroll
        for (int ks = 0; ks < 8; ks++) {
            const __half2* qh0 = Qhi + r_a * QH_STR + 8 * ks + tg;
            const __half2* qh1 = Qhi + r_b * QH_STR + 8 * ks + tg;
            const __half2* ql0 = Qlo + r_a * QH_STR + 8 * ks + tg;
            const __half2* ql1 = Qlo + r_b * QH_STR + 8 * ks + tg;
            uint32_t ah[4] = { *reinterpret_cast<const uint32_t*>(qh0),
                               *reinterpret_cast<const uint32_t*>(qh1),
                               *reinterpret_cast<const uint32_t*>(qh0 + 4),
                               *reinterpret_cast<const uint32_t*>(qh1 + 4) };
            uint32_t al[4] = { *reinterpret_cast<const uint32_t*>(ql0),
                               *reinterpret_cast<const uint32_t*>(ql1),
                               *reinterpret_cast<const uint32_t*>(ql0 + 4),
                               *reinterpret_cast<const uint32_t*>(ql1 + 4) };
            const __half2* kh0 = Khi + (8 * ks + tg) * KH_STR + g;
            const __half2* kh1 = Khi + (8 * ks + 4 + tg) * KH_STR + g;
            const __half2* kl0 = Klo + (8 * ks + tg) * KH_STR + g;
            const __half2* kl1 = Klo + (8 * ks + 4 + tg) * KH_STR + g;
#pragma unroll
            for (int nc = 0; nc < 8; nc++) {
                uint32_t bh[2] = { *reinterpret_cast<const uint32_t*>(kh0 + 8 * nc),
                                   *reinterpret_cast<const uint32_t*>(kh1 + 8 * nc) };
                uint32_t bl[2] = { *reinterpret_cast<const uint32_t*>(kl0 + 8 * nc),
                                   *reinterpret_cast<const uint32_t*>(kl1 + 8 * nc) };
                mma_f16(scc[nc], ah, bh);
                mma_f16(scl[nc], al, bh);
                mma_f16(scl[nc], ah, bl);
            }
        }
        // combine: S = hi·hi + 2^-10 * cross
#pragma unroll
        for (int nc = 0; nc < 8; nc++)
#pragma unroll
            for (int j = 0; j < 4; j++)
                scc[nc][j] += scl[nc][j] * LO_INV;

        // ---- online softmax (log2 domain, f16x2 ex2) ----
        float lm_a = -1e30f, lm_b = -1e30f;
#pragma unroll
        for (int nc = 0; nc < 8; nc++) {
            lm_a = fmaxf(lm_a, fmaxf(scc[nc][0], scc[nc][1]));
            lm_b = fmaxf(lm_b, fmaxf(scc[nc][2], scc[nc][3]));
        }
#pragma unroll
        for (int off = 1; off <= 2; off <<= 1) {
            lm_a = fmaxf(lm_a, __shfl_xor_sync(0xffffffffu, lm_a, off));
            lm_b = fmaxf(lm_b, __shfl_xor_sync(0xffffffffu, lm_b, off));
        }
        float mn_a = fmaxf(m_a, lm_a), mn_b = fmaxf(m_b, lm_b);
        float al_a = exp2f(m_a - mn_a), al_b = exp2f(m_b - mn_b);
        m_a = mn_a; m_b = mn_b;

        float rs_a = 0.f, rs_b = 0.f;
#pragma unroll
        for (int nc = 0; nc < 8; nc++) {
            __half2 ha = h2exp2(__floats2half2_rn(scc[nc][0] - mn_a, scc[nc][1] - mn_a));
            __half2 hb = h2exp2(__floats2half2_rn(scc[nc][2] - mn_b, scc[nc][3] - mn_b));
            int cp = 4 * nc + tg;
            Ps2[r_a * PS2_STR + cp] = ha;
            Ps2[r_b * PS2_STR + cp] = hb;
            float2 fa = __half22float2(ha);
            float2 fb = __half22float2(hb);
            rs_a += fa.x + fa.y;
            rs_b += fb.x + fb.y;
        }
#pragma unroll
        for (int off = 1; off <= 2; off <<= 1) {
            rs_a += __shfl_xor_sync(0xffffffffu, rs_a, off);
            rs_b += __shfl_xor_sync(0xffffffffu, rs_b, off);
        }
        l_a = l_a * al_a + rs_a;
        l_b = l_b * al_b + rs_b;
#pragma unroll
        for (int nc = 0; nc < 16; nc++) {
            o[nc][0] *= al_a; o[nc][1] *= al_a;
            o[nc][2] *= al_b; o[nc][3] *= al_b;
        }

        // ---- O += P V : fp16 m16n8k16, per-warp-private Ps2, no sync ----
#pragma unroll
        for (int ks = 0; ks < 4; ks++) {
            const __half2* pa0 = Ps2 + r_a * PS2_STR + 8 * ks + tg;
            const __half2* pa1 = Ps2 + r_b * PS2_STR + 8 * ks + tg;
            uint32_t a[4];
            a[0] = *reinterpret_cast<const uint32_t*>(pa0);
            a[1] = *reinterpret_cast<const uint32_t*>(pa1);
            a[2] = *reinterpret_cast<const uint32_t*>(pa0 + 4);
            a[3] = *reinterpret_cast<const uint32_t*>(pa1 + 4);
#pragma unroll
            for (int nc = 0; nc < 16; nc++) {
                const __half2* vb = VhT2 + (8 * nc + g) * VT2_STR + 8 * ks + tg;
                uint32_t bb[2];
                bb[0] = *reinterpret_cast<const uint32_t*>(vb);
                bb[1] = *reinterpret_cast<const uint32_t*>(vb + 4);
                mma_f16(o[nc], a, bb);
            }
        }
    }

    float inv_a = 1.f / l_a, inv_b = 1.f / l_b;
    float* dsta = g_attno + (((size_t)(bN0 + n0 + r_a)) * H + h) * HD;
    float* dstb = g_attno + (((size_t)(bN0 + n0 + r_b)) * H + h) * HD;
#pragma unroll
    for (int nc = 0; nc < 16; nc++) {
        *reinterpret_cast<float2*>(dsta + 8 * nc + 2 * tg) =
            make_float2(o[nc][0] * inv_a, o[nc][1] * inv_a);
        *reinterpret_cast<float2*>(dstb + 8 * nc + 2 * tg) =
            make_float2(o[nc][2] * inv_b, o[nc][3] * inv_b);
    }
}

// ---------------------------------------------------------------------------
// Kernel 7: grouped combine GEMM — single-pass tf32 (linear output path)
// ---------------------------------------------------------------------------
constexpr int GBK = 32;
constexpr int AS_STR = 36;
constexpr int BS_STR = 136;

__global__ __launch_bounds__(256, 2) void cgemm_kernel(const float* __restrict__ Wo)
{
    __shared__ float As[TQ * AS_STR];
    __shared__ float Bs[GBK * BS_STR];
    __shared__ int   s_slot[TQ];
    __shared__ float s_gate[TQ];

    int t = blockIdx.x;
    if (t >= g_ntiles) return;
    int n0 = blockIdx.y * 128;
    int e = g_tile_e[t], r0 = g_tile_r0[t];
    int rend = g_eoff[e + 1];
    int tid = threadIdx.x;

    if (tid < TQ) {
        int gr = r0 + tid;
        if (gr >= rend) gr = r0;
        int s = g_slots[gr];
        s_slot[tid] = s;
        s_gate[tid] = g_gates[s];
    }
    __syncthreads();

    int warp = tid >> 5, lane = tid & 31;
    int g = lane >> 2, tg = lane & 3;
    int r_a = warp * 16 + g, r_b = r_a + 8;
    const float* wo = Wo + (size_t)e * HD * D;

    float acc[16][4] = {};

    for (int k0 = 0; k0 < HD; k0 += GBK) {
#pragma unroll
        for (int i = 0; i < 4; i++) {
            int f4 = tid + i * 256;
            int r = f4 >> 3, c = (f4 & 7) * 4;
            float4 av = *reinterpret_cast<const float4*>(
                g_attno + (size_t)s_slot[r] * HD + k0 + c);
            av.x = tf32_hi(av.x); av.y = tf32_hi(av.y);
            av.z = tf32_hi(av.z); av.w = tf32_hi(av.w);
            *reinterpret_cast<float4*>(As + r * AS_STR + c) = av;
        }
#pragma unroll
        for (int i = 0; i < 4; i++) {
            int f4 = tid + i * 256;
            int kr = f4 >> 5, c = (f4 & 31) * 4;
            float4 bv = *reinterpret_cast<const float4*>(
                wo + (size_t)(k0 + kr) * D + n0 + c);
            bv.x = tf32_hi(bv.x); bv.y = tf32_hi(bv.y);
            bv.z = tf32_hi(bv.z); bv.w = tf32_hi(bv.w);
            *reinterpret_cast<float4*>(Bs + kr * BS_STR + c) = bv;
        }
        __syncthreads();
#pragma unroll
        for (int ks = 0; ks < 4; ks++) {
            int krow = 8 * ks + tg;
            uint32_t a[4] = { fu(As[r_a * AS_STR + krow]), fu(As[r_b * AS_STR + krow]),
                              fu(As[r_a * AS_STR + krow + 4]), fu(As[r_b * AS_STR + krow + 4]) };
            const float* b0p = Bs + krow * BS_STR + g;
            const float* b1p = b0p + 4 * BS_STR;
#pragma unroll
            for (int nc = 0; nc < 16; nc++) {
                uint32_t bb[2] = { fu(b0p[8 * nc]), fu(b1p[8 * nc]) };
                mma_tf32(acc[nc], a, bb);
            }
        }
        __syncthreads();
    }

    bool va = (r0 + r_a < rend), vb = (r0 + r_b < rend);
    float ga = s_gate[r_a], gb = s_gate[r_b];
    float* da = g_ws + (size_t)s_slot[r_a] * D + n0;
    float* db = g_ws + (size_t)s_slot[r_b] * D + n0;
#pragma unroll
    for (int nc = 0; nc < 16; nc++) {
        int c = 8 * nc + 2 * tg;
        if (va) *reinterpret_cast<float2*>(da + c) = make_float2(acc[nc][0] * ga, acc[nc][1] * ga);
        if (vb) *reinterpret_cast<float2*>(db + c) = make_float2(acc[nc][2] * gb, acc[nc][3] * gb);
    }
}

// ---------------------------------------------------------------------------
// Kernel 8: reduce 8 slot rows per token → y
// ---------------------------------------------------------------------------
__global__ __launch_bounds__(256) void reduce_kernel(float* __restrict__ y)
{
    int t = blockIdx.x;
    int c = threadIdx.x * 4;
    float4 s = make_float4(0.f, 0.f, 0.f, 0.f);
#pragma unroll
    for (int h = 0; h < H; h++) {
        float4 v = *reinterpret_cast<const float4*>(g_ws + ((size_t)(t * H + h)) * D + c);
        s.x += v.x; s.y += v.y; s.z += v.z; s.w += v.w;
    }
    *reinterpret_cast<float4*>(y + (size_t)t * D + c) = s;
}

// ---------------------------------------------------------------------------
// Kernel 9: finalize aux loss
// ---------------------------------------------------------------------------
__global__ void aux_final_kernel(float* __restrict__ out) {
    if (threadIdx.x == 0) {
        const float inv_bn = 1.0f / (float)BN_TOK;
        float sw = 0.f;
        for (int e = 0; e < E; e++)
            sw += (g_aux[e] * inv_bn) * (g_aux[E + e] * inv_bn);
        float aux = 0.1f * (float)E * sw + 0.001f * (g_aux[2 * E] * inv_bn);
        out[(size_t)BN_TOK * D] = aux;
    }
}

// ---------------------------------------------------------------------------
// Launch
// ---------------------------------------------------------------------------
extern "C" void kernel_launch(void* const* d_in, const int* in_sizes, int n_in,
                              void* d_out, int out_size)
{
    const float* x    = (const float*)d_in[0];
    const int* task_bh = (const int*)d_in[1];
    const float* Wg   = (const float*)d_in[2];
    const float* Wq   = (const float*)d_in[3];
    const float* Wo   = (const float*)d_in[4];
    const float* Wkv  = (const float*)d_in[5];
    const float* bkv  = (const float*)d_in[6];
    float* out = (float*)d_out;

    const int attn_smem = (2 * QT * QH_STR + 2 * 64 * KH_STR +
                           HD * VT2_STR + QT * PS2_STR) * 4;
    const int qg_smem = (2 * TQ * QA_STR + 2 * 32 * QB_STR) * 4 + 2 * TQ * 4;
    cudaFuncSetAttribute(attn_kernel,  cudaFuncAttributeMaxDynamicSharedMemorySize, attn_smem);
    cudaFuncSetAttribute(qgemm_kernel, cudaFuncAttributeMaxDynamicSharedMemorySize, qg_smem);

    init_aux_kernel<<<1, 64>>>();
    gating_kernel<<<BN_TOK / 8, 256>>>(x, task_bh, Wg);
    scan_kernel<<<1, 32>>>();
    scatter_kernel<<<NSLOT / 256, 256>>>();
    kv_kernel<<<dim3(BN_TOK / 64, (2 * HD) / 64), 256>>>(x, Wkv, bkv);
    qgemm_kernel<<<NT_MAX, 512, qg_smem>>>(x, Wq);
    attn_kernel<<<dim3(N / QT, H, B), 256, attn_smem>>>();
    cgemm_kernel<<<dim3(NT_MAX, 8), 256>>>(Wo);
    reduce_kernel<<<BN_TOK, 256>>>(out);
    aux_final_kernel<<<1, 32>>>(out);
}

// round 10
// speedup vs baseline: 1.4552x; 1.0239x over previous
#include <cuda_runtime.h>
#include <cuda_fp16.h>
#include <math.h>
#include <stdint.h>

// ---------------------------------------------------------------------------
// Problem constants
// ---------------------------------------------------------------------------
constexpr int B    = 4;
constexpr int N    = 2048;
constexpr int D    = 1024;
constexpr int E    = 24;
constexpr int H    = 8;
constexpr int HD   = 128;
constexpr int BN_TOK = B * N;          // 8192 tokens
constexpr int NSLOT  = BN_TOK * H;     // 65536 (token,slot) pairs

// Grouped-GEMM tiling
constexpr int TQ = 128;                // rows per expert tile
constexpr int NT_MAX = NSLOT / TQ + E; // 536 max tiles

// ---------------------------------------------------------------------------
// Scratch (device globals — no allocations allowed)
// ---------------------------------------------------------------------------
__device__ float g_kT[HD * BN_TOK];            // 4 MB  K^T: [hd][token]
__device__ float g_v[BN_TOK * HD];             // 4 MB
__device__ float g_q[NSLOT * HD];              // 32 MB  [slot][hd], slot=token*8+h
__device__ float g_attno[NSLOT * HD];          // 32 MB
__device__ float g_ws[(size_t)NSLOT * D];      // 268 MB combine scratch [slot][D]
__device__ int   g_topi[NSLOT];
__device__ float g_gates[NSLOT];
__device__ float g_aux[2 * E + 1];
// expert bucketing
__device__ int g_ecnt[E];
__device__ int g_eoff[E + 1];
__device__ int g_ecursor[E];
__device__ int g_slots[NSLOT];
__device__ int g_tile_e[NT_MAX];
__device__ int g_tile_r0[NT_MAX];
__device__ int g_ntiles;

// ---------------------------------------------------------------------------
// mma helpers
// ---------------------------------------------------------------------------
__device__ __forceinline__ void mma_f16(float* d, const uint32_t* a, const uint32_t* b) {
    asm volatile(
        "mma.sync.aligned.m16n8k16.row.col.f32.f16.f16.f32 "
        "{%0,%1,%2,%3}, {%4,%5,%6,%7}, {%8,%9}, {%0,%1,%2,%3};\n"
        : "+f"(d[0]), "+f"(d[1]), "+f"(d[2]), "+f"(d[3])
        : "r"(a[0]), "r"(a[1]), "r"(a[2]), "r"(a[3]), "r"(b[0]), "r"(b[1]));
}
__device__ __forceinline__ uint32_t fu(float x) { return __float_as_uint(x); }
// split a float pair into f16 hi + f16 lo*1024
__device__ __forceinline__ void h2split(float x, float y, __half2& hi, __half2& lo) {
    hi = __floats2half2_rn(x, y);
    float2 hf = __half22float2(hi);
    lo = __floats2half2_rn((x - hf.x) * 1024.f, (y - hf.y) * 1024.f);
}
constexpr float LO_INV = 1.f / 1024.f;

// ---------------------------------------------------------------------------
// Kernel 0: zero aux + expert histogram
// ---------------------------------------------------------------------------
__global__ void init_aux_kernel() {
    int tid = threadIdx.x;
    if (tid < 2 * E + 1) g_aux[tid] = 0.f;
    if (tid < E) g_ecnt[tid] = 0;
}

// ---------------------------------------------------------------------------
// Kernel 1: gating
// ---------------------------------------------------------------------------
__global__ __launch_bounds__(256) void gating_kernel(
    const float* __restrict__ x, const int* __restrict__ task_bh,
    const float* __restrict__ Wg)
{
    __shared__ float s_aux[2 * E + 1];
    __shared__ int   s_ecnt[E];
    int tid = threadIdx.x;
    if (tid < 2 * E + 1) s_aux[tid] = 0.f;
    if (tid < E) s_ecnt[tid] = 0;
    __syncthreads();

    int warp = tid >> 5, lane = tid & 31;
    int t = blockIdx.x * 8 + warp;
    int b = t >> 11;
    int task = task_bh[b];
    const float* xrow = x + (size_t)t * D;
    const float* wg   = Wg + (size_t)task * D * E;

    float acc[E];
#pragma unroll
    for (int e = 0; e < E; e++) acc[e] = 0.f;

    for (int i = lane; i < D; i += 32) {
        float xv = xrow[i];
        const float4* w4 = reinterpret_cast<const float4*>(wg + (size_t)i * E);
#pragma unroll
        for (int j = 0; j < 6; j++) {
            float4 v = w4[j];
            acc[4*j+0] += xv * v.x; acc[4*j+1] += xv * v.y;
            acc[4*j+2] += xv * v.z; acc[4*j+3] += xv * v.w;
        }
    }
#pragma unroll
    for (int e = 0; e < E; e++) {
#pragma unroll
        for (int off = 16; off >= 1; off >>= 1)
            acc[e] += __shfl_xor_sync(0xffffffffu, acc[e], off);
    }
    float mx = acc[0];
#pragma unroll
    for (int e = 1; e < E; e++) mx = fmaxf(mx, acc[e]);
    float p[E]; float s = 0.f;
#pragma unroll
    for (int e = 0; e < E; e++) { p[e] = __expf(acc[e] - mx); s += p[e]; }
    float inv_s = 1.f / s;
    float lse = mx + __logf(s);

    if (lane < E) atomicAdd(&s_aux[E + lane], p[lane] * inv_s);
    if (lane == 0) {
        atomicAdd(&s_aux[2 * E], lse * lse);
        float tv[H]; int ti[H]; float gsum = 0.f;
#pragma unroll
        for (int h = 0; h < H; h++) {
            float best = -1.f; int bi = 0;
#pragma unroll
            for (int e = 0; e < E; e++)
                if (p[e] > best) { best = p[e]; bi = e; }
            tv[h] = best * inv_s; ti[h] = bi; p[bi] = -2.f;
            gsum += tv[h];
            atomicAdd(&s_aux[bi], 1.0f);
            atomicAdd(&s_ecnt[bi], 1);
        }
        float ig = 1.f / gsum;
#pragma unroll
        for (int h = 0; h < H; h++) {
            g_topi[t * H + h]  = ti[h];
            g_gates[t * H + h] = tv[h] * ig;
        }
    }
    __syncthreads();
    if (tid < 2 * E + 1) atomicAdd(&g_aux[tid], s_aux[tid]);
    if (tid < E) atomicAdd(&g_ecnt[tid], s_ecnt[tid]);
}

// ---------------------------------------------------------------------------
// Kernel 2: serial scan over experts → offsets + tile table
// ---------------------------------------------------------------------------
__global__ void scan_kernel() {
    if (threadIdx.x == 0) {
        int off = 0, nt = 0;
        for (int e = 0; e < E; e++) {
            g_eoff[e] = off;
            g_ecursor[e] = 0;
            int c = g_ecnt[e];
            for (int r = 0; r < c; r += TQ) {
                g_tile_e[nt]  = e;
                g_tile_r0[nt] = off + r;
                nt++;
            }
            off += c;
        }
        g_eoff[E] = off;
        g_ntiles = nt;
    }
}

// ---------------------------------------------------------------------------
// Kernel 3: scatter slot ids into expert buckets
// ---------------------------------------------------------------------------
__global__ void scatter_kernel() {
    int i = blockIdx.x * 256 + threadIdx.x;
    int e = g_topi[i];
    int pos = atomicAdd(&g_ecursor[e], 1);
    g_slots[g_eoff[e] + pos] = i;
}

// ---------------------------------------------------------------------------
// Kernel 4: kv = x @ Wkv + bkv  → g_kT (transposed), g_v
// ---------------------------------------------------------------------------
__global__ __launch_bounds__(256) void kv_kernel(
    const float* __restrict__ x, const float* __restrict__ Wkv,
    const float* __restrict__ bkv)
{
    __shared__ float As[64][17];
    __shared__ float Bs[16][64];
    int tid = threadIdx.x;
    int tx = tid & 15, ty = tid >> 4;
    int t0 = blockIdx.x * 64;
    int n0 = blockIdx.y * 64;

    float acc[4][4] = {};

    for (int k0 = 0; k0 < D; k0 += 16) {
#pragma unroll
        for (int i = 0; i < 4; i++) {
            int idx = tid + i * 256;
            int r = idx >> 4, kk = idx & 15;
            As[r][kk] = x[(size_t)(t0 + r) * D + k0 + kk];
        }
#pragma unroll
        for (int i = 0; i < 4; i++) {
            int idx = tid + i * 256;
            int kr = idx >> 6, nn = idx & 63;
            Bs[kr][nn] = Wkv[(size_t)(k0 + kr) * (2 * HD) + n0 + nn];
        }
        __syncthreads();
#pragma unroll
        for (int kk = 0; kk < 16; kk++) {
            float a[4];
#pragma unroll
            for (int i = 0; i < 4; i++) a[i] = As[ty * 4 + i][kk];
            float4 bv = *reinterpret_cast<const float4*>(&Bs[kk][tx * 4]);
            float bb[4] = {bv.x, bv.y, bv.z, bv.w};
#pragma unroll
            for (int i = 0; i < 4; i++)
#pragma unroll
                for (int j = 0; j < 4; j++)
                    acc[i][j] += a[i] * bb[j];
        }
        __syncthreads();
    }
#pragma unroll
    for (int i = 0; i < 4; i++) {
        int t = t0 + ty * 4 + i;
#pragma unroll
        for (int j = 0; j < 4; j++) {
            int c = n0 + tx * 4 + j;
            float v = acc[i][j] + bkv[c];
            if (c < HD) g_kT[(size_t)c * BN_TOK + t] = v;
            else        g_v[(size_t)t * HD + (c - HD)] = v;
        }
    }
}

// ---------------------------------------------------------------------------
// Kernel 5: grouped q GEMM — f16 error-compensated mma (hi + lo*2^10),
// 512 threads: warp = (row-group 0..7, col-half 0..1); M=128, N=128, K=1024.
// ---------------------------------------------------------------------------
constexpr int QG_K  = 64;    // floats per k-chunk (32 pairs)
constexpr int QA_STR = 36;   // Ahi/Alo [row 128][kpair 32 + pad]  (half2)
constexpr int QB_STR = 136;  // Bhi/Blo [kpair 32][n 128 + pad]    (half2)

__global__ __launch_bounds__(512, 1) void qgemm_kernel(
    const float* __restrict__ x, const float* __restrict__ Wq)
{
    extern __shared__ __half2 qsm[];
    __half2* Ahi = qsm;                    // 128*36
    __half2* Alo = Ahi + TQ * QA_STR;      // 128*36
    __half2* Bhi = Alo + TQ * QA_STR;      // 32*136
    __half2* Blo = Bhi + 32 * QB_STR;      // 32*136
    int* s_tok  = reinterpret_cast<int*>(Blo + 32 * QB_STR);   // 128
    int* s_slot = s_tok + TQ;                                   // 128

    int t = blockIdx.x;
    if (t >= g_ntiles) return;
    int e = g_tile_e[t], r0 = g_tile_r0[t];
    int rend = g_eoff[e + 1];
    int tid = threadIdx.x;

    if (tid < TQ) {
        int gr = r0 + tid;
        if (gr >= rend) gr = r0;       // padded rows duplicate row0 (not written back)
        int s = g_slots[gr];
        s_slot[tid] = s;
        s_tok[tid]  = s >> 3;
    }
    __syncthreads();

    int warp = tid >> 5, lane = tid & 31;
    int g = lane >> 2, tg = lane & 3;
    int rg = warp & 7, ch = warp >> 3;     // row-group, col-half
    int r_a = rg * 16 + g, r_b = r_a + 8;
    const float* wq = Wq + (size_t)e * D * HD;

    float scc[8][4] = {};
    float scl[8][4] = {};

    for (int k0 = 0; k0 < D; k0 += QG_K) {
        // A: 128 rows x 64 k (gathered), split to f16 hi/lo
        for (int idx = tid; idx < TQ * (QG_K / 4); idx += 512) {
            int r = idx >> 4, kq = (idx & 15) * 4;
            float4 av = *reinterpret_cast<const float4*>(
                x + (size_t)s_tok[r] * D + k0 + kq);
            __half2 h0, l0, h1, l1;
            h2split(av.x, av.y, h0, l0);
            h2split(av.z, av.w, h1, l1);
            int p0 = kq >> 1;
            Ahi[r * QA_STR + p0]     = h0;
            Ahi[r * QA_STR + p0 + 1] = h1;
            Alo[r * QA_STR + p0]     = l0;
            Alo[r * QA_STR + p0 + 1] = l1;
        }
        // B: pair-major [kpair 32][n 128]: half2(Wq[2p][n], Wq[2p+1][n])
        for (int idx = tid; idx < 32 * 32; idx += 512) {
            int p  = idx >> 5;
            int nq = (idx & 31) * 4;
            const float* w0 = wq + (size_t)(k0 + 2 * p)     * HD + nq;
            const float* w1 = wq + (size_t)(k0 + 2 * p + 1) * HD + nq;
            float4 fa = *reinterpret_cast<const float4*>(w0);
            float4 fb = *reinterpret_cast<const float4*>(w1);
            __half2 hh, ll;
            h2split(fa.x, fb.x, hh, ll);
            Bhi[p * QB_STR + nq + 0] = hh; Blo[p * QB_STR + nq + 0] = ll;
            h2split(fa.y, fb.y, hh, ll);
            Bhi[p * QB_STR + nq + 1] = hh; Blo[p * QB_STR + nq + 1] = ll;
            h2split(fa.z, fb.z, hh, ll);
            Bhi[p * QB_STR + nq + 2] = hh; Blo[p * QB_STR + nq + 2] = ll;
            h2split(fa.w, fb.w, hh, ll);
            Bhi[p * QB_STR + nq + 3] = hh; Blo[p * QB_STR + nq + 3] = ll;
        }
        __syncthreads();

#pragma unroll
        for (int ks = 0; ks < 4; ks++) {
            const __half2* ah0 = Ahi + r_a * QA_STR + 8 * ks + tg;
            const __half2* ah1 = Ahi + r_b * QA_STR + 8 * ks + tg;
            const __half2* al0 = Alo + r_a * QA_STR + 8 * ks + tg;
            const __half2* al1 = Alo + r_b * QA_STR + 8 * ks + tg;
            uint32_t ah[4] = { *reinterpret_cast<const uint32_t*>(ah0),
                               *reinterpret_cast<const uint32_t*>(ah1),
                               *reinterpret_cast<const uint32_t*>(ah0 + 4),
                               *reinterpret_cast<const uint32_t*>(ah1 + 4) };
            uint32_t al[4] = { *reinterpret_cast<const uint32_t*>(al0),
                               *reinterpret_cast<const uint32_t*>(al1),
                               *reinterpret_cast<const uint32_t*>(al0 + 4),
                               *reinterpret_cast<const uint32_t*>(al1 + 4) };
            const __half2* bh0 = Bhi + (8 * ks + tg) * QB_STR + ch * 64 + g;
            const __half2* bh1 = Bhi + (8 * ks + 4 + tg) * QB_STR + ch * 64 + g;
            const __half2* bl0 = Blo + (8 * ks + tg) * QB_STR + ch * 64 + g;
            const __half2* bl1 = Blo + (8 * ks + 4 + tg) * QB_STR + ch * 64 + g;
#pragma unroll
            for (int nc = 0; nc < 8; nc++) {
                uint32_t bh[2] = { *reinterpret_cast<const uint32_t*>(bh0 + 8 * nc),
                                   *reinterpret_cast<const uint32_t*>(bh1 + 8 * nc) };
                uint32_t bl[2] = { *reinterpret_cast<const uint32_t*>(bl0 + 8 * nc),
                                   *reinterpret_cast<const uint32_t*>(bl1 + 8 * nc) };
                mma_f16(scc[nc], ah, bh);
                mma_f16(scl[nc], al, bh);
                mma_f16(scl[nc], ah, bl);
            }
        }
        __syncthreads();
    }

    bool va = (r0 + r_a < rend), vb = (r0 + r_b < rend);
    float* da = g_q + (size_t)s_slot[r_a] * HD + ch * 64;
    float* db = g_q + (size_t)s_slot[r_b] * HD + ch * 64;
#pragma unroll
    for (int nc = 0; nc < 8; nc++) {
        int c = 8 * nc + 2 * tg;
        float o0 = scc[nc][0] + scl[nc][0] * LO_INV;
        float o1 = scc[nc][1] + scl[nc][1] * LO_INV;
        float o2 = scc[nc][2] + scl[nc][2] * LO_INV;
        float o3 = scc[nc][3] + scl[nc][3] * LO_INV;
        if (va) *reinterpret_cast<float2*>(da + c) = make_float2(o0, o1);
        if (vb) *reinterpret_cast<float2*>(db + c) = make_float2(o2, o3);
    }
}

// ---------------------------------------------------------------------------
// Kernel 6: flash attention — QK^T via f16 error-compensated mma.m16n8k16,
// softmax in log2 domain with ex2.approx.f16x2, P fp16, PV fp16 mma.
// block = 256 threads (8 warps), q-tile 128 rows, KV-tile 64.
// ---------------------------------------------------------------------------
constexpr int QT = 128;
constexpr int KT = 64;
constexpr int QH_STR  = 68;   // Qhi/Qlo [row 128][hd-pair 64 + pad]   (half2)
constexpr int KH_STR  = 72;   // Khi/Klo [hd-pair 64][kv 64 + pad]     (half2)
constexpr int VT2_STR = 36;   // VhT2 [hd 128][kv-pair 32 + pad]       (half2)
constexpr int PS2_STR = 36;   // Ps2  [row 128][kv-pair 32 + pad]      (half2)

__global__ __launch_bounds__(256, 1) void attn_kernel()
{
    extern __shared__ __half2 smh[];
    __half2* Qhi  = smh;                     // 128*68
    __half2* Qlo  = Qhi  + QT * QH_STR;      // 128*68
    __half2* Khi  = Qlo  + QT * QH_STR;      // 64*72
    __half2* Klo  = Khi  + 64 * KH_STR;      // 64*72
    __half2* VhT2 = Klo  + 64 * KH_STR;      // 128*36
    __half2* Ps2  = VhT2 + HD * VT2_STR;     // 128*36

    int tid  = threadIdx.x;
    int warp = tid >> 5, lane = tid & 31;
    int g = lane >> 2, tg = lane & 3;
    int n0 = blockIdx.x * QT;
    int h  = blockIdx.y;
    int b  = blockIdx.z;
    int bN0 = b * N;
    // scale * log2(e): softmax computed in log2 domain
    const float qsc = 0.08838834764831845f * 1.44269504088896340736f;

    // load Q once: scale, split into f16 hi / lo*2^10
    for (int idx = tid; idx < QT * (HD / 4); idx += 256) {
        int r = idx >> 5, kq = (idx & 31) * 4;
        float4 qv = *reinterpret_cast<const float4*>(
            g_q + (((size_t)(bN0 + n0 + r)) * H + h) * HD + kq);
        qv.x *= qsc; qv.y *= qsc; qv.z *= qsc; qv.w *= qsc;
        __half2 h0, l0, h1, l1;
        h2split(qv.x, qv.y, h0, l0);
        h2split(qv.z, qv.w, h1, l1);
        int p0 = kq >> 1;
        Qhi[r * QH_STR + p0]     = h0;
        Qhi[r * QH_STR + p0 + 1] = h1;
        Qlo[r * QH_STR + p0]     = l0;
        Qlo[r * QH_STR + p0 + 1] = l1;
    }

    const int r_a = warp * 16 + g;
    const int r_b = r_a + 8;

    float o[16][4];
#pragma unroll
    for (int nc = 0; nc < 16; nc++)
#pragma unroll
        for (int j = 0; j < 4; j++) o[nc][j] = 0.f;
    float m_a = -1e30f, m_b = -1e30f, l_a = 0.f, l_b = 0.f;

    for (int m0 = 0; m0 < N; m0 += KT) {
        __syncthreads();   // prev tile consumed (also covers initial Q load)
        // K tile: pair-major Khi/Klo[p][m] = half2(K[m][2p], K[m][2p+1])
        for (int idx = tid; idx < 64 * 16; idx += 256) {
            int p  = idx >> 4;
            int mq = (idx & 15) * 4;
            const float* kr0 = g_kT + (size_t)(2 * p)     * BN_TOK + bN0 + m0 + mq;
            const float* kr1 = g_kT + (size_t)(2 * p + 1) * BN_TOK + bN0 + m0 + mq;
            float4 fa = *reinterpret_cast<const float4*>(kr0);
            float4 fb = *reinterpret_cast<const float4*>(kr1);
            __half2 hh, ll;
            h2split(fa.x, fb.x, hh, ll);
            Khi[p * KH_STR + mq + 0] = hh; Klo[p * KH_STR + mq + 0] = ll;
            h2split(fa.y, fb.y, hh, ll);
            Khi[p * KH_STR + mq + 1] = hh; Klo[p * KH_STR + mq + 1] = ll;
            h2split(fa.z, fb.z, hh, ll);
            Khi[p * KH_STR + mq + 2] = hh; Klo[p * KH_STR + mq + 2] = ll;
            h2split(fa.w, fb.w, hh, ll);
            Khi[p * KH_STR + mq + 3] = hh; Klo[p * KH_STR + mq + 3] = ll;
        }
        // V tile transposed to half2: VhT2[hd][kvpair] = (V[2p][hd], V[2p+1][hd])
        for (int idx = tid; idx < (KT / 2) * (HD / 4); idx += 256) {
            int p  = idx & 31;             // kv pair 0..31
            int kq = (idx >> 5) * 4;       // hd quad
            float4 fa = *reinterpret_cast<const float4*>(
                g_v + ((size_t)(bN0 + m0 + 2 * p)) * HD + kq);
            float4 fb = *reinterpret_cast<const float4*>(
                g_v + ((size_t)(bN0 + m0 + 2 * p + 1)) * HD + kq);
            VhT2[(kq + 0) * VT2_STR + p] = __floats2half2_rn(fa.x, fb.x);
            VhT2[(kq + 1) * VT2_STR + p] = __floats2half2_rn(fa.y, fb.y);
            VhT2[(kq + 2) * VT2_STR + p] = __floats2half2_rn(fa.z, fb.z);
            VhT2[(kq + 3) * VT2_STR + p] = __floats2half2_rn(fa.w, fb.w);
        }
        __syncthreads();

        // ---- S = Q K^T : 16 x 64 per warp, f16 compensated, k16 steps ----
        float scc[8][4] = {};
        float scl[8][4] = {};
#pragma unroll
        for (int ks = 0; ks < 8; ks++) {
            const __half2* qh0 = Qhi + r_a * QH_STR + 8 * ks + tg;
            const __half2* qh1 = Qhi + r_b * QH_STR + 8 * ks + tg;
            const __half2* ql0 = Qlo + r_a * QH_STR + 8 * ks + tg;
            const __half2* ql1 = Qlo + r_b * QH_STR + 8 * ks + tg;
            uint32_t ah[4] = { *reinterpret_cast<const uint32_t*>(qh0),
                               *reinterpret_cast<const uint32_t*>(qh1),
                               *reinterpret_cast<const uint32_t*>(qh0 + 4),
                               *reinterpret_cast<const uint32_t*>(qh1 + 4) };
            uint32_t al[4] = { *reinterpret_cast<const uint32_t*>(ql0),
                               *reinterpret_cast<const uint32_t*>(ql1),
                               *reinterpret_cast<const uint32_t*>(ql0 + 4),
                               *reinterpret_cast<const uint32_t*>(ql1 + 4) };
            const __half2* kh0 = Khi + (8 * ks + tg) * KH_STR + g;
            const __half2* kh1 = Khi + (8 * ks + 4 + tg) * KH_STR + g;
            const __half2* kl0 = Klo + (8 * ks + tg) * KH_STR + g;
            const __half2* kl1 = Klo + (8 * ks + 4 + tg) * KH_STR + g;
#pragma unroll
            for (int nc = 0; nc < 8; nc++) {
                uint32_t bh[2] = { *reinterpret_cast<const uint32_t*>(kh0 + 8 * nc),
                                   *reinterpret_cast<const uint32_t*>(kh1 + 8 * nc) };
                uint32_t bl[2] = { *reinterpret_cast<const uint32_t*>(kl0 + 8 * nc),
                                   *reinterpret_cast<const uint32_t*>(kl1 + 8 * nc) };
                mma_f16(scc[nc], ah, bh);
                mma_f16(scl[nc], al, bh);
                mma_f16(scl[nc], ah, bl);
            }
        }
        // combine: S = hi·hi + 2^-10 * cross
#pragma unroll
        for (int nc = 0; nc < 8; nc++)
#pragma unroll
            for (int j = 0; j < 4; j++)
                scc[nc][j] += scl[nc][j] * LO_INV;

        // ---- online softmax (log2 domain, f16x2 ex2) ----
        float lm_a = -1e30f, lm_b = -1e30f;
#pragma unroll
        for (int nc = 0; nc < 8; nc++) {
            lm_a = fmaxf(lm_a, fmaxf(scc[nc][0], scc[nc][1]));
            lm_b = fmaxf(lm_b, fmaxf(scc[nc][2], scc[nc][3]));
        }
#pragma unroll
        for (int off = 1; off <= 2; off <<= 1) {
            lm_a = fmaxf(lm_a, __shfl_xor_sync(0xffffffffu, lm_a, off));
            lm_b = fmaxf(lm_b, __shfl_xor_sync(0xffffffffu, lm_b, off));
        }
        float mn_a = fmaxf(m_a, lm_a), mn_b = fmaxf(m_b, lm_b);
        float al_a = exp2f(m_a - mn_a), al_b = exp2f(m_b - mn_b);
        m_a = mn_a; m_b = mn_b;

        float rs_a = 0.f, rs_b = 0.f;
#pragma unroll
        for (int nc = 0; nc < 8; nc++) {
            __half2 ha = h2exp2(__floats2half2_rn(scc[nc][0] - mn_a, scc[nc][1] - mn_a));
            __half2 hb = h2exp2(__floats2half2_rn(scc[nc][2] - mn_b, scc[nc][3] - mn_b));
            int cp = 4 * nc + tg;
            Ps2[r_a * PS2_STR + cp] = ha;
            Ps2[r_b * PS2_STR + cp] = hb;
            float2 fa = __half22float2(ha);
            float2 fb = __half22float2(hb);
            rs_a += fa.x + fa.y;
            rs_b += fb.x + fb.y;
        }
#pragma unroll
        for (int off = 1; off <= 2; off <<= 1) {
            rs_a += __shfl_xor_sync(0xffffffffu, rs_a, off);
            rs_b += __shfl_xor_sync(0xffffffffu, rs_b, off);
        }
        l_a = l_a * al_a + rs_a;
        l_b = l_b * al_b + rs_b;
#pragma unroll
        for (int nc = 0; nc < 16; nc++) {
            o[nc][0] *= al_a; o[nc][1] *= al_a;
            o[nc][2] *= al_b; o[nc][3] *= al_b;
        }

        // ---- O += P V : fp16 m16n8k16, per-warp-private Ps2, no sync ----
#pragma unroll
        for (int ks = 0; ks < 4; ks++) {
            const __half2* pa0 = Ps2 + r_a * PS2_STR + 8 * ks + tg;
            const __half2* pa1 = Ps2 + r_b * PS2_STR + 8 * ks + tg;
            uint32_t a[4];
            a[0] = *reinterpret_cast<const uint32_t*>(pa0);
            a[1] = *reinterpret_cast<const uint32_t*>(pa1);
            a[2] = *reinterpret_cast<const uint32_t*>(pa0 + 4);
            a[3] = *reinterpret_cast<const uint32_t*>(pa1 + 4);
#pragma unroll
            for (int nc = 0; nc < 16; nc++) {
                const __half2* vb = VhT2 + (8 * nc + g) * VT2_STR + 8 * ks + tg;
                uint32_t bb[2];
                bb[0] = *reinterpret_cast<const uint32_t*>(vb);
                bb[1] = *reinterpret_cast<const uint32_t*>(vb + 4);
                mma_f16(o[nc], a, bb);
            }
        }
    }

    float inv_a = 1.f / l_a, inv_b = 1.f / l_b;
    float* dsta = g_attno + (((size_t)(bN0 + n0 + r_a)) * H + h) * HD;
    float* dstb = g_attno + (((size_t)(bN0 + n0 + r_b)) * H + h) * HD;
#pragma unroll
    for (int nc = 0; nc < 16; nc++) {
        *reinterpret_cast<float2*>(dsta + 8 * nc + 2 * tg) =
            make_float2(o[nc][0] * inv_a, o[nc][1] * inv_a);
        *reinterpret_cast<float2*>(dstb + 8 * nc + 2 * tg) =
            make_float2(o[nc][2] * inv_b, o[nc][3] * inv_b);
    }
}

// ---------------------------------------------------------------------------
// Kernel 7: grouped combine GEMM — single-pass f16 (same 2^-11 mantissa as
// tf32; operands well within f16 range). K=HD loaded once; single sync;
// 2 CTAs/SM.
// ---------------------------------------------------------------------------
constexpr int CA_STR = 68;    // A2 [row 128][kpair 64 + pad]  (half2)
constexpr int CB_STR = 136;   // B2 [kpair 64][n 128 + pad]    (half2)

__global__ __launch_bounds__(256, 2) void cgemm_kernel(const float* __restrict__ Wo)
{
    extern __shared__ __half2 csm[];
    __half2* A2 = csm;                  // 128*68
    __half2* B2 = A2 + TQ * CA_STR;     // 64*136
    int*   s_slot = reinterpret_cast<int*>(B2 + 64 * CB_STR);  // 128
    float* s_gate = reinterpret_cast<float*>(s_slot + TQ);     // 128

    int t = blockIdx.x;
    if (t >= g_ntiles) return;
    int n0 = blockIdx.y * 128;
    int e = g_tile_e[t], r0 = g_tile_r0[t];
    int rend = g_eoff[e + 1];
    int tid = threadIdx.x;

    if (tid < TQ) {
        int gr = r0 + tid;
        if (gr >= rend) gr = r0;
        int s = g_slots[gr];
        s_slot[tid] = s;
        s_gate[tid] = g_gates[s];
    }
    __syncthreads();

    // A: attn_out rows → f16, [row][kpair 64]
    for (int idx = tid; idx < TQ * (HD / 4); idx += 256) {
        int r = idx >> 5, kq = (idx & 31) * 4;
        float4 av = *reinterpret_cast<const float4*>(
            g_attno + (size_t)s_slot[r] * HD + kq);
        int p0 = kq >> 1;
        A2[r * CA_STR + p0]     = __floats2half2_rn(av.x, av.y);
        A2[r * CA_STR + p0 + 1] = __floats2half2_rn(av.z, av.w);
    }
    // B: Wo pair-major [kpair 64][n 128]: half2(Wo[2p][n], Wo[2p+1][n])
    const float* wo = Wo + (size_t)e * HD * D;
    for (int idx = tid; idx < 64 * 32; idx += 256) {
        int p  = idx >> 5;
        int nq = (idx & 31) * 4;
        const float* w0 = wo + (size_t)(2 * p)     * D + n0 + nq;
        const float* w1 = wo + (size_t)(2 * p + 1) * D + n0 + nq;
        float4 fa = *reinterpret_cast<const float4*>(w0);
        float4 fb = *reinterpret_cast<const float4*>(w1);
        B2[p * CB_STR + nq + 0] = __floats2half2_rn(fa.x, fb.x);
        B2[p * CB_STR + nq + 1] = __floats2half2_rn(fa.y, fb.y);
        B2[p * CB_STR + nq + 2] = __floats2half2_rn(fa.z, fb.z);
        B2[p * CB_STR + nq + 3] = __floats2half2_rn(fa.w, fb.w);
    }
    __syncthreads();

    int warp = tid >> 5, lane = tid & 31;
    int g = lane >> 2, tg = lane & 3;
    int r_a = warp * 16 + g, r_b = r_a + 8;

    float acc[16][4] = {};

#pragma unroll
    for (int ks = 0; ks < 8; ks++) {
        const __half2* a0 = A2 + r_a * CA_STR + 8 * ks + tg;
        const __half2* a1 = A2 + r_b * CA_STR + 8 * ks + tg;
        uint32_t a[4] = { *reinterpret_cast<const uint32_t*>(a0),
                          *reinterpret_cast<const uint32_t*>(a1),
                          *reinterpret_cast<const uint32_t*>(a0 + 4),
                          *reinterpret_cast<const uint32_t*>(a1 + 4) };
        const __half2* b0 = B2 + (8 * ks + tg) * CB_STR + g;
        const __half2* b1 = B2 + (8 * ks + 4 + tg) * CB_STR + g;
#pragma unroll
        for (int nc = 0; nc < 16; nc++) {
            uint32_t bb[2] = { *reinterpret_cast<const uint32_t*>(b0 + 8 * nc),
                               *reinterpret_cast<const uint32_t*>(b1 + 8 * nc) };
            mma_f16(acc[nc], a, bb);
        }
    }

    bool va = (r0 + r_a < rend), vb = (r0 + r_b < rend);
    float ga = s_gate[r_a], gb = s_gate[r_b];
    float* da = g_ws + (size_t)s_slot[r_a] * D + n0;
    float* db = g_ws + (size_t)s_slot[r_b] * D + n0;
#pragma unroll
    for (int nc = 0; nc < 16; nc++) {
        int c = 8 * nc + 2 * tg;
        if (va) *reinterpret_cast<float2*>(da + c) = make_float2(acc[nc][0] * ga, acc[nc][1] * ga);
        if (vb) *reinterpret_cast<float2*>(db + c) = make_float2(acc[nc][2] * gb, acc[nc][3] * gb);
    }
}

// ---------------------------------------------------------------------------
// Kernel 8: reduce 8 slot rows per token → y
// ---------------------------------------------------------------------------
__global__ __launch_bounds__(256) void reduce_kernel(float* __restrict__ y)
{
    int t = blockIdx.x;
    int c = threadIdx.x * 4;
    float4 s = make_float4(0.f, 0.f, 0.f, 0.f);
#pragma unroll
    for (int h = 0; h < H; h++) {
        float4 v = *reinterpret_cast<const float4*>(g_ws + ((size_t)(t * H + h)) * D + c);
        s.x += v.x; s.y += v.y; s.z += v.z; s.w += v.w;
    }
    *reinterpret_cast<float4*>(y + (size_t)t * D + c) = s;
}

// ---------------------------------------------------------------------------
// Kernel 9: finalize aux loss
// ---------------------------------------------------------------------------
__global__ void aux_final_kernel(float* __restrict__ out) {
    if (threadIdx.x == 0) {
        const float inv_bn = 1.0f / (float)BN_TOK;
        float sw = 0.f;
        for (int e = 0; e < E; e++)
            sw += (g_aux[e] * inv_bn) * (g_aux[E + e] * inv_bn);
        float aux = 0.1f * (float)E * sw + 0.001f * (g_aux[2 * E] * inv_bn);
        out[(size_t)BN_TOK * D] = aux;
    }
}

// ---------------------------------------------------------------------------
// Launch
// ---------------------------------------------------------------------------
extern "C" void kernel_launch(void* const* d_in, const int* in_sizes, int n_in,
                              void* d_out, int out_size)
{
    const float* x    = (const float*)d_in[0];
    const int* task_bh = (const int*)d_in[1];
    const float* Wg   = (const float*)d_in[2];
    const float* Wq   = (const float*)d_in[3];
    const float* Wo   = (const float*)d_in[4];
    const float* Wkv  = (const float*)d_in[5];
    const float* bkv  = (const float*)d_in[6];
    float* out = (float*)d_out;

    const int attn_smem = (2 * QT * QH_STR + 2 * 64 * KH_STR +
                           HD * VT2_STR + QT * PS2_STR) * 4;
    const int qg_smem = (2 * TQ * QA_STR + 2 * 32 * QB_STR) * 4 + 2 * TQ * 4;
    const int cg_smem = (TQ * CA_STR + 64 * CB_STR) * 4 + 2 * TQ * 4;
    cudaFuncSetAttribute(attn_kernel,  cudaFuncAttributeMaxDynamicSharedMemorySize, attn_smem);
    cudaFuncSetAttribute(qgemm_kernel, cudaFuncAttributeMaxDynamicSharedMemorySize, qg_smem);
    cudaFuncSetAttribute(cgemm_kernel, cudaFuncAttributeMaxDynamicSharedMemorySize, cg_smem);

    init_aux_kernel<<<1, 64>>>();
    gating_kernel<<<BN_TOK / 8, 256>>>(x, task_bh, Wg);
    scan_kernel<<<1, 32>>>();
    scatter_kernel<<<NSLOT / 256, 256>>>();
    kv_kernel<<<dim3(BN_TOK / 64, (2 * HD) / 64), 256>>>(x, Wkv, bkv);
    qgemm_kernel<<<NT_MAX, 512, qg_smem>>>(x, Wq);
    attn_kernel<<<dim3(N / QT, H, B), 256, attn_smem>>>();
    cgemm_kernel<<<dim3(NT_MAX, 8), 256, cg_smem>>>(Wo);
    reduce_kernel<<<BN_TOK, 256>>>(out);
    aux_final_kernel<<<1, 32>>>(out);
}

// round 11
// speedup vs baseline: 1.5552x; 1.0687x over previous
#include <cuda_runtime.h>
#include <cuda_fp16.h>
#include <math.h>
#include <stdint.h>

// ---------------------------------------------------------------------------
// Problem constants
// ---------------------------------------------------------------------------
constexpr int B    = 4;
constexpr int N    = 2048;
constexpr int D    = 1024;
constexpr int E    = 24;
constexpr int H    = 8;
constexpr int HD   = 128;
constexpr int BN_TOK = B * N;          // 8192 tokens
constexpr int NSLOT  = BN_TOK * H;     // 65536 (token,slot) pairs

// Grouped-GEMM tiling
constexpr int TQ = 128;                // rows per expert tile
constexpr int NT_MAX = NSLOT / TQ + E; // 536 max tiles

// ---------------------------------------------------------------------------
// Scratch (device globals — no allocations allowed)
// ---------------------------------------------------------------------------
__device__ __half2 g_kh2[(HD / 2) * BN_TOK];   // 2 MB  K hi,  pair-major [hd-pair][token]
__device__ __half2 g_kl2[(HD / 2) * BN_TOK];   // 2 MB  K lo*2^10
__device__ __half2 g_vh2[HD * (BN_TOK / 2)];   // 2 MB  V f16 transposed [hd][token-pair]
__device__ float   g_q[NSLOT * HD];            // 32 MB [slot][hd]
__device__ __half2 g_attno2[NSLOT * (HD / 2)]; // 16 MB attn out f16 [slot][hd-pair]
__device__ float   g_ws[(size_t)NSLOT * D];    // 268 MB combine scratch [slot][D]
__device__ int   g_topi[NSLOT];
__device__ float g_gates[NSLOT];
__device__ float g_aux[2 * E + 1];
// expert bucketing
__device__ int g_ecnt[E];
__device__ int g_eoff[E + 1];
__device__ int g_ecursor[E];
__device__ int g_slots[NSLOT];
__device__ int g_tile_e[NT_MAX];
__device__ int g_tile_r0[NT_MAX];
__device__ int g_ntiles;

// ---------------------------------------------------------------------------
// mma helpers
// ---------------------------------------------------------------------------
__device__ __forceinline__ void mma_f16(float* d, const uint32_t* a, const uint32_t* b) {
    asm volatile(
        "mma.sync.aligned.m16n8k16.row.col.f32.f16.f16.f32 "
        "{%0,%1,%2,%3}, {%4,%5,%6,%7}, {%8,%9}, {%0,%1,%2,%3};\n"
        : "+f"(d[0]), "+f"(d[1]), "+f"(d[2]), "+f"(d[3])
        : "r"(a[0]), "r"(a[1]), "r"(a[2]), "r"(a[3]), "r"(b[0]), "r"(b[1]));
}
// split a float pair into f16 hi + f16 lo*1024
__device__ __forceinline__ void h2split(float x, float y, __half2& hi, __half2& lo) {
    hi = __floats2half2_rn(x, y);
    float2 hf = __half22float2(hi);
    lo = __floats2half2_rn((x - hf.x) * 1024.f, (y - hf.y) * 1024.f);
}
constexpr float LO_INV = 1.f / 1024.f;

// ---------------------------------------------------------------------------
// Kernel 0: zero aux + expert histogram
// ---------------------------------------------------------------------------
__global__ void init_aux_kernel() {
    int tid = threadIdx.x;
    if (tid < 2 * E + 1) g_aux[tid] = 0.f;
    if (tid < E) g_ecnt[tid] = 0;
}

// ---------------------------------------------------------------------------
// Kernel 1: gating
// ---------------------------------------------------------------------------
__global__ __launch_bounds__(256) void gating_kernel(
    const float* __restrict__ x, const int* __restrict__ task_bh,
    const float* __restrict__ Wg)
{
    __shared__ float s_aux[2 * E + 1];
    __shared__ int   s_ecnt[E];
    int tid = threadIdx.x;
    if (tid < 2 * E + 1) s_aux[tid] = 0.f;
    if (tid < E) s_ecnt[tid] = 0;
    __syncthreads();

    int warp = tid >> 5, lane = tid & 31;
    int t = blockIdx.x * 8 + warp;
    int b = t >> 11;
    int task = task_bh[b];
    const float* xrow = x + (size_t)t * D;
    const float* wg   = Wg + (size_t)task * D * E;

    float acc[E];
#pragma unroll
    for (int e = 0; e < E; e++) acc[e] = 0.f;

    for (int i = lane; i < D; i += 32) {
        float xv = xrow[i];
        const float4* w4 = reinterpret_cast<const float4*>(wg + (size_t)i * E);
#pragma unroll
        for (int j = 0; j < 6; j++) {
            float4 v = w4[j];
            acc[4*j+0] += xv * v.x; acc[4*j+1] += xv * v.y;
            acc[4*j+2] += xv * v.z; acc[4*j+3] += xv * v.w;
        }
    }
#pragma unroll
    for (int e = 0; e < E; e++) {
#pragma unroll
        for (int off = 16; off >= 1; off >>= 1)
            acc[e] += __shfl_xor_sync(0xffffffffu, acc[e], off);
    }
    float mx = acc[0];
#pragma unroll
    for (int e = 1; e < E; e++) mx = fmaxf(mx, acc[e]);
    float p[E]; float s = 0.f;
#pragma unroll
    for (int e = 0; e < E; e++) { p[e] = __expf(acc[e] - mx); s += p[e]; }
    float inv_s = 1.f / s;
    float lse = mx + __logf(s);

    if (lane < E) atomicAdd(&s_aux[E + lane], p[lane] * inv_s);
    if (lane == 0) {
        atomicAdd(&s_aux[2 * E], lse * lse);
        float tv[H]; int ti[H]; float gsum = 0.f;
#pragma unroll
        for (int h = 0; h < H; h++) {
            float best = -1.f; int bi = 0;
#pragma unroll
            for (int e = 0; e < E; e++)
                if (p[e] > best) { best = p[e]; bi = e; }
            tv[h] = best * inv_s; ti[h] = bi; p[bi] = -2.f;
            gsum += tv[h];
            atomicAdd(&s_aux[bi], 1.0f);
            atomicAdd(&s_ecnt[bi], 1);
        }
        float ig = 1.f / gsum;
#pragma unroll
        for (int h = 0; h < H; h++) {
            g_topi[t * H + h]  = ti[h];
            g_gates[t * H + h] = tv[h] * ig;
        }
    }
    __syncthreads();
    if (tid < 2 * E + 1) atomicAdd(&g_aux[tid], s_aux[tid]);
    if (tid < E) atomicAdd(&g_ecnt[tid], s_ecnt[tid]);
}

// ---------------------------------------------------------------------------
// Kernel 2: serial scan over experts → offsets + tile table
// ---------------------------------------------------------------------------
__global__ void scan_kernel() {
    if (threadIdx.x == 0) {
        int off = 0, nt = 0;
        for (int e = 0; e < E; e++) {
            g_eoff[e] = off;
            g_ecursor[e] = 0;
            int c = g_ecnt[e];
            for (int r = 0; r < c; r += TQ) {
                g_tile_e[nt]  = e;
                g_tile_r0[nt] = off + r;
                nt++;
            }
            off += c;
        }
        g_eoff[E] = off;
        g_ntiles = nt;
    }
}

// ---------------------------------------------------------------------------
// Kernel 3: scatter slot ids into expert buckets
// ---------------------------------------------------------------------------
__global__ void scatter_kernel() {
    int i = blockIdx.x * 256 + threadIdx.x;
    int e = g_topi[i];
    int pos = atomicAdd(&g_ecursor[e], 1);
    g_slots[g_eoff[e] + pos] = i;
}

// ---------------------------------------------------------------------------
// Kernel 4: kv = x @ Wkv + bkv → K as f16 hi/lo pair-major, V as f16 transposed
// ---------------------------------------------------------------------------
__global__ __launch_bounds__(256) void kv_kernel(
    const float* __restrict__ x, const float* __restrict__ Wkv,
    const float* __restrict__ bkv)
{
    __shared__ float As[64][17];
    __shared__ float Bs[16][64];
    int tid = threadIdx.x;
    int tx = tid & 15, ty = tid >> 4;
    int t0 = blockIdx.x * 64;
    int n0 = blockIdx.y * 64;

    float acc[4][4] = {};

    for (int k0 = 0; k0 < D; k0 += 16) {
#pragma unroll
        for (int i = 0; i < 4; i++) {
            int idx = tid + i * 256;
            int r = idx >> 4, kk = idx & 15;
            As[r][kk] = x[(size_t)(t0 + r) * D + k0 + kk];
        }
#pragma unroll
        for (int i = 0; i < 4; i++) {
            int idx = tid + i * 256;
            int kr = idx >> 6, nn = idx & 63;
            Bs[kr][nn] = Wkv[(size_t)(k0 + kr) * (2 * HD) + n0 + nn];
        }
        __syncthreads();
#pragma unroll
        for (int kk = 0; kk < 16; kk++) {
            float a[4];
#pragma unroll
            for (int i = 0; i < 4; i++) a[i] = As[ty * 4 + i][kk];
            float4 bv = *reinterpret_cast<const float4*>(&Bs[kk][tx * 4]);
            float bb[4] = {bv.x, bv.y, bv.z, bv.w};
#pragma unroll
            for (int i = 0; i < 4; i++)
#pragma unroll
                for (int j = 0; j < 4; j++)
                    acc[i][j] += a[i] * bb[j];
        }
        __syncthreads();
    }

    int c0 = n0 + tx * 4;
    float vv[4][4];
#pragma unroll
    for (int i = 0; i < 4; i++)
#pragma unroll
        for (int j = 0; j < 4; j++)
            vv[i][j] = acc[i][j] + bkv[c0 + j];

    if (c0 < HD) {
        // K half: write f16 hi/lo pair-major [hd-pair][token]
        int p0 = c0 >> 1;
#pragma unroll
        for (int i = 0; i < 4; i++) {
            int t = t0 + ty * 4 + i;
            __half2 hh, ll;
            h2split(vv[i][0], vv[i][1], hh, ll);
            g_kh2[(size_t)p0 * BN_TOK + t] = hh;
            g_kl2[(size_t)p0 * BN_TOK + t] = ll;
            h2split(vv[i][2], vv[i][3], hh, ll);
            g_kh2[(size_t)(p0 + 1) * BN_TOK + t] = hh;
            g_kl2[(size_t)(p0 + 1) * BN_TOK + t] = ll;
        }
    } else {
        // V half: write f16 transposed [hd][token-pair]
        int tp0 = (t0 + ty * 4) >> 1;
#pragma unroll
        for (int j = 0; j < 4; j++) {
            int k = c0 + j - HD;
            g_vh2[(size_t)k * (BN_TOK / 2) + tp0]     = __floats2half2_rn(vv[0][j], vv[1][j]);
            g_vh2[(size_t)k * (BN_TOK / 2) + tp0 + 1] = __floats2half2_rn(vv[2][j], vv[3][j]);
        }
    }
}

// ---------------------------------------------------------------------------
// Kernel 5: grouped q GEMM — f16 error-compensated mma (hi + lo*2^10),
// 512 threads: warp = (row-group 0..7, col-half 0..1); M=128, N=128, K=1024.
// ---------------------------------------------------------------------------
constexpr int QG_K  = 64;    // floats per k-chunk (32 pairs)
constexpr int QA_STR = 36;   // Ahi/Alo [row 128][kpair 32 + pad]  (half2)
constexpr int QB_STR = 136;  // Bhi/Blo [kpair 32][n 128 + pad]    (half2)

__global__ __launch_bounds__(512, 1) void qgemm_kernel(
    const float* __restrict__ x, const float* __restrict__ Wq)
{
    extern __shared__ __half2 qsm[];
    __half2* Ahi = qsm;                    // 128*36
    __half2* Alo = Ahi + TQ * QA_STR;      // 128*36
    __half2* Bhi = Alo + TQ * QA_STR;      // 32*136
    __half2* Blo = Bhi + 32 * QB_STR;      // 32*136
    int* s_tok  = reinterpret_cast<int*>(Blo + 32 * QB_STR);   // 128
    int* s_slot = s_tok + TQ;                                   // 128

    int t = blockIdx.x;
    if (t >= g_ntiles) return;
    int e = g_tile_e[t], r0 = g_tile_r0[t];
    int rend = g_eoff[e + 1];
    int tid = threadIdx.x;

    if (tid < TQ) {
        int gr = r0 + tid;
        if (gr >= rend) gr = r0;       // padded rows duplicate row0 (not written back)
        int s = g_slots[gr];
        s_slot[tid] = s;
        s_tok[tid]  = s >> 3;
    }
    __syncthreads();

    int warp = tid >> 5, lane = tid & 31;
    int g = lane >> 2, tg = lane & 3;
    int rg = warp & 7, ch = warp >> 3;     // row-group, col-half
    int r_a = rg * 16 + g, r_b = r_a + 8;
    const float* wq = Wq + (size_t)e * D * HD;

    float scc[8][4] = {};
    float scl[8][4] = {};

    for (int k0 = 0; k0 < D; k0 += QG_K) {
        // A: 128 rows x 64 k (gathered), split to f16 hi/lo
        for (int idx = tid; idx < TQ * (QG_K / 4); idx += 512) {
            int r = idx >> 4, kq = (idx & 15) * 4;
            float4 av = *reinterpret_cast<const float4*>(
                x + (size_t)s_tok[r] * D + k0 + kq);
            __half2 h0, l0, h1, l1;
            h2split(av.x, av.y, h0, l0);
            h2split(av.z, av.w, h1, l1);
            int p0 = kq >> 1;
            Ahi[r * QA_STR + p0]     = h0;
            Ahi[r * QA_STR + p0 + 1] = h1;
            Alo[r * QA_STR + p0]     = l0;
            Alo[r * QA_STR + p0 + 1] = l1;
        }
        // B: pair-major [kpair 32][n 128]: half2(Wq[2p][n], Wq[2p+1][n])
        for (int idx = tid; idx < 32 * 32; idx += 512) {
            int p  = idx >> 5;
            int nq = (idx & 31) * 4;
            const float* w0 = wq + (size_t)(k0 + 2 * p)     * HD + nq;
            const float* w1 = wq + (size_t)(k0 + 2 * p + 1) * HD + nq;
            float4 fa = *reinterpret_cast<const float4*>(w0);
            float4 fb = *reinterpret_cast<const float4*>(w1);
            __half2 hh, ll;
            h2split(fa.x, fb.x, hh, ll);
            Bhi[p * QB_STR + nq + 0] = hh; Blo[p * QB_STR + nq + 0] = ll;
            h2split(fa.y, fb.y, hh, ll);
            Bhi[p * QB_STR + nq + 1] = hh; Blo[p * QB_STR + nq + 1] = ll;
            h2split(fa.z, fb.z, hh, ll);
            Bhi[p * QB_STR + nq + 2] = hh; Blo[p * QB_STR + nq + 2] = ll;
            h2split(fa.w, fb.w, hh, ll);
            Bhi[p * QB_STR + nq + 3] = hh; Blo[p * QB_STR + nq + 3] = ll;
        }
        __syncthreads();

#pragma unroll
        for (int ks = 0; ks < 4; ks++) {
            const __half2* ah0 = Ahi + r_a * QA_STR + 8 * ks + tg;
            const __half2* ah1 = Ahi + r_b * QA_STR + 8 * ks + tg;
            const __half2* al0 = Alo + r_a * QA_STR + 8 * ks + tg;
            const __half2* al1 = Alo + r_b * QA_STR + 8 * ks + tg;
            uint32_t ah[4] = { *reinterpret_cast<const uint32_t*>(ah0),
                               *reinterpret_cast<const uint32_t*>(ah1),
                               *reinterpret_cast<const uint32_t*>(ah0 + 4),
                               *reinterpret_cast<const uint32_t*>(ah1 + 4) };
            uint32_t al[4] = { *reinterpret_cast<const uint32_t*>(al0),
                               *reinterpret_cast<const uint32_t*>(al1),
                               *reinterpret_cast<const uint32_t*>(al0 + 4),
                               *reinterpret_cast<const uint32_t*>(al1 + 4) };
            const __half2* bh0 = Bhi + (8 * ks + tg) * QB_STR + ch * 64 + g;
            const __half2* bh1 = Bhi + (8 * ks + 4 + tg) * QB_STR + ch * 64 + g;
            const __half2* bl0 = Blo + (8 * ks + tg) * QB_STR + ch * 64 + g;
            const __half2* bl1 = Blo + (8 * ks + 4 + tg) * QB_STR + ch * 64 + g;
#pragma unroll
            for (int nc = 0; nc < 8; nc++) {
                uint32_t bh[2] = { *reinterpret_cast<const uint32_t*>(bh0 + 8 * nc),
                                   *reinterpret_cast<const uint32_t*>(bh1 + 8 * nc) };
                uint32_t bl[2] = { *reinterpret_cast<const uint32_t*>(bl0 + 8 * nc),
                                   *reinterpret_cast<const uint32_t*>(bl1 + 8 * nc) };
                mma_f16(scc[nc], ah, bh);
                mma_f16(scl[nc], al, bh);
                mma_f16(scl[nc], ah, bl);
            }
        }
        __syncthreads();
    }

    bool va = (r0 + r_a < rend), vb = (r0 + r_b < rend);
    float* da = g_q + (size_t)s_slot[r_a] * HD + ch * 64;
    float* db = g_q + (size_t)s_slot[r_b] * HD + ch * 64;
#pragma unroll
    for (int nc = 0; nc < 8; nc++) {
        int c = 8 * nc + 2 * tg;
        float o0 = scc[nc][0] + scl[nc][0] * LO_INV;
        float o1 = scc[nc][1] + scl[nc][1] * LO_INV;
        float o2 = scc[nc][2] + scl[nc][2] * LO_INV;
        float o3 = scc[nc][3] + scl[nc][3] * LO_INV;
        if (va) *reinterpret_cast<float2*>(da + c) = make_float2(o0, o1);
        if (vb) *reinterpret_cast<float2*>(db + c) = make_float2(o2, o3);
    }
}

// ---------------------------------------------------------------------------
// Kernel 6: flash attention — K/V pre-converted in global (pure copy loads),
// QK^T f16 error-compensated, softmax log2 + ex2.f16x2, PV f16,
// epilogue writes f16 attn-out directly.
// ---------------------------------------------------------------------------
constexpr int QT = 128;
constexpr int KT = 64;
constexpr int QH_STR  = 68;   // Qhi/Qlo [row 128][hd-pair 64 + pad]   (half2)
constexpr int KH_STR  = 72;   // Khi/Klo [hd-pair 64][kv 64 + pad]     (half2)
constexpr int VT2_STR = 36;   // VhT2 [hd 128][kv-pair 32 + pad]       (half2)
constexpr int PS2_STR = 36;   // Ps2  [row 128][kv-pair 32 + pad]      (half2)

__global__ __launch_bounds__(256, 1) void attn_kernel()
{
    extern __shared__ __half2 smh[];
    __half2* Qhi  = smh;                     // 128*68
    __half2* Qlo  = Qhi  + QT * QH_STR;      // 128*68
    __half2* Khi  = Qlo  + QT * QH_STR;      // 64*72
    __half2* Klo  = Khi  + 64 * KH_STR;      // 64*72
    __half2* VhT2 = Klo  + 64 * KH_STR;      // 128*36
    __half2* Ps2  = VhT2 + HD * VT2_STR;     // 128*36

    int tid  = threadIdx.x;
    int warp = tid >> 5, lane = tid & 31;
    int g = lane >> 2, tg = lane & 3;
    int n0 = blockIdx.x * QT;
    int h  = blockIdx.y;
    int b  = blockIdx.z;
    int bN0 = b * N;
    // scale * log2(e): softmax computed in log2 domain
    const float qsc = 0.08838834764831845f * 1.44269504088896340736f;

    // load Q once: scale, split into f16 hi / lo*2^10
    for (int idx = tid; idx < QT * (HD / 4); idx += 256) {
        int r = idx >> 5, kq = (idx & 31) * 4;
        float4 qv = *reinterpret_cast<const float4*>(
            g_q + (((size_t)(bN0 + n0 + r)) * H + h) * HD + kq);
        qv.x *= qsc; qv.y *= qsc; qv.z *= qsc; qv.w *= qsc;
        __half2 h0, l0, h1, l1;
        h2split(qv.x, qv.y, h0, l0);
        h2split(qv.z, qv.w, h1, l1);
        int p0 = kq >> 1;
        Qhi[r * QH_STR + p0]     = h0;
        Qhi[r * QH_STR + p0 + 1] = h1;
        Qlo[r * QH_STR + p0]     = l0;
        Qlo[r * QH_STR + p0 + 1] = l1;
    }

    const int r_a = warp * 16 + g;
    const int r_b = r_a + 8;

    float o[16][4];
#pragma unroll
    for (int nc = 0; nc < 16; nc++)
#pragma unroll
        for (int j = 0; j < 4; j++) o[nc][j] = 0.f;
    float m_a = -1e30f, m_b = -1e30f, l_a = 0.f, l_b = 0.f;

    for (int m0 = 0; m0 < N; m0 += KT) {
        __syncthreads();   // prev tile consumed (also covers initial Q load)
        // K tile: pure uint4 copies from pre-split global (hi and lo)
        for (int idx = tid; idx < 64 * 16; idx += 256) {
            int p  = idx >> 4;
            int mq = (idx & 15) * 4;
            *reinterpret_cast<uint4*>(Khi + p * KH_STR + mq) =
                *reinterpret_cast<const uint4*>(g_kh2 + (size_t)p * BN_TOK + bN0 + m0 + mq);
            *reinterpret_cast<uint4*>(Klo + p * KH_STR + mq) =
                *reinterpret_cast<const uint4*>(g_kl2 + (size_t)p * BN_TOK + bN0 + m0 + mq);
        }
        // V tile: pure uint4 copy from pre-transposed f16 global
        int tp0 = (bN0 + m0) >> 1;
        for (int idx = tid; idx < HD * 8; idx += 256) {
            int k = idx >> 3, tq = (idx & 7) * 4;
            *reinterpret_cast<uint4*>(VhT2 + k * VT2_STR + tq) =
                *reinterpret_cast<const uint4*>(g_vh2 + (size_t)k * (BN_TOK / 2) + tp0 + tq);
        }
        __syncthreads();

        // ---- S = Q K^T : 16 x 64 per warp, f16 compensated, k16 steps ----
        float scc[8][4] = {};
        float scl[8][4] = {};
#pragma unroll
        for (int ks = 0; ks < 8; ks++) {
            const __half2* qh0 = Qhi + r_a * QH_STR + 8 * ks + tg;
            const __half2* qh1 = Qhi + r_b * QH_STR + 8 * ks + tg;
            const __half2* ql0 = Qlo + r_a * QH_STR + 8 * ks + tg;
            const __half2* ql1 = Qlo + r_b * QH_STR + 8 * ks + tg;
            uint32_t ah[4] = { *reinterpret_cast<const uint32_t*>(qh0),
                               *reinterpret_cast<const uint32_t*>(qh1),
                               *reinterpret_cast<const uint32_t*>(qh0 + 4),
                               *reinterpret_cast<const uint32_t*>(qh1 + 4) };
            uint32_t al[4] = { *reinterpret_cast<const uint32_t*>(ql0),
                               *reinterpret_cast<const uint32_t*>(ql1),
                               *reinterpret_cast<const uint32_t*>(ql0 + 4),
                               *reinterpret_cast<const uint32_t*>(ql1 + 4) };
            const __half2* kh0 = Khi + (8 * ks + tg) * KH_STR + g;
            const __half2* kh1 = Khi + (8 * ks + 4 + tg) * KH_STR + g;
            const __half2* kl0 = Klo + (8 * ks + tg) * KH_STR + g;
            const __half2* kl1 = Klo + (8 * ks + 4 + tg) * KH_STR + g;
#pragma unroll
            for (int nc = 0; nc < 8; nc++) {
                uint32_t bh[2] = { *reinterpret_cast<const uint32_t*>(kh0 + 8 * nc),
                                   *reinterpret_cast<const uint32_t*>(kh1 + 8 * nc) };
                uint32_t bl[2] = { *reinterpret_cast<const uint32_t*>(kl0 + 8 * nc),
                                   *reinterpret_cast<const uint32_t*>(kl1 + 8 * nc) };
                mma_f16(scc[nc], ah, bh);
                mma_f16(scl[nc], al, bh);
                mma_f16(scl[nc], ah, bl);
            }
        }
        // combine: S = hi·hi + 2^-10 * cross
#pragma unroll
        for (int nc = 0; nc < 8; nc++)
#pragma unroll
            for (int j = 0; j < 4; j++)
                scc[nc][j] += scl[nc][j] * LO_INV;

        // ---- online softmax (log2 domain, f16x2 ex2) ----
        float lm_a = -1e30f, lm_b = -1e30f;
#pragma unroll
        for (int nc = 0; nc < 8; nc++) {
            lm_a = fmaxf(lm_a, fmaxf(scc[nc][0], scc[nc][1]));
            lm_b = fmaxf(lm_b, fmaxf(scc[nc][2], scc[nc][3]));
        }
#pragma unroll
        for (int off = 1; off <= 2; off <<= 1) {
            lm_a = fmaxf(lm_a, __shfl_xor_sync(0xffffffffu, lm_a, off));
            lm_b = fmaxf(lm_b, __shfl_xor_sync(0xffffffffu, lm_b, off));
        }
        float mn_a = fmaxf(m_a, lm_a), mn_b = fmaxf(m_b, lm_b);
        float al_a = exp2f(m_a - mn_a), al_b = exp2f(m_b - mn_b);
        m_a = mn_a; m_b = mn_b;

        float rs_a = 0.f, rs_b = 0.f;
#pragma unroll
        for (int nc = 0; nc < 8; nc++) {
            __half2 ha = h2exp2(__floats2half2_rn(scc[nc][0] - mn_a, scc[nc][1] - mn_a));
            __half2 hb = h2exp2(__floats2half2_rn(scc[nc][2] - mn_b, scc[nc][3] - mn_b));
            int cp = 4 * nc + tg;
            Ps2[r_a * PS2_STR + cp] = ha;
            Ps2[r_b * PS2_STR + cp] = hb;
            float2 fa = __half22float2(ha);
            float2 fb = __half22float2(hb);
            rs_a += fa.x + fa.y;
            rs_b += fb.x + fb.y;
        }
#pragma unroll
        for (int off = 1; off <= 2; off <<= 1) {
            rs_a += __shfl_xor_sync(0xffffffffu, rs_a, off);
            rs_b += __shfl_xor_sync(0xffffffffu, rs_b, off);
        }
        l_a = l_a * al_a + rs_a;
        l_b = l_b * al_b + rs_b;
#pragma unroll
        for (int nc = 0; nc < 16; nc++) {
            o[nc][0] *= al_a; o[nc][1] *= al_a;
            o[nc][2] *= al_b; o[nc][3] *= al_b;
        }

        // ---- O += P V : fp16 m16n8k16, per-warp-private Ps2, no sync ----
#pragma unroll
        for (int ks = 0; ks < 4; ks++) {
            const __half2* pa0 = Ps2 + r_a * PS2_STR + 8 * ks + tg;
            const __half2* pa1 = Ps2 + r_b * PS2_STR + 8 * ks + tg;
            uint32_t a[4];
            a[0] = *reinterpret_cast<const uint32_t*>(pa0);
            a[1] = *reinterpret_cast<const uint32_t*>(pa1);
            a[2] = *reinterpret_cast<const uint32_t*>(pa0 + 4);
            a[3] = *reinterpret_cast<const uint32_t*>(pa1 + 4);
#pragma unroll
            for (int nc = 0; nc < 16; nc++) {
                const __half2* vb = VhT2 + (8 * nc + g) * VT2_STR + 8 * ks + tg;
                uint32_t bb[2];
                bb[0] = *reinterpret_cast<const uint32_t*>(vb);
                bb[1] = *reinterpret_cast<const uint32_t*>(vb + 4);
                mma_f16(o[nc], a, bb);
            }
        }
    }

    // epilogue: write attn out directly as f16 [slot][hd-pair]
    float inv_a = 1.f / l_a, inv_b = 1.f / l_b;
    __half2* dsta = g_attno2 + (((size_t)(bN0 + n0 + r_a)) * H + h) * (HD / 2);
    __half2* dstb = g_attno2 + (((size_t)(bN0 + n0 + r_b)) * H + h) * (HD / 2);
#pragma unroll
    for (int nc = 0; nc < 16; nc++) {
        int p = 4 * nc + tg;
        dsta[p] = __floats2half2_rn(o[nc][0] * inv_a, o[nc][1] * inv_a);
        dstb[p] = __floats2half2_rn(o[nc][2] * inv_b, o[nc][3] * inv_b);
    }
}

// ---------------------------------------------------------------------------
// Kernel 7: grouped combine GEMM — single-pass f16, A pre-converted in global.
// K=HD loaded once; single sync; 2 CTAs/SM.
// ---------------------------------------------------------------------------
constexpr int CA_STR = 68;    // A2 [row 128][kpair 64 + pad]  (half2)
constexpr int CB_STR = 136;   // B2 [kpair 64][n 128 + pad]    (half2)

__global__ __launch_bounds__(256, 2) void cgemm_kernel(const float* __restrict__ Wo)
{
    extern __shared__ __half2 csm[];
    __half2* A2 = csm;                  // 128*68
    __half2* B2 = A2 + TQ * CA_STR;     // 64*136
    int*   s_slot = reinterpret_cast<int*>(B2 + 64 * CB_STR);  // 128
    float* s_gate = reinterpret_cast<float*>(s_slot + TQ);     // 128

    int t = blockIdx.x;
    if (t >= g_ntiles) return;
    int n0 = blockIdx.y * 128;
    int e = g_tile_e[t], r0 = g_tile_r0[t];
    int rend = g_eoff[e + 1];
    int tid = threadIdx.x;

    if (tid < TQ) {
        int gr = r0 + tid;
        if (gr >= rend) gr = r0;
        int s = g_slots[gr];
        s_slot[tid] = s;
        s_gate[tid] = g_gates[s];
    }
    __syncthreads();

    // A: pure uint4 copy from f16 attn-out
    for (int idx = tid; idx < TQ * 16; idx += 256) {
        int r = idx >> 4, pq = (idx & 15) * 4;
        *reinterpret_cast<uint4*>(A2 + r * CA_STR + pq) =
            *reinterpret_cast<const uint4*>(g_attno2 + (size_t)s_slot[r] * (HD / 2) + pq);
    }
    // B: Wo pair-major [kpair 64][n 128]: half2(Wo[2p][n], Wo[2p+1][n])
    const float* wo = Wo + (size_t)e * HD * D;
    for (int idx = tid; idx < 64 * 32; idx += 256) {
        int p  = idx >> 5;
        int nq = (idx & 31) * 4;
        const float* w0 = wo + (size_t)(2 * p)     * D + n0 + nq;
        const float* w1 = wo + (size_t)(2 * p + 1) * D + n0 + nq;
        float4 fa = *reinterpret_cast<const float4*>(w0);
        float4 fb = *reinterpret_cast<const float4*>(w1);
        B2[p * CB_STR + nq + 0] = __floats2half2_rn(fa.x, fb.x);
        B2[p * CB_STR + nq + 1] = __floats2half2_rn(fa.y, fb.y);
        B2[p * CB_STR + nq + 2] = __floats2half2_rn(fa.z, fb.z);
        B2[p * CB_STR + nq + 3] = __floats2half2_rn(fa.w, fb.w);
    }
    __syncthreads();

    int warp = tid >> 5, lane = tid & 31;
    int g = lane >> 2, tg = lane & 3;
    int r_a = warp * 16 + g, r_b = r_a + 8;

    float acc[16][4] = {};

#pragma unroll
    for (int ks = 0; ks < 8; ks++) {
        const __half2* a0 = A2 + r_a * CA_STR + 8 * ks + tg;
        const __half2* a1 = A2 + r_b * CA_STR + 8 * ks + tg;
        uint32_t a[4] = { *reinterpret_cast<const uint32_t*>(a0),
                          *reinterpret_cast<const uint32_t*>(a1),
                          *reinterpret_cast<const uint32_t*>(a0 + 4),
                          *reinterpret_cast<const uint32_t*>(a1 + 4) };
        const __half2* b0 = B2 + (8 * ks + tg) * CB_STR + g;
        const __half2* b1 = B2 + (8 * ks + 4 + tg) * CB_STR + g;
#pragma unroll
        for (int nc = 0; nc < 16; nc++) {
            uint32_t bb[2] = { *reinterpret_cast<const uint32_t*>(b0 + 8 * nc),
                               *reinterpret_cast<const uint32_t*>(b1 + 8 * nc) };
            mma_f16(acc[nc], a, bb);
        }
    }

    bool va = (r0 + r_a < rend), vb = (r0 + r_b < rend);
    float ga = s_gate[r_a], gb = s_gate[r_b];
    float* da = g_ws + (size_t)s_slot[r_a] * D + n0;
    float* db = g_ws + (size_t)s_slot[r_b] * D + n0;
#pragma unroll
    for (int nc = 0; nc < 16; nc++) {
        int c = 8 * nc + 2 * tg;
        if (va) *reinterpret_cast<float2*>(da + c) = make_float2(acc[nc][0] * ga, acc[nc][1] * ga);
        if (vb) *reinterpret_cast<float2*>(db + c) = make_float2(acc[nc][2] * gb, acc[nc][3] * gb);
    }
}

// ---------------------------------------------------------------------------
// Kernel 8: reduce 8 slot rows per token → y
// ---------------------------------------------------------------------------
__global__ __launch_bounds__(256) void reduce_kernel(float* __restrict__ y)
{
    int t = blockIdx.x;
    int c = threadIdx.x * 4;
    float4 s = make_float4(0.f, 0.f, 0.f, 0.f);
#pragma unroll
    for (int h = 0; h < H; h++) {
        float4 v = *reinterpret_cast<const float4*>(g_ws + ((size_t)(t * H + h)) * D + c);
        s.x += v.x; s.y += v.y; s.z += v.z; s.w += v.w;
    }
    *reinterpret_cast<float4*>(y + (size_t)t * D + c) = s;
}

// ---------------------------------------------------------------------------
// Kernel 9: finalize aux loss
// ---------------------------------------------------------------------------
__global__ void aux_final_kernel(float* __restrict__ out) {
    if (threadIdx.x == 0) {
        const float inv_bn = 1.0f / (float)BN_TOK;
        float sw = 0.f;
        for (int e = 0; e < E; e++)
            sw += (g_aux[e] * inv_bn) * (g_aux[E + e] * inv_bn);
        float aux = 0.1f * (float)E * sw + 0.001f * (g_aux[2 * E] * inv_bn);
        out[(size_t)BN_TOK * D] = aux;
    }
}

// ---------------------------------------------------------------------------
// Launch
// ---------------------------------------------------------------------------
extern "C" void kernel_launch(void* const* d_in, const int* in_sizes, int n_in,
                              void* d_out, int out_size)
{
    const float* x    = (const float*)d_in[0];
    const int* task_bh = (const int*)d_in[1];
    const float* Wg   = (const float*)d_in[2];
    const float* Wq   = (const float*)d_in[3];
    const float* Wo   = (const float*)d_in[4];
    const float* Wkv  = (const float*)d_in[5];
    const float* bkv  = (const float*)d_in[6];
    float* out = (float*)d_out;

    const int attn_smem = (2 * QT * QH_STR + 2 * 64 * KH_STR +
                           HD * VT2_STR + QT * PS2_STR) * 4;
    const int qg_smem = (2 * TQ * QA_STR + 2 * 32 * QB_STR) * 4 + 2 * TQ * 4;
    const int cg_smem = (TQ * CA_STR + 64 * CB_STR) * 4 + 2 * TQ * 4;
    cudaFuncSetAttribute(attn_kernel,  cudaFuncAttributeMaxDynamicSharedMemorySize, attn_smem);
    cudaFuncSetAttribute(qgemm_kernel, cudaFuncAttributeMaxDynamicSharedMemorySize, qg_smem);
    cudaFuncSetAttribute(cgemm_kernel, cudaFuncAttributeMaxDynamicSharedMemorySize, cg_smem);

    init_aux_kernel<<<1, 64>>>();
    gating_kernel<<<BN_TOK / 8, 256>>>(x, task_bh, Wg);
    scan_kernel<<<1, 32>>>();
    scatter_kernel<<<NSLOT / 256, 256>>>();
    kv_kernel<<<dim3(BN_TOK / 64, (2 * HD) / 64), 256>>>(x, Wkv, bkv);
    qgemm_kernel<<<NT_MAX, 512, qg_smem>>>(x, Wq);
    attn_kernel<<<dim3(N / QT, H, B), 256, attn_smem>>>();
    cgemm_kernel<<<dim3(NT_MAX, 8), 256, cg_smem>>>(Wo);
    reduce_kernel<<<BN_TOK, 256>>>(out);
    aux_final_kernel<<<1, 32>>>(out);
}

// round 12
// speedup vs baseline: 1.8989x; 1.2210x over previous
#include <cuda_runtime.h>
#include <cuda_fp16.h>
#include <math.h>
#include <stdint.h>

// ---------------------------------------------------------------------------
// Problem constants
// ---------------------------------------------------------------------------
constexpr int B    = 4;
constexpr int N    = 2048;
constexpr int D    = 1024;
constexpr int E    = 24;
constexpr int H    = 8;
constexpr int HD   = 128;
constexpr int BN_TOK = B * N;          // 8192 tokens
constexpr int NSLOT  = BN_TOK * H;     // 65536 (token,slot) pairs

// Grouped-GEMM tiling
constexpr int TQ = 128;                // rows per expert tile
constexpr int NT_MAX = NSLOT / TQ + E; // 536 max tiles

// ---------------------------------------------------------------------------
// Scratch (device globals — no allocations allowed)
// ---------------------------------------------------------------------------
__device__ __half2 g_kh2[(HD / 2) * BN_TOK];   // 2 MB  K hi,  pair-major [hd-pair][token]
__device__ __half2 g_kl2[(HD / 2) * BN_TOK];   // 2 MB  K lo*2^10
__device__ __half2 g_vh2[HD * (BN_TOK / 2)];   // 2 MB  V f16 transposed [hd][token-pair]
__device__ float   g_q[NSLOT * HD];            // 32 MB [slot][hd]
__device__ __half2 g_attno2[NSLOT * (HD / 2)]; // 16 MB attn out f16 [slot][hd-pair]
__device__ float   g_ws[(size_t)NSLOT * D];    // 268 MB combine scratch [slot][D]
// pre-split inputs (convert-once)
__device__ __half2 g_xh2[BN_TOK * (D / 2)];    // 16 MB x hi [token][pair]
__device__ __half2 g_xl2[BN_TOK * (D / 2)];    // 16 MB x lo*2^10
__device__ __half2 g_wqh2[(size_t)E * (D / 2) * HD];  // 6.3 MB Wq hi [e][kpair][n]
__device__ __half2 g_wql2[(size_t)E * (D / 2) * HD];  // 6.3 MB Wq lo*2^10
__device__ __half2 g_woh2[(size_t)E * (HD / 2) * D];  // 6.3 MB Wo f16 [e][kpair][n]
__device__ int   g_topi[NSLOT];
__device__ float g_gates[NSLOT];
__device__ float g_aux[2 * E + 1];
// expert bucketing
__device__ int g_ecnt[E];
__device__ int g_eoff[E + 1];
__device__ int g_ecursor[E];
__device__ int g_slots[NSLOT];
__device__ int g_tile_e[NT_MAX];
__device__ int g_tile_r0[NT_MAX];
__device__ int g_ntiles;

// ---------------------------------------------------------------------------
// helpers
// ---------------------------------------------------------------------------
__device__ __forceinline__ void mma_f16(float* d, const uint32_t* a, const uint32_t* b) {
    asm volatile(
        "mma.sync.aligned.m16n8k16.row.col.f32.f16.f16.f32 "
        "{%0,%1,%2,%3}, {%4,%5,%6,%7}, {%8,%9}, {%0,%1,%2,%3};\n"
        : "+f"(d[0]), "+f"(d[1]), "+f"(d[2]), "+f"(d[3])
        : "r"(a[0]), "r"(a[1]), "r"(a[2]), "r"(a[3]), "r"(b[0]), "r"(b[1]));
}
__device__ __forceinline__ void h2split(float x, float y, __half2& hi, __half2& lo) {
    hi = __floats2half2_rn(x, y);
    float2 hf = __half22float2(hi);
    lo = __floats2half2_rn((x - hf.x) * 1024.f, (y - hf.y) * 1024.f);
}
constexpr float LO_INV = 1.f / 1024.f;

__device__ __forceinline__ void cp16(void* smem, const void* gmem) {
    uint32_t s = (uint32_t)__cvta_generic_to_shared(smem);
    asm volatile("cp.async.cg.shared.global [%0], [%1], 16;\n" :: "r"(s), "l"(gmem));
}
__device__ __forceinline__ void cp_commit() {
    asm volatile("cp.async.commit_group;\n");
}
__device__ __forceinline__ void cp_wait0() {
    asm volatile("cp.async.wait_group 0;\n" ::: "memory");
}

// ---------------------------------------------------------------------------
// Kernel 0: zero aux + expert histogram
// ---------------------------------------------------------------------------
__global__ void init_aux_kernel() {
    int tid = threadIdx.x;
    if (tid < 2 * E + 1) g_aux[tid] = 0.f;
    if (tid < E) g_ecnt[tid] = 0;
}

// ---------------------------------------------------------------------------
// Pre-split kernels (convert-once)
// ---------------------------------------------------------------------------
__global__ __launch_bounds__(256) void xsplit_kernel(const float* __restrict__ x) {
    int t = blockIdx.x;
    int c = threadIdx.x * 4;
    float4 v = *reinterpret_cast<const float4*>(x + (size_t)t * D + c);
    __half2 h0, l0, h1, l1;
    h2split(v.x, v.y, h0, l0);
    h2split(v.z, v.w, h1, l1);
    int p = c >> 1;
    g_xh2[(size_t)t * (D / 2) + p]     = h0;
    g_xh2[(size_t)t * (D / 2) + p + 1] = h1;
    g_xl2[(size_t)t * (D / 2) + p]     = l0;
    g_xl2[(size_t)t * (D / 2) + p + 1] = l1;
}

__global__ __launch_bounds__(128) void wqsplit_kernel(const float* __restrict__ Wq) {
    int p = blockIdx.x;      // kpair 0..511
    int e = blockIdx.y;
    int n = threadIdx.x;     // 0..127
    const float* w = Wq + (size_t)e * D * HD;
    float a = w[(size_t)(2 * p) * HD + n];
    float b2 = w[(size_t)(2 * p + 1) * HD + n];
    __half2 hh, ll;
    h2split(a, b2, hh, ll);
    size_t o = ((size_t)e * (D / 2) + p) * HD + n;
    g_wqh2[o] = hh;
    g_wql2[o] = ll;
}

__global__ __launch_bounds__(256) void wosplit_kernel(const float* __restrict__ Wo) {
    int p = blockIdx.x;      // kpair 0..63
    int e = blockIdx.y;
    const float* w = Wo + (size_t)e * HD * D;
    for (int n = threadIdx.x; n < D; n += 256) {
        g_woh2[((size_t)e * (HD / 2) + p) * D + n] =
            __floats2half2_rn(w[(size_t)(2 * p) * D + n], w[(size_t)(2 * p + 1) * D + n]);
    }
}

// ---------------------------------------------------------------------------
// Kernel 1: gating
// ---------------------------------------------------------------------------
__global__ __launch_bounds__(256) void gating_kernel(
    const float* __restrict__ x, const int* __restrict__ task_bh,
    const float* __restrict__ Wg)
{
    __shared__ float s_aux[2 * E + 1];
    __shared__ int   s_ecnt[E];
    int tid = threadIdx.x;
    if (tid < 2 * E + 1) s_aux[tid] = 0.f;
    if (tid < E) s_ecnt[tid] = 0;
    __syncthreads();

    int warp = tid >> 5, lane = tid & 31;
    int t = blockIdx.x * 8 + warp;
    int b = t >> 11;
    int task = task_bh[b];
    const float* xrow = x + (size_t)t * D;
    const float* wg   = Wg + (size_t)task * D * E;

    float acc[E];
#pragma unroll
    for (int e = 0; e < E; e++) acc[e] = 0.f;

    for (int i = lane; i < D; i += 32) {
        float xv = xrow[i];
        const float4* w4 = reinterpret_cast<const float4*>(wg + (size_t)i * E);
#pragma unroll
        for (int j = 0; j < 6; j++) {
            float4 v = w4[j];
            acc[4*j+0] += xv * v.x; acc[4*j+1] += xv * v.y;
            acc[4*j+2] += xv * v.z; acc[4*j+3] += xv * v.w;
        }
    }
#pragma unroll
    for (int e = 0; e < E; e++) {
#pragma unroll
        for (int off = 16; off >= 1; off >>= 1)
            acc[e] += __shfl_xor_sync(0xffffffffu, acc[e], off);
    }
    float mx = acc[0];
#pragma unroll
    for (int e = 1; e < E; e++) mx = fmaxf(mx, acc[e]);
    float p[E]; float s = 0.f;
#pragma unroll
    for (int e = 0; e < E; e++) { p[e] = __expf(acc[e] - mx); s += p[e]; }
    float inv_s = 1.f / s;
    float lse = mx + __logf(s);

    if (lane < E) atomicAdd(&s_aux[E + lane], p[lane] * inv_s);
    if (lane == 0) {
        atomicAdd(&s_aux[2 * E], lse * lse);
        float tv[H]; int ti[H]; float gsum = 0.f;
#pragma unroll
        for (int h = 0; h < H; h++) {
            float best = -1.f; int bi = 0;
#pragma unroll
            for (int e = 0; e < E; e++)
                if (p[e] > best) { best = p[e]; bi = e; }
            tv[h] = best * inv_s; ti[h] = bi; p[bi] = -2.f;
            gsum += tv[h];
            atomicAdd(&s_aux[bi], 1.0f);
            atomicAdd(&s_ecnt[bi], 1);
        }
        float ig = 1.f / gsum;
#pragma unroll
        for (int h = 0; h < H; h++) {
            g_topi[t * H + h]  = ti[h];
            g_gates[t * H + h] = tv[h] * ig;
        }
    }
    __syncthreads();
    if (tid < 2 * E + 1) atomicAdd(&g_aux[tid], s_aux[tid]);
    if (tid < E) atomicAdd(&g_ecnt[tid], s_ecnt[tid]);
}

// ---------------------------------------------------------------------------
// Kernel 2: serial scan over experts → offsets + tile table
// ---------------------------------------------------------------------------
__global__ void scan_kernel() {
    if (threadIdx.x == 0) {
        int off = 0, nt = 0;
        for (int e = 0; e < E; e++) {
            g_eoff[e] = off;
            g_ecursor[e] = 0;
            int c = g_ecnt[e];
            for (int r = 0; r < c; r += TQ) {
                g_tile_e[nt]  = e;
                g_tile_r0[nt] = off + r;
                nt++;
            }
            off += c;
        }
        g_eoff[E] = off;
        g_ntiles = nt;
    }
}

// ---------------------------------------------------------------------------
// Kernel 3: scatter slot ids into expert buckets
// ---------------------------------------------------------------------------
__global__ void scatter_kernel() {
    int i = blockIdx.x * 256 + threadIdx.x;
    int e = g_topi[i];
    int pos = atomicAdd(&g_ecursor[e], 1);
    g_slots[g_eoff[e] + pos] = i;
}

// ---------------------------------------------------------------------------
// Kernel 4: kv = x @ Wkv + bkv → K as f16 hi/lo pair-major, V as f16 transposed
// ---------------------------------------------------------------------------
__global__ __launch_bounds__(256) void kv_kernel(
    const float* __restrict__ x, const float* __restrict__ Wkv,
    const float* __restrict__ bkv)
{
    __shared__ float As[64][17];
    __shared__ float Bs[16][64];
    int tid = threadIdx.x;
    int tx = tid & 15, ty = tid >> 4;
    int t0 = blockIdx.x * 64;
    int n0 = blockIdx.y * 64;

    float acc[4][4] = {};

    for (int k0 = 0; k0 < D; k0 += 16) {
#pragma unroll
        for (int i = 0; i < 4; i++) {
            int idx = tid + i * 256;
            int r = idx >> 4, kk = idx & 15;
            As[r][kk] = x[(size_t)(t0 + r) * D + k0 + kk];
        }
#pragma unroll
        for (int i = 0; i < 4; i++) {
            int idx = tid + i * 256;
            int kr = idx >> 6, nn = idx & 63;
            Bs[kr][nn] = Wkv[(size_t)(k0 + kr) * (2 * HD) + n0 + nn];
        }
        __syncthreads();
#pragma unroll
        for (int kk = 0; kk < 16; kk++) {
            float a[4];
#pragma unroll
            for (int i = 0; i < 4; i++) a[i] = As[ty * 4 + i][kk];
            float4 bv = *reinterpret_cast<const float4*>(&Bs[kk][tx * 4]);
            float bb[4] = {bv.x, bv.y, bv.z, bv.w};
#pragma unroll
            for (int i = 0; i < 4; i++)
#pragma unroll
                for (int j = 0; j < 4; j++)
                    acc[i][j] += a[i] * bb[j];
        }
        __syncthreads();
    }

    int c0 = n0 + tx * 4;
    float vv[4][4];
#pragma unroll
    for (int i = 0; i < 4; i++)
#pragma unroll
        for (int j = 0; j < 4; j++)
            vv[i][j] = acc[i][j] + bkv[c0 + j];

    if (c0 < HD) {
        int p0 = c0 >> 1;
#pragma unroll
        for (int i = 0; i < 4; i++) {
            int t = t0 + ty * 4 + i;
            __half2 hh, ll;
            h2split(vv[i][0], vv[i][1], hh, ll);
            g_kh2[(size_t)p0 * BN_TOK + t] = hh;
            g_kl2[(size_t)p0 * BN_TOK + t] = ll;
            h2split(vv[i][2], vv[i][3], hh, ll);
            g_kh2[(size_t)(p0 + 1) * BN_TOK + t] = hh;
            g_kl2[(size_t)(p0 + 1) * BN_TOK + t] = ll;
        }
    } else {
        int tp0 = (t0 + ty * 4) >> 1;
#pragma unroll
        for (int j = 0; j < 4; j++) {
            int k = c0 + j - HD;
            g_vh2[(size_t)k * (BN_TOK / 2) + tp0]     = __floats2half2_rn(vv[0][j], vv[1][j]);
            g_vh2[(size_t)k * (BN_TOK / 2) + tp0 + 1] = __floats2half2_rn(vv[2][j], vv[3][j]);
        }
    }
}

// ---------------------------------------------------------------------------
// Kernel 5: grouped q GEMM — f16 error-compensated mma; A and B pre-split in
// global → pure uint4 copy loads. 512 threads, M=128, N=128, K=1024.
// ---------------------------------------------------------------------------
constexpr int QG_K  = 64;    // floats per k-chunk (32 pairs)
constexpr int QA_STR = 36;   // Ahi/Alo [row 128][kpair 32 + pad]  (half2)
constexpr int QB_STR = 136;  // Bhi/Blo [kpair 32][n 128 + pad]    (half2)

__global__ __launch_bounds__(512, 1) void qgemm_kernel()
{
    extern __shared__ __half2 qsm[];
    __half2* Ahi = qsm;                    // 128*36
    __half2* Alo = Ahi + TQ * QA_STR;      // 128*36
    __half2* Bhi = Alo + TQ * QA_STR;      // 32*136
    __half2* Blo = Bhi + 32 * QB_STR;      // 32*136
    int* s_tok  = reinterpret_cast<int*>(Blo + 32 * QB_STR);   // 128
    int* s_slot = s_tok + TQ;                                   // 128

    int t = blockIdx.x;
    if (t >= g_ntiles) return;
    int e = g_tile_e[t], r0 = g_tile_r0[t];
    int rend = g_eoff[e + 1];
    int tid = threadIdx.x;

    if (tid < TQ) {
        int gr = r0 + tid;
        if (gr >= rend) gr = r0;
        int s = g_slots[gr];
        s_slot[tid] = s;
        s_tok[tid]  = s >> 3;
    }
    __syncthreads();

    int warp = tid >> 5, lane = tid & 31;
    int g = lane >> 2, tg = lane & 3;
    int rg = warp & 7, ch = warp >> 3;
    int r_a = rg * 16 + g, r_b = r_a + 8;
    const size_t wq_base = (size_t)e * (D / 2) * HD;

    float scc[8][4] = {};
    float scl[8][4] = {};

    for (int k0 = 0; k0 < D; k0 += QG_K) {
        int kp0 = k0 >> 1;
        // A: pure uint4 copies from pre-split x
        for (int idx = tid; idx < TQ * 8; idx += 512) {
            int r = idx >> 3, pq = (idx & 7) * 4;
            size_t src = (size_t)s_tok[r] * (D / 2) + kp0 + pq;
            *reinterpret_cast<uint4*>(Ahi + r * QA_STR + pq) =
                *reinterpret_cast<const uint4*>(g_xh2 + src);
            *reinterpret_cast<uint4*>(Alo + r * QA_STR + pq) =
                *reinterpret_cast<const uint4*>(g_xl2 + src);
        }
        // B: pure uint4 copies from pre-split Wq
        for (int idx = tid; idx < 32 * 32; idx += 512) {
            int p = idx >> 5, nq = (idx & 31) * 4;
            size_t src = wq_base + (size_t)(kp0 + p) * HD + nq;
            *reinterpret_cast<uint4*>(Bhi + p * QB_STR + nq) =
                *reinterpret_cast<const uint4*>(g_wqh2 + src);
            *reinterpret_cast<uint4*>(Blo + p * QB_STR + nq) =
                *reinterpret_cast<const uint4*>(g_wql2 + src);
        }
        __syncthreads();

#pragma unroll
        for (int ks = 0; ks < 4; ks++) {
            const __half2* ah0 = Ahi + r_a * QA_STR + 8 * ks + tg;
            const __half2* ah1 = Ahi + r_b * QA_STR + 8 * ks + tg;
            const __half2* al0 = Alo + r_a * QA_STR + 8 * ks + tg;
            const __half2* al1 = Alo + r_b * QA_STR + 8 * ks + tg;
            uint32_t ah[4] = { *reinterpret_cast<const uint32_t*>(ah0),
                               *reinterpret_cast<const uint32_t*>(ah1),
                               *reinterpret_cast<const uint32_t*>(ah0 + 4),
                               *reinterpret_cast<const uint32_t*>(ah1 + 4) };
            uint32_t al[4] = { *reinterpret_cast<const uint32_t*>(al0),
                               *reinterpret_cast<const uint32_t*>(al1),
                               *reinterpret_cast<const uint32_t*>(al0 + 4),
                               *reinterpret_cast<const uint32_t*>(al1 + 4) };
            const __half2* bh0 = Bhi + (8 * ks + tg) * QB_STR + ch * 64 + g;
            const __half2* bh1 = Bhi + (8 * ks + 4 + tg) * QB_STR + ch * 64 + g;
            const __half2* bl0 = Blo + (8 * ks + tg) * QB_STR + ch * 64 + g;
            const __half2* bl1 = Blo + (8 * ks + 4 + tg) * QB_STR + ch * 64 + g;
#pragma unroll
            for (int nc = 0; nc < 8; nc++) {
                uint32_t bh[2] = { *reinterpret_cast<const uint32_t*>(bh0 + 8 * nc),
                                   *reinterpret_cast<const uint32_t*>(bh1 + 8 * nc) };
                uint32_t bl[2] = { *reinterpret_cast<const uint32_t*>(bl0 + 8 * nc),
                                   *reinterpret_cast<const uint32_t*>(bl1 + 8 * nc) };
                mma_f16(scc[nc], ah, bh);
                mma_f16(scl[nc], al, bh);
                mma_f16(scl[nc], ah, bl);
            }
        }
        __syncthreads();
    }

    bool va = (r0 + r_a < rend), vb = (r0 + r_b < rend);
    float* da = g_q + (size_t)s_slot[r_a] * HD + ch * 64;
    float* db = g_q + (size_t)s_slot[r_b] * HD + ch * 64;
#pragma unroll
    for (int nc = 0; nc < 8; nc++) {
        int c = 8 * nc + 2 * tg;
        float o0 = scc[nc][0] + scl[nc][0] * LO_INV;
        float o1 = scc[nc][1] + scl[nc][1] * LO_INV;
        float o2 = scc[nc][2] + scl[nc][2] * LO_INV;
        float o3 = scc[nc][3] + scl[nc][3] * LO_INV;
        if (va) *reinterpret_cast<float2*>(da + c) = make_float2(o0, o1);
        if (vb) *reinterpret_cast<float2*>(db + c) = make_float2(o2, o3);
    }
}

// ---------------------------------------------------------------------------
// Kernel 6: flash attention — cp.async double-buffered K/V, f16-compensated QK,
// log2-domain softmax (ex2.f16x2), f16 PV, f16 attn-out.
// ---------------------------------------------------------------------------
constexpr int QT = 128;
constexpr int KT = 64;
constexpr int QH_STR  = 68;
constexpr int KH_STR  = 72;
constexpr int VT2_STR = 36;
constexpr int PS2_STR = 36;
constexpr int KBUF = 64 * KH_STR;
constexpr int VBUF = HD * VT2_STR;

__global__ __launch_bounds__(256, 1) void attn_kernel()
{
    extern __shared__ __half2 smh[];
    __half2* Qhi  = smh;                      // 128*68
    __half2* Qlo  = Qhi  + QT * QH_STR;       // 128*68
    __half2* Khi  = Qlo  + QT * QH_STR;       // 2 * 64*72
    __half2* Klo  = Khi  + 2 * KBUF;          // 2 * 64*72
    __half2* VhT2 = Klo  + 2 * KBUF;          // 2 * 128*36
    __half2* Ps2  = VhT2 + 2 * VBUF;          // 128*36

    int tid  = threadIdx.x;
    int warp = tid >> 5, lane = tid & 31;
    int g = lane >> 2, tg = lane & 3;
    int n0 = blockIdx.x * QT;
    int h  = blockIdx.y;
    int b  = blockIdx.z;
    int bN0 = b * N;
    const float qsc = 0.08838834764831845f * 1.44269504088896340736f;

    // load Q once: scale, split into f16 hi / lo*2^10
    for (int idx = tid; idx < QT * (HD / 4); idx += 256) {
        int r = idx >> 5, kq = (idx & 31) * 4;
        float4 qv = *reinterpret_cast<const float4*>(
            g_q + (((size_t)(bN0 + n0 + r)) * H + h) * HD + kq);
        qv.x *= qsc; qv.y *= qsc; qv.z *= qsc; qv.w *= qsc;
        __half2 h0, l0, h1, l1;
        h2split(qv.x, qv.y, h0, l0);
        h2split(qv.z, qv.w, h1, l1);
        int p0 = kq >> 1;
        Qhi[r * QH_STR + p0]     = h0;
        Qhi[r * QH_STR + p0 + 1] = h1;
        Qlo[r * QH_STR + p0]     = l0;
        Qlo[r * QH_STR + p0 + 1] = l1;
    }

    // prefetch tile 0 into buffer 0
    {
        for (int idx = tid; idx < 64 * 16; idx += 256) {
            int p = idx >> 4, mq = (idx & 15) * 4;
            cp16(Khi + p * KH_STR + mq, g_kh2 + (size_t)p * BN_TOK + bN0 + mq);
            cp16(Klo + p * KH_STR + mq, g_kl2 + (size_t)p * BN_TOK + bN0 + mq);
        }
        int tp0 = bN0 >> 1;
        for (int idx = tid; idx < HD * 8; idx += 256) {
            int k = idx >> 3, tq = (idx & 7) * 4;
            cp16(VhT2 + k * VT2_STR + tq, g_vh2 + (size_t)k * (BN_TOK / 2) + tp0 + tq);
        }
        cp_commit();
    }

    const int r_a = warp * 16 + g;
    const int r_b = r_a + 8;

    float o[16][4];
#pragma unroll
    for (int nc = 0; nc < 16; nc++)
#pragma unroll
        for (int j = 0; j < 4; j++) o[nc][j] = 0.f;
    float m_a = -1e30f, m_b = -1e30f, l_a = 0.f, l_b = 0.f;

    for (int it = 0; it < N / KT; it++) {
        int buf = it & 1;
        cp_wait0();
        __syncthreads();   // tile `it` ready in buf; prev compute on buf^1 done

        if (it + 1 < N / KT) {
            int m0n = (it + 1) * KT;
            int bn = buf ^ 1;
            __half2* KhiN = Khi + bn * KBUF;
            __half2* KloN = Klo + bn * KBUF;
            __half2* VN   = VhT2 + bn * VBUF;
            for (int idx = tid; idx < 64 * 16; idx += 256) {
                int p = idx >> 4, mq = (idx & 15) * 4;
                cp16(KhiN + p * KH_STR + mq, g_kh2 + (size_t)p * BN_TOK + bN0 + m0n + mq);
                cp16(KloN + p * KH_STR + mq, g_kl2 + (size_t)p * BN_TOK + bN0 + m0n + mq);
            }
            int tp0 = (bN0 + m0n) >> 1;
            for (int idx = tid; idx < HD * 8; idx += 256) {
                int k = idx >> 3, tq = (idx & 7) * 4;
                cp16(VN + k * VT2_STR + tq, g_vh2 + (size_t)k * (BN_TOK / 2) + tp0 + tq);
            }
            cp_commit();
        }

        __half2* KhiB = Khi + buf * KBUF;
        __half2* KloB = Klo + buf * KBUF;
        __half2* VB   = VhT2 + buf * VBUF;

        // ---- S = Q K^T : f16 compensated, k16 steps ----
        float scc[8][4] = {};
        float scl[8][4] = {};
#pragma unroll
        for (int ks = 0; ks < 8; ks++) {
            const __half2* qh0 = Qhi + r_a * QH_STR + 8 * ks + tg;
            const __half2* qh1 = Qhi + r_b * QH_STR + 8 * ks + tg;
            const __half2* ql0 = Qlo + r_a * QH_STR + 8 * ks + tg;
            const __half2* ql1 = Qlo + r_b * QH_STR + 8 * ks + tg;
            uint32_t ah[4] = { *reinterpret_cast<const uint32_t*>(qh0),
                               *reinterpret_cast<const uint32_t*>(qh1),
                               *reinterpret_cast<const uint32_t*>(qh0 + 4),
                               *reinterpret_cast<const uint32_t*>(qh1 + 4) };
            uint32_t al[4] = { *reinterpret_cast<const uint32_t*>(ql0),
                               *reinterpret_cast<const uint32_t*>(ql1),
                               *reinterpret_cast<const uint32_t*>(ql0 + 4),
                               *reinterpret_cast<const uint32_t*>(ql1 + 4) };
            const __half2* kh0 = KhiB + (8 * ks + tg) * KH_STR + g;
            const __half2* kh1 = KhiB + (8 * ks + 4 + tg) * KH_STR + g;
            const __half2* kl0 = KloB + (8 * ks + tg) * KH_STR + g;
            const __half2* kl1 = KloB + (8 * ks + 4 + tg) * KH_STR + g;
#pragma unroll
            for (int nc = 0; nc < 8; nc++) {
                uint32_t bh[2] = { *reinterpret_cast<const uint32_t*>(kh0 + 8 * nc),
                                   *reinterpret_cast<const uint32_t*>(kh1 + 8 * nc) };
                uint32_t bl[2] = { *reinterpret_cast<const uint32_t*>(kl0 + 8 * nc),
                                   *reinterpret_cast<const uint32_t*>(kl1 + 8 * nc) };
                mma_f16(scc[nc], ah, bh);
                mma_f16(scl[nc], al, bh);
                mma_f16(scl[nc], ah, bl);
            }
        }
#pragma unroll
        for (int nc = 0; nc < 8; nc++)
#pragma unroll
            for (int j = 0; j < 4; j++)
                scc[nc][j] += scl[nc][j] * LO_INV;

        // ---- online softmax (log2 domain, f16x2 ex2) ----
        float lm_a = -1e30f, lm_b = -1e30f;
#pragma unroll
        for (int nc = 0; nc < 8; nc++) {
            lm_a = fmaxf(lm_a, fmaxf(scc[nc][0], scc[nc][1]));
            lm_b = fmaxf(lm_b, fmaxf(scc[nc][2], scc[nc][3]));
        }
#pragma unroll
        for (int off = 1; off <= 2; off <<= 1) {
            lm_a = fmaxf(lm_a, __shfl_xor_sync(0xffffffffu, lm_a, off));
            lm_b = fmaxf(lm_b, __shfl_xor_sync(0xffffffffu, lm_b, off));
        }
        float mn_a = fmaxf(m_a, lm_a), mn_b = fmaxf(m_b, lm_b);
        float al_a = exp2f(m_a - mn_a), al_b = exp2f(m_b - mn_b);
        m_a = mn_a; m_b = mn_b;

        float rs_a = 0.f, rs_b = 0.f;
#pragma unroll
        for (int nc = 0; nc < 8; nc++) {
            __half2 ha = h2exp2(__floats2half2_rn(scc[nc][0] - mn_a, scc[nc][1] - mn_a));
            __half2 hb = h2exp2(__floats2half2_rn(scc[nc][2] - mn_b, scc[nc][3] - mn_b));
            int cp = 4 * nc + tg;
            Ps2[r_a * PS2_STR + cp] = ha;
            Ps2[r_b * PS2_STR + cp] = hb;
            float2 fa = __half22float2(ha);
            float2 fb = __half22float2(hb);
            rs_a += fa.x + fa.y;
            rs_b += fb.x + fb.y;
        }
#pragma unroll
        for (int off = 1; off <= 2; off <<= 1) {
            rs_a += __shfl_xor_sync(0xffffffffu, rs_a, off);
            rs_b += __shfl_xor_sync(0xffffffffu, rs_b, off);
        }
        l_a = l_a * al_a + rs_a;
        l_b = l_b * al_b + rs_b;
#pragma unroll
        for (int nc = 0; nc < 16; nc++) {
            o[nc][0] *= al_a; o[nc][1] *= al_a;
            o[nc][2] *= al_b; o[nc][3] *= al_b;
        }

        // ---- O += P V ----
#pragma unroll
        for (int ks = 0; ks < 4; ks++) {
            const __half2* pa0 = Ps2 + r_a * PS2_STR + 8 * ks + tg;
            const __half2* pa1 = Ps2 + r_b * PS2_STR + 8 * ks + tg;
            uint32_t a[4];
            a[0] = *reinterpret_cast<const uint32_t*>(pa0);
            a[1] = *reinterpret_cast<const uint32_t*>(pa1);
            a[2] = *reinterpret_cast<const uint32_t*>(pa0 + 4);
            a[3] = *reinterpret_cast<const uint32_t*>(pa1 + 4);
#pragma unroll
            for (int nc = 0; nc < 16; nc++) {
                const __half2* vb = VB + (8 * nc + g) * VT2_STR + 8 * ks + tg;
                uint32_t bb[2];
                bb[0] = *reinterpret_cast<const uint32_t*>(vb);
                bb[1] = *reinterpret_cast<const uint32_t*>(vb + 4);
                mma_f16(o[nc], a, bb);
            }
        }
    }

    float inv_a = 1.f / l_a, inv_b = 1.f / l_b;
    __half2* dsta = g_attno2 + (((size_t)(bN0 + n0 + r_a)) * H + h) * (HD / 2);
    __half2* dstb = g_attno2 + (((size_t)(bN0 + n0 + r_b)) * H + h) * (HD / 2);
#pragma unroll
    for (int nc = 0; nc < 16; nc++) {
        int p = 4 * nc + tg;
        dsta[p] = __floats2half2_rn(o[nc][0] * inv_a, o[nc][1] * inv_a);
        dstb[p] = __floats2half2_rn(o[nc][2] * inv_b, o[nc][3] * inv_b);
    }
}

// ---------------------------------------------------------------------------
// Kernel 7: grouped combine GEMM — single-pass f16, A and B pre-converted.
// ---------------------------------------------------------------------------
constexpr int CA_STR = 68;
constexpr int CB_STR = 136;

__global__ __launch_bounds__(256, 2) void cgemm_kernel()
{
    extern __shared__ __half2 csm[];
    __half2* A2 = csm;                  // 128*68
    __half2* B2 = A2 + TQ * CA_STR;     // 64*136
    int*   s_slot = reinterpret_cast<int*>(B2 + 64 * CB_STR);
    float* s_gate = reinterpret_cast<float*>(s_slot + TQ);

    int t = blockIdx.x;
    if (t >= g_ntiles) return;
    int n0 = blockIdx.y * 128;
    int e = g_tile_e[t], r0 = g_tile_r0[t];
    int rend = g_eoff[e + 1];
    int tid = threadIdx.x;

    if (tid < TQ) {
        int gr = r0 + tid;
        if (gr >= rend) gr = r0;
        int s = g_slots[gr];
        s_slot[tid] = s;
        s_gate[tid] = g_gates[s];
    }
    __syncthreads();

    // A: pure uint4 copy from f16 attn-out
    for (int idx = tid; idx < TQ * 16; idx += 256) {
        int r = idx >> 4, pq = (idx & 15) * 4;
        *reinterpret_cast<uint4*>(A2 + r * CA_STR + pq) =
            *reinterpret_cast<const uint4*>(g_attno2 + (size_t)s_slot[r] * (HD / 2) + pq);
    }
    // B: pure uint4 copy from pre-converted Wo
    for (int idx = tid; idx < 64 * 32; idx += 256) {
        int p = idx >> 5, nq = (idx & 31) * 4;
        *reinterpret_cast<uint4*>(B2 + p * CB_STR + nq) =
            *reinterpret_cast<const uint4*>(g_woh2 + ((size_t)e * (HD / 2) + p) * D + n0 + nq);
    }
    __syncthreads();

    int warp = tid >> 5, lane = tid & 31;
    int g = lane >> 2, tg = lane & 3;
    int r_a = warp * 16 + g, r_b = r_a + 8;

    float acc[16][4] = {};

#pragma unroll
    for (int ks = 0; ks < 8; ks++) {
        const __half2* a0 = A2 + r_a * CA_STR + 8 * ks + tg;
        const __half2* a1 = A2 + r_b * CA_STR + 8 * ks + tg;
        uint32_t a[4] = { *reinterpret_cast<const uint32_t*>(a0),
                          *reinterpret_cast<const uint32_t*>(a1),
                          *reinterpret_cast<const uint32_t*>(a0 + 4),
                          *reinterpret_cast<const uint32_t*>(a1 + 4) };
        const __half2* b0 = B2 + (8 * ks + tg) * CB_STR + g;
        const __half2* b1 = B2 + (8 * ks + 4 + tg) * CB_STR + g;
#pragma unroll
        for (int nc = 0; nc < 16; nc++) {
            uint32_t bb[2] = { *reinterpret_cast<const uint32_t*>(b0 + 8 * nc),
                               *reinterpret_cast<const uint32_t*>(b1 + 8 * nc) };
            mma_f16(acc[nc], a, bb);
        }
    }

    bool va = (r0 + r_a < rend), vb = (r0 + r_b < rend);
    float ga = s_gate[r_a], gb = s_gate[r_b];
    float* da = g_ws + (size_t)s_slot[r_a] * D + n0;
    float* db = g_ws + (size_t)s_slot[r_b] * D + n0;
#pragma unroll
    for (int nc = 0; nc < 16; nc++) {
        int c = 8 * nc + 2 * tg;
        if (va) *reinterpret_cast<float2*>(da + c) = make_float2(acc[nc][0] * ga, acc[nc][1] * ga);
        if (vb) *reinterpret_cast<float2*>(db + c) = make_float2(acc[nc][2] * gb, acc[nc][3] * gb);
    }
}

// ---------------------------------------------------------------------------
// Kernel 8: reduce 8 slot rows per token → y
// ---------------------------------------------------------------------------
__global__ __launch_bounds__(256) void reduce_kernel(float* __restrict__ y)
{
    int t = blockIdx.x;
    int c = threadIdx.x * 4;
    float4 s = make_float4(0.f, 0.f, 0.f, 0.f);
#pragma unroll
    for (int h = 0; h < H; h++) {
        float4 v = *reinterpret_cast<const float4*>(g_ws + ((size_t)(t * H + h)) * D + c);
        s.x += v.x; s.y += v.y; s.z += v.z; s.w += v.w;
    }
    *reinterpret_cast<float4*>(y + (size_t)t * D + c) = s;
}

// ---------------------------------------------------------------------------
// Kernel 9: finalize aux loss
// ---------------------------------------------------------------------------
__global__ void aux_final_kernel(float* __restrict__ out) {
    if (threadIdx.x == 0) {
        const float inv_bn = 1.0f / (float)BN_TOK;
        float sw = 0.f;
        for (int e = 0; e < E; e++)
            sw += (g_aux[e] * inv_bn) * (g_aux[E + e] * inv_bn);
        float aux = 0.1f * (float)E * sw + 0.001f * (g_aux[2 * E] * inv_bn);
        out[(size_t)BN_TOK * D] = aux;
    }
}

// ---------------------------------------------------------------------------
// Launch
// ---------------------------------------------------------------------------
extern "C" void kernel_launch(void* const* d_in, const int* in_sizes, int n_in,
                              void* d_out, int out_size)
{
    const float* x    = (const float*)d_in[0];
    const int* task_bh = (const int*)d_in[1];
    const float* Wg   = (const float*)d_in[2];
    const float* Wq   = (const float*)d_in[3];
    const float* Wo   = (const float*)d_in[4];
    const float* Wkv  = (const float*)d_in[5];
    const float* bkv  = (const float*)d_in[6];
    float* out = (float*)d_out;

    const int attn_smem = (2 * QT * QH_STR + 4 * KBUF + 2 * VBUF + QT * PS2_STR) * 4;
    const int qg_smem = (2 * TQ * QA_STR + 2 * 32 * QB_STR) * 4 + 2 * TQ * 4;
    const int cg_smem = (TQ * CA_STR + 64 * CB_STR) * 4 + 2 * TQ * 4;
    cudaFuncSetAttribute(attn_kernel,  cudaFuncAttributeMaxDynamicSharedMemorySize, attn_smem);
    cudaFuncSetAttribute(qgemm_kernel, cudaFuncAttributeMaxDynamicSharedMemorySize, qg_smem);
    cudaFuncSetAttribute(cgemm_kernel, cudaFuncAttributeMaxDynamicSharedMemorySize, cg_smem);

    init_aux_kernel<<<1, 64>>>();
    xsplit_kernel<<<BN_TOK, 256>>>(x);
    wqsplit_kernel<<<dim3(D / 2, E), 128>>>(Wq);
    wosplit_kernel<<<dim3(HD / 2, E), 256>>>(Wo);
    gating_kernel<<<BN_TOK / 8, 256>>>(x, task_bh, Wg);
    scan_kernel<<<1, 32>>>();
    scatter_kernel<<<NSLOT / 256, 256>>>();
    kv_kernel<<<dim3(BN_TOK / 64, (2 * HD) / 64), 256>>>(x, Wkv, bkv);
    qgemm_kernel<<<NT_MAX, 512, qg_smem>>>();
    attn_kernel<<<dim3(N / QT, H, B), 256, attn_smem>>>();
    cgemm_kernel<<<dim3(NT_MAX, 8), 256, cg_smem>>>();
    reduce_kernel<<<BN_TOK, 256>>>(out);
    aux_final_kernel<<<1, 32>>>(out);
}

// round 13
// speedup vs baseline: 2.1397x; 1.1268x over previous
#include <cuda_runtime.h>
#include <cuda_fp16.h>
#include <math.h>
#include <stdint.h>

// ---------------------------------------------------------------------------
// Problem constants
// ---------------------------------------------------------------------------
constexpr int B    = 4;
constexpr int N    = 2048;
constexpr int D    = 1024;
constexpr int E    = 24;
constexpr int H    = 8;
constexpr int HD   = 128;
constexpr int BN_TOK = B * N;          // 8192 tokens
constexpr int NSLOT  = BN_TOK * H;     // 65536 (token,slot) pairs

// Grouped-GEMM tiling
constexpr int TQ = 128;                // rows per expert tile
constexpr int NT_MAX = NSLOT / TQ + E; // 536 max tiles

// ---------------------------------------------------------------------------
// Scratch (device globals — no allocations allowed)
// ---------------------------------------------------------------------------
__device__ __half2 g_kh2[(HD / 2) * BN_TOK];   // 2 MB  K hi,  pair-major [hd-pair][token]
__device__ __half2 g_kl2[(HD / 2) * BN_TOK];   // 2 MB  K lo*2^10
__device__ __half2 g_vh2[HD * (BN_TOK / 2)];   // 2 MB  V f16 transposed [hd][token-pair]
__device__ float   g_q[NSLOT * HD];            // 32 MB [slot][hd]
__device__ __half2 g_attno2[NSLOT * (HD / 2)]; // 16 MB attn out f16 [slot][hd-pair]
__device__ __half2 g_ws2[(size_t)NSLOT * (D / 2)]; // 134 MB combine scratch f16 [slot][pair]
// pre-split inputs (convert-once)
__device__ __half2 g_xh2[BN_TOK * (D / 2)];    // 16 MB x hi [token][pair]
__device__ __half2 g_xl2[BN_TOK * (D / 2)];    // 16 MB x lo*2^10
__device__ __half2 g_wqh2[(size_t)E * (D / 2) * HD];  // 6.3 MB Wq hi [e][kpair][n]
__device__ __half2 g_wql2[(size_t)E * (D / 2) * HD];  // 6.3 MB Wq lo*2^10
__device__ __half2 g_woh2[(size_t)E * (HD / 2) * D];  // 6.3 MB Wo f16 [e][kpair][n]
__device__ int   g_topi[NSLOT];
__device__ float g_gates[NSLOT];
__device__ float g_aux[2 * E + 1];
// expert bucketing
__device__ int g_ecnt[E];
__device__ int g_eoff[E + 1];
__device__ int g_ecursor[E];
__device__ int g_slots[NSLOT];
__device__ int g_tile_e[NT_MAX];
__device__ int g_tile_r0[NT_MAX];
__device__ int g_ntiles;

// ---------------------------------------------------------------------------
// helpers
// ---------------------------------------------------------------------------
__device__ __forceinline__ void mma_f16(float* d, const uint32_t* a, const uint32_t* b) {
    asm volatile(
        "mma.sync.aligned.m16n8k16.row.col.f32.f16.f16.f32 "
        "{%0,%1,%2,%3}, {%4,%5,%6,%7}, {%8,%9}, {%0,%1,%2,%3};\n"
        : "+f"(d[0]), "+f"(d[1]), "+f"(d[2]), "+f"(d[3])
        : "r"(a[0]), "r"(a[1]), "r"(a[2]), "r"(a[3]), "r"(b[0]), "r"(b[1]));
}
__device__ __forceinline__ void h2split(float x, float y, __half2& hi, __half2& lo) {
    hi = __floats2half2_rn(x, y);
    float2 hf = __half22float2(hi);
    lo = __floats2half2_rn((x - hf.x) * 1024.f, (y - hf.y) * 1024.f);
}
constexpr float LO_INV = 1.f / 1024.f;

__device__ __forceinline__ void cp16(void* smem, const void* gmem) {
    uint32_t s = (uint32_t)__cvta_generic_to_shared(smem);
    asm volatile("cp.async.cg.shared.global [%0], [%1], 16;\n" :: "r"(s), "l"(gmem));
}
__device__ __forceinline__ void cp_commit() {
    asm volatile("cp.async.commit_group;\n");
}
__device__ __forceinline__ void cp_wait0() {
    asm volatile("cp.async.wait_group 0;\n" ::: "memory");
}

// ---------------------------------------------------------------------------
// Kernel 0: zero aux + expert histogram
// ---------------------------------------------------------------------------
__global__ void init_aux_kernel() {
    int tid = threadIdx.x;
    if (tid < 2 * E + 1) g_aux[tid] = 0.f;
    if (tid < E) g_ecnt[tid] = 0;
}

// ---------------------------------------------------------------------------
// Pre-split kernels (convert-once)
// ---------------------------------------------------------------------------
__global__ __launch_bounds__(256) void xsplit_kernel(const float* __restrict__ x) {
    int t = blockIdx.x;
    int c = threadIdx.x * 4;
    float4 v = *reinterpret_cast<const float4*>(x + (size_t)t * D + c);
    __half2 h0, l0, h1, l1;
    h2split(v.x, v.y, h0, l0);
    h2split(v.z, v.w, h1, l1);
    int p = c >> 1;
    g_xh2[(size_t)t * (D / 2) + p]     = h0;
    g_xh2[(size_t)t * (D / 2) + p + 1] = h1;
    g_xl2[(size_t)t * (D / 2) + p]     = l0;
    g_xl2[(size_t)t * (D / 2) + p + 1] = l1;
}

__global__ __launch_bounds__(128) void wqsplit_kernel(const float* __restrict__ Wq) {
    int p = blockIdx.x;      // kpair 0..511
    int e = blockIdx.y;
    int n = threadIdx.x;     // 0..127
    const float* w = Wq + (size_t)e * D * HD;
    float a = w[(size_t)(2 * p) * HD + n];
    float b2 = w[(size_t)(2 * p + 1) * HD + n];
    __half2 hh, ll;
    h2split(a, b2, hh, ll);
    size_t o = ((size_t)e * (D / 2) + p) * HD + n;
    g_wqh2[o] = hh;
    g_wql2[o] = ll;
}

__global__ __launch_bounds__(256) void wosplit_kernel(const float* __restrict__ Wo) {
    int p = blockIdx.x;      // kpair 0..63
    int e = blockIdx.y;
    const float* w = Wo + (size_t)e * HD * D;
    for (int n = threadIdx.x; n < D; n += 256) {
        g_woh2[((size_t)e * (HD / 2) + p) * D + n] =
            __floats2half2_rn(w[(size_t)(2 * p) * D + n], w[(size_t)(2 * p + 1) * D + n]);
    }
}

// ---------------------------------------------------------------------------
// Kernel 1: gating
// ---------------------------------------------------------------------------
__global__ __launch_bounds__(256) void gating_kernel(
    const float* __restrict__ x, const int* __restrict__ task_bh,
    const float* __restrict__ Wg)
{
    __shared__ float s_aux[2 * E + 1];
    __shared__ int   s_ecnt[E];
    int tid = threadIdx.x;
    if (tid < 2 * E + 1) s_aux[tid] = 0.f;
    if (tid < E) s_ecnt[tid] = 0;
    __syncthreads();

    int warp = tid >> 5, lane = tid & 31;
    int t = blockIdx.x * 8 + warp;
    int b = t >> 11;
    int task = task_bh[b];
    const float* xrow = x + (size_t)t * D;
    const float* wg   = Wg + (size_t)task * D * E;

    float acc[E];
#pragma unroll
    for (int e = 0; e < E; e++) acc[e] = 0.f;

    for (int i = lane; i < D; i += 32) {
        float xv = xrow[i];
        const float4* w4 = reinterpret_cast<const float4*>(wg + (size_t)i * E);
#pragma unroll
        for (int j = 0; j < 6; j++) {
            float4 v = w4[j];
            acc[4*j+0] += xv * v.x; acc[4*j+1] += xv * v.y;
            acc[4*j+2] += xv * v.z; acc[4*j+3] += xv * v.w;
        }
    }
#pragma unroll
    for (int e = 0; e < E; e++) {
#pragma unroll
        for (int off = 16; off >= 1; off >>= 1)
            acc[e] += __shfl_xor_sync(0xffffffffu, acc[e], off);
    }
    float mx = acc[0];
#pragma unroll
    for (int e = 1; e < E; e++) mx = fmaxf(mx, acc[e]);
    float p[E]; float s = 0.f;
#pragma unroll
    for (int e = 0; e < E; e++) { p[e] = __expf(acc[e] - mx); s += p[e]; }
    float inv_s = 1.f / s;
    float lse = mx + __logf(s);

    if (lane < E) atomicAdd(&s_aux[E + lane], p[lane] * inv_s);
    if (lane == 0) {
        atomicAdd(&s_aux[2 * E], lse * lse);
        float tv[H]; int ti[H]; float gsum = 0.f;
#pragma unroll
        for (int h = 0; h < H; h++) {
            float best = -1.f; int bi = 0;
#pragma unroll
            for (int e = 0; e < E; e++)
                if (p[e] > best) { best = p[e]; bi = e; }
            tv[h] = best * inv_s; ti[h] = bi; p[bi] = -2.f;
            gsum += tv[h];
            atomicAdd(&s_aux[bi], 1.0f);
            atomicAdd(&s_ecnt[bi], 1);
        }
        float ig = 1.f / gsum;
#pragma unroll
        for (int h = 0; h < H; h++) {
            g_topi[t * H + h]  = ti[h];
            g_gates[t * H + h] = tv[h] * ig;
        }
    }
    __syncthreads();
    if (tid < 2 * E + 1) atomicAdd(&g_aux[tid], s_aux[tid]);
    if (tid < E) atomicAdd(&g_ecnt[tid], s_ecnt[tid]);
}

// ---------------------------------------------------------------------------
// Kernel 2: serial scan over experts → offsets + tile table
// ---------------------------------------------------------------------------
__global__ void scan_kernel() {
    if (threadIdx.x == 0) {
        int off = 0, nt = 0;
        for (int e = 0; e < E; e++) {
            g_eoff[e] = off;
            g_ecursor[e] = 0;
            int c = g_ecnt[e];
            for (int r = 0; r < c; r += TQ) {
                g_tile_e[nt]  = e;
                g_tile_r0[nt] = off + r;
                nt++;
            }
            off += c;
        }
        g_eoff[E] = off;
        g_ntiles = nt;
    }
}

// ---------------------------------------------------------------------------
// Kernel 3: scatter slot ids into expert buckets
// ---------------------------------------------------------------------------
__global__ void scatter_kernel() {
    int i = blockIdx.x * 256 + threadIdx.x;
    int e = g_topi[i];
    int pos = atomicAdd(&g_ecursor[e], 1);
    g_slots[g_eoff[e] + pos] = i;
}

// ---------------------------------------------------------------------------
// Kernel 4: kv = x @ Wkv + bkv → K as f16 hi/lo pair-major, V as f16 transposed
// ---------------------------------------------------------------------------
__global__ __launch_bounds__(256) void kv_kernel(
    const float* __restrict__ x, const float* __restrict__ Wkv,
    const float* __restrict__ bkv)
{
    __shared__ float As[64][17];
    __shared__ float Bs[16][64];
    int tid = threadIdx.x;
    int tx = tid & 15, ty = tid >> 4;
    int t0 = blockIdx.x * 64;
    int n0 = blockIdx.y * 64;

    float acc[4][4] = {};

    for (int k0 = 0; k0 < D; k0 += 16) {
#pragma unroll
        for (int i = 0; i < 4; i++) {
            int idx = tid + i * 256;
            int r = idx >> 4, kk = idx & 15;
            As[r][kk] = x[(size_t)(t0 + r) * D + k0 + kk];
        }
#pragma unroll
        for (int i = 0; i < 4; i++) {
            int idx = tid + i * 256;
            int kr = idx >> 6, nn = idx & 63;
            Bs[kr][nn] = Wkv[(size_t)(k0 + kr) * (2 * HD) + n0 + nn];
        }
        __syncthreads();
#pragma unroll
        for (int kk = 0; kk < 16; kk++) {
            float a[4];
#pragma unroll
            for (int i = 0; i < 4; i++) a[i] = As[ty * 4 + i][kk];
            float4 bv = *reinterpret_cast<const float4*>(&Bs[kk][tx * 4]);
            float bb[4] = {bv.x, bv.y, bv.z, bv.w};
#pragma unroll
            for (int i = 0; i < 4; i++)
#pragma unroll
                for (int j = 0; j < 4; j++)
                    acc[i][j] += a[i] * bb[j];
        }
        __syncthreads();
    }

    int c0 = n0 + tx * 4;
    float vv[4][4];
#pragma unroll
    for (int i = 0; i < 4; i++)
#pragma unroll
        for (int j = 0; j < 4; j++)
            vv[i][j] = acc[i][j] + bkv[c0 + j];

    if (c0 < HD) {
        int p0 = c0 >> 1;
#pragma unroll
        for (int i = 0; i < 4; i++) {
            int t = t0 + ty * 4 + i;
            __half2 hh, ll;
            h2split(vv[i][0], vv[i][1], hh, ll);
            g_kh2[(size_t)p0 * BN_TOK + t] = hh;
            g_kl2[(size_t)p0 * BN_TOK + t] = ll;
            h2split(vv[i][2], vv[i][3], hh, ll);
            g_kh2[(size_t)(p0 + 1) * BN_TOK + t] = hh;
            g_kl2[(size_t)(p0 + 1) * BN_TOK + t] = ll;
        }
    } else {
        int tp0 = (t0 + ty * 4) >> 1;
#pragma unroll
        for (int j = 0; j < 4; j++) {
            int k = c0 + j - HD;
            g_vh2[(size_t)k * (BN_TOK / 2) + tp0]     = __floats2half2_rn(vv[0][j], vv[1][j]);
            g_vh2[(size_t)k * (BN_TOK / 2) + tp0 + 1] = __floats2half2_rn(vv[2][j], vv[3][j]);
        }
    }
}

// ---------------------------------------------------------------------------
// Kernel 5: grouped q GEMM — f16 error-compensated mma, cp.async
// double-buffered chunk pipeline. 512 threads, M=128, N=128, K=1024.
// ---------------------------------------------------------------------------
constexpr int QG_K  = 64;    // floats per k-chunk (32 pairs)
constexpr int QA_STR = 36;   // Ahi/Alo [row 128][kpair 32 + pad]  (half2)
constexpr int QB_STR = 136;  // Bhi/Blo [kpair 32][n 128 + pad]    (half2)
constexpr int QABUF = TQ * QA_STR;   // 4608
constexpr int QBBUF = 32 * QB_STR;   // 4352
constexpr int QNCH  = D / QG_K;      // 16 chunks

__global__ __launch_bounds__(512, 1) void qgemm_kernel()
{
    extern __shared__ __half2 qsm[];
    __half2* Ahi = qsm;                     // 2 * 4608
    __half2* Alo = Ahi + 2 * QABUF;         // 2 * 4608
    __half2* Bhi = Alo + 2 * QABUF;         // 2 * 4352
    __half2* Blo = Bhi + 2 * QBBUF;         // 2 * 4352
    int* s_tok  = reinterpret_cast<int*>(Blo + 2 * QBBUF);   // 128
    int* s_slot = s_tok + TQ;                                 // 128

    int t = blockIdx.x;
    if (t >= g_ntiles) return;
    int e = g_tile_e[t], r0 = g_tile_r0[t];
    int rend = g_eoff[e + 1];
    int tid = threadIdx.x;

    if (tid < TQ) {
        int gr = r0 + tid;
        if (gr >= rend) gr = r0;
        int s = g_slots[gr];
        s_slot[tid] = s;
        s_tok[tid]  = s >> 3;
    }
    __syncthreads();

    int warp = tid >> 5, lane = tid & 31;
    int g = lane >> 2, tg = lane & 3;
    int rg = warp & 7, ch = warp >> 3;
    int r_a = rg * 16 + g, r_b = r_a + 8;
    const size_t wq_base = (size_t)e * (D / 2) * HD;

    // prefetch chunk 0 into buffer 0
    {
        for (int idx = tid; idx < TQ * 8; idx += 512) {
            int r = idx >> 3, pq = (idx & 7) * 4;
            size_t src = (size_t)s_tok[r] * (D / 2) + pq;
            cp16(Ahi + r * QA_STR + pq, g_xh2 + src);
            cp16(Alo + r * QA_STR + pq, g_xl2 + src);
        }
        for (int idx = tid; idx < 32 * 32; idx += 512) {
            int p = idx >> 5, nq = (idx & 31) * 4;
            size_t src = wq_base + (size_t)p * HD + nq;
            cp16(Bhi + p * QB_STR + nq, g_wqh2 + src);
            cp16(Blo + p * QB_STR + nq, g_wql2 + src);
        }
        cp_commit();
    }

    float scc[8][4] = {};
    float scl[8][4] = {};

    for (int it = 0; it < QNCH; it++) {
        int buf = it & 1;
        cp_wait0();
        __syncthreads();   // chunk `it` ready; prev compute done on other buf

        if (it + 1 < QNCH) {
            int kp0 = (it + 1) * (QG_K / 2);
            int bn = buf ^ 1;
            __half2* AhiN = Ahi + bn * QABUF;
            __half2* AloN = Alo + bn * QABUF;
            __half2* BhiN = Bhi + bn * QBBUF;
            __half2* BloN = Blo + bn * QBBUF;
            for (int idx = tid; idx < TQ * 8; idx += 512) {
                int r = idx >> 3, pq = (idx & 7) * 4;
                size_t src = (size_t)s_tok[r] * (D / 2) + kp0 + pq;
                cp16(AhiN + r * QA_STR + pq, g_xh2 + src);
                cp16(AloN + r * QA_STR + pq, g_xl2 + src);
            }
            for (int idx = tid; idx < 32 * 32; idx += 512) {
                int p = idx >> 5, nq = (idx & 31) * 4;
                size_t src = wq_base + (size_t)(kp0 + p) * HD + nq;
                cp16(BhiN + p * QB_STR + nq, g_wqh2 + src);
                cp16(BloN + p * QB_STR + nq, g_wql2 + src);
            }
            cp_commit();
        }

        __half2* AhiB = Ahi + buf * QABUF;
        __half2* AloB = Alo + buf * QABUF;
        __half2* BhiB = Bhi + buf * QBBUF;
        __half2* BloB = Blo + buf * QBBUF;

#pragma unroll
        for (int ks = 0; ks < 4; ks++) {
            const __half2* ah0 = AhiB + r_a * QA_STR + 8 * ks + tg;
            const __half2* ah1 = AhiB + r_b * QA_STR + 8 * ks + tg;
            const __half2* al0 = AloB + r_a * QA_STR + 8 * ks + tg;
            const __half2* al1 = AloB + r_b * QA_STR + 8 * ks + tg;
            uint32_t ah[4] = { *reinterpret_cast<const uint32_t*>(ah0),
                               *reinterpret_cast<const uint32_t*>(ah1),
                               *reinterpret_cast<const uint32_t*>(ah0 + 4),
                               *reinterpret_cast<const uint32_t*>(ah1 + 4) };
            uint32_t al[4] = { *reinterpret_cast<const uint32_t*>(al0),
                               *reinterpret_cast<const uint32_t*>(al1),
                               *reinterpret_cast<const uint32_t*>(al0 + 4),
                               *reinterpret_cast<const uint32_t*>(al1 + 4) };
            const __half2* bh0 = BhiB + (8 * ks + tg) * QB_STR + ch * 64 + g;
            const __half2* bh1 = BhiB + (8 * ks + 4 + tg) * QB_STR + ch * 64 + g;
            const __half2* bl0 = BloB + (8 * ks + tg) * QB_STR + ch * 64 + g;
            const __half2* bl1 = BloB + (8 * ks + 4 + tg) * QB_STR + ch * 64 + g;
#pragma unroll
            for (int nc = 0; nc < 8; nc++) {
                uint32_t bh[2] = { *reinterpret_cast<const uint32_t*>(bh0 + 8 * nc),
                                   *reinterpret_cast<const uint32_t*>(bh1 + 8 * nc) };
                uint32_t bl[2] = { *reinterpret_cast<const uint32_t*>(bl0 + 8 * nc),
                                   *reinterpret_cast<const uint32_t*>(bl1 + 8 * nc) };
                mma_f16(scc[nc], ah, bh);
                mma_f16(scl[nc], al, bh);
                mma_f16(scl[nc], ah, bl);
            }
        }
        __syncthreads();   // compute on buf done before it's refilled next iter
    }

    bool va = (r0 + r_a < rend), vb = (r0 + r_b < rend);
    float* da = g_q + (size_t)s_slot[r_a] * HD + ch * 64;
    float* db = g_q + (size_t)s_slot[r_b] * HD + ch * 64;
#pragma unroll
    for (int nc = 0; nc < 8; nc++) {
        int c = 8 * nc + 2 * tg;
        float o0 = scc[nc][0] + scl[nc][0] * LO_INV;
        float o1 = scc[nc][1] + scl[nc][1] * LO_INV;
        float o2 = scc[nc][2] + scl[nc][2] * LO_INV;
        float o3 = scc[nc][3] + scl[nc][3] * LO_INV;
        if (va) *reinterpret_cast<float2*>(da + c) = make_float2(o0, o1);
        if (vb) *reinterpret_cast<float2*>(db + c) = make_float2(o2, o3);
    }
}

// ---------------------------------------------------------------------------
// Kernel 6: flash attention — cp.async double-buffered K/V, f16-compensated QK,
// log2-domain softmax (ex2.f16x2), f16 PV, f16 attn-out.
// ---------------------------------------------------------------------------
constexpr int QT = 128;
constexpr int KT = 64;
constexpr int QH_STR  = 68;
constexpr int KH_STR  = 72;
constexpr int VT2_STR = 36;
constexpr int PS2_STR = 36;
constexpr int KBUF = 64 * KH_STR;
constexpr int VBUF = HD * VT2_STR;

__global__ __launch_bounds__(256, 1) void attn_kernel()
{
    extern __shared__ __half2 smh[];
    __half2* Qhi  = smh;                      // 128*68
    __half2* Qlo  = Qhi  + QT * QH_STR;       // 128*68
    __half2* Khi  = Qlo  + QT * QH_STR;       // 2 * 64*72
    __half2* Klo  = Khi  + 2 * KBUF;          // 2 * 64*72
    __half2* VhT2 = Klo  + 2 * KBUF;          // 2 * 128*36
    __half2* Ps2  = VhT2 + 2 * VBUF;          // 128*36

    int tid  = threadIdx.x;
    int warp = tid >> 5, lane = tid & 31;
    int g = lane >> 2, tg = lane & 3;
    int n0 = blockIdx.x * QT;
    int h  = blockIdx.y;
    int b  = blockIdx.z;
    int bN0 = b * N;
    const float qsc = 0.08838834764831845f * 1.44269504088896340736f;

    // load Q once: scale, split into f16 hi / lo*2^10
    for (int idx = tid; idx < QT * (HD / 4); idx += 256) {
        int r = idx >> 5, kq = (idx & 31) * 4;
        float4 qv = *reinterpret_cast<const float4*>(
            g_q + (((size_t)(bN0 + n0 + r)) * H + h) * HD + kq);
        qv.x *= qsc; qv.y *= qsc; qv.z *= qsc; qv.w *= qsc;
        __half2 h0, l0, h1, l1;
        h2split(qv.x, qv.y, h0, l0);
        h2split(qv.z, qv.w, h1, l1);
        int p0 = kq >> 1;
        Qhi[r * QH_STR + p0]     = h0;
        Qhi[r * QH_STR + p0 + 1] = h1;
        Qlo[r * QH_STR + p0]     = l0;
        Qlo[r * QH_STR + p0 + 1] = l1;
    }

    // prefetch tile 0 into buffer 0
    {
        for (int idx = tid; idx < 64 * 16; idx += 256) {
            int p = idx >> 4, mq = (idx & 15) * 4;
            cp16(Khi + p * KH_STR + mq, g_kh2 + (size_t)p * BN_TOK + bN0 + mq);
            cp16(Klo + p * KH_STR + mq, g_kl2 + (size_t)p * BN_TOK + bN0 + mq);
        }
        int tp0 = bN0 >> 1;
        for (int idx = tid; idx < HD * 8; idx += 256) {
            int k = idx >> 3, tq = (idx & 7) * 4;
            cp16(VhT2 + k * VT2_STR + tq, g_vh2 + (size_t)k * (BN_TOK / 2) + tp0 + tq);
        }
        cp_commit();
    }

    const int r_a = warp * 16 + g;
    const int r_b = r_a + 8;

    float o[16][4];
#pragma unroll
    for (int nc = 0; nc < 16; nc++)
#pragma unroll
        for (int j = 0; j < 4; j++) o[nc][j] = 0.f;
    float m_a = -1e30f, m_b = -1e30f, l_a = 0.f, l_b = 0.f;

    for (int it = 0; it < N / KT; it++) {
        int buf = it & 1;
        cp_wait0();
        __syncthreads();

        if (it + 1 < N / KT) {
            int m0n = (it + 1) * KT;
            int bn = buf ^ 1;
            __half2* KhiN = Khi + bn * KBUF;
            __half2* KloN = Klo + bn * KBUF;
            __half2* VN   = VhT2 + bn * VBUF;
            for (int idx = tid; idx < 64 * 16; idx += 256) {
                int p = idx >> 4, mq = (idx & 15) * 4;
                cp16(KhiN + p * KH_STR + mq, g_kh2 + (size_t)p * BN_TOK + bN0 + m0n + mq);
                cp16(KloN + p * KH_STR + mq, g_kl2 + (size_t)p * BN_TOK + bN0 + m0n + mq);
            }
            int tp0 = (bN0 + m0n) >> 1;
            for (int idx = tid; idx < HD * 8; idx += 256) {
                int k = idx >> 3, tq = (idx & 7) * 4;
                cp16(VN + k * VT2_STR + tq, g_vh2 + (size_t)k * (BN_TOK / 2) + tp0 + tq);
            }
            cp_commit();
        }

        __half2* KhiB = Khi + buf * KBUF;
        __half2* KloB = Klo + buf * KBUF;
        __half2* VB   = VhT2 + buf * VBUF;

        // ---- S = Q K^T : f16 compensated, k16 steps ----
        float scc[8][4] = {};
        float scl[8][4] = {};
#pragma unroll
        for (int ks = 0; ks < 8; ks++) {
            const __half2* qh0 = Qhi + r_a * QH_STR + 8 * ks + tg;
            const __half2* qh1 = Qhi + r_b * QH_STR + 8 * ks + tg;
            const __half2* ql0 = Qlo + r_a * QH_STR + 8 * ks + tg;
            const __half2* ql1 = Qlo + r_b * QH_STR + 8 * ks + tg;
            uint32_t ah[4] = { *reinterpret_cast<const uint32_t*>(qh0),
                               *reinterpret_cast<const uint32_t*>(qh1),
                               *reinterpret_cast<const uint32_t*>(qh0 + 4),
                               *reinterpret_cast<const uint32_t*>(qh1 + 4) };
            uint32_t al[4] = { *reinterpret_cast<const uint32_t*>(ql0),
                               *reinterpret_cast<const uint32_t*>(ql1),
                               *reinterpret_cast<const uint32_t*>(ql0 + 4),
                               *reinterpret_cast<const uint32_t*>(ql1 + 4) };
            const __half2* kh0 = KhiB + (8 * ks + tg) * KH_STR + g;
            const __half2* kh1 = KhiB + (8 * ks + 4 + tg) * KH_STR + g;
            const __half2* kl0 = KloB + (8 * ks + tg) * KH_STR + g;
            const __half2* kl1 = KloB + (8 * ks + 4 + tg) * KH_STR + g;
#pragma unroll
            for (int nc = 0; nc < 8; nc++) {
                uint32_t bh[2] = { *reinterpret_cast<const uint32_t*>(kh0 + 8 * nc),
                                   *reinterpret_cast<const uint32_t*>(kh1 + 8 * nc) };
                uint32_t bl[2] = { *reinterpret_cast<const uint32_t*>(kl0 + 8 * nc),
                                   *reinterpret_cast<const uint32_t*>(kl1 + 8 * nc) };
                mma_f16(scc[nc], ah, bh);
                mma_f16(scl[nc], al, bh);
                mma_f16(scl[nc], ah, bl);
            }
        }
#pragma unroll
        for (int nc = 0; nc < 8; nc++)
#pragma unroll
            for (int j = 0; j < 4; j++)
                scc[nc][j] += scl[nc][j] * LO_INV;

        // ---- online softmax (log2 domain, f16x2 ex2) ----
        float lm_a = -1e30f, lm_b = -1e30f;
#pragma unroll
        for (int nc = 0; nc < 8; nc++) {
            lm_a = fmaxf(lm_a, fmaxf(scc[nc][0], scc[nc][1]));
            lm_b = fmaxf(lm_b, fmaxf(scc[nc][2], scc[nc][3]));
        }
#pragma unroll
        for (int off = 1; off <= 2; off <<= 1) {
            lm_a = fmaxf(lm_a, __shfl_xor_sync(0xffffffffu, lm_a, off));
            lm_b = fmaxf(lm_b, __shfl_xor_sync(0xffffffffu, lm_b, off));
        }
        float mn_a = fmaxf(m_a, lm_a), mn_b = fmaxf(m_b, lm_b);
        float al_a = exp2f(m_a - mn_a), al_b = exp2f(m_b - mn_b);
        m_a = mn_a; m_b = mn_b;

        float rs_a = 0.f, rs_b = 0.f;
#pragma unroll
        for (int nc = 0; nc < 8; nc++) {
            __half2 ha = h2exp2(__floats2half2_rn(scc[nc][0] - mn_a, scc[nc][1] - mn_a));
            __half2 hb = h2exp2(__floats2half2_rn(scc[nc][2] - mn_b, scc[nc][3] - mn_b));
            int cp = 4 * nc + tg;
            Ps2[r_a * PS2_STR + cp] = ha;
            Ps2[r_b * PS2_STR + cp] = hb;
            float2 fa = __half22float2(ha);
            float2 fb = __half22float2(hb);
            rs_a += fa.x + fa.y;
            rs_b += fb.x + fb.y;
        }
#pragma unroll
        for (int off = 1; off <= 2; off <<= 1) {
            rs_a += __shfl_xor_sync(0xffffffffu, rs_a, off);
            rs_b += __shfl_xor_sync(0xffffffffu, rs_b, off);
        }
        l_a = l_a * al_a + rs_a;
        l_b = l_b * al_b + rs_b;
#pragma unroll
        for (int nc = 0; nc < 16; nc++) {
            o[nc][0] *= al_a; o[nc][1] *= al_a;
            o[nc][2] *= al_b; o[nc][3] *= al_b;
        }

        // ---- O += P V ----
#pragma unroll
        for (int ks = 0; ks < 4; ks++) {
            const __half2* pa0 = Ps2 + r_a * PS2_STR + 8 * ks + tg;
            const __half2* pa1 = Ps2 + r_b * PS2_STR + 8 * ks + tg;
            uint32_t a[4];
            a[0] = *reinterpret_cast<const uint32_t*>(pa0);
            a[1] = *reinterpret_cast<const uint32_t*>(pa1);
            a[2] = *reinterpret_cast<const uint32_t*>(pa0 + 4);
            a[3] = *reinterpret_cast<const uint32_t*>(pa1 + 4);
#pragma unroll
            for (int nc = 0; nc < 16; nc++) {
                const __half2* vb = VB + (8 * nc + g) * VT2_STR + 8 * ks + tg;
                uint32_t bb[2];
                bb[0] = *reinterpret_cast<const uint32_t*>(vb);
                bb[1] = *reinterpret_cast<const uint32_t*>(vb + 4);
                mma_f16(o[nc], a, bb);
            }
        }
    }

    float inv_a = 1.f / l_a, inv_b = 1.f / l_b;
    __half2* dsta = g_attno2 + (((size_t)(bN0 + n0 + r_a)) * H + h) * (HD / 2);
    __half2* dstb = g_attno2 + (((size_t)(bN0 + n0 + r_b)) * H + h) * (HD / 2);
#pragma unroll
    for (int nc = 0; nc < 16; nc++) {
        int p = 4 * nc + tg;
        dsta[p] = __floats2half2_rn(o[nc][0] * inv_a, o[nc][1] * inv_a);
        dstb[p] = __floats2half2_rn(o[nc][2] * inv_b, o[nc][3] * inv_b);
    }
}

// ---------------------------------------------------------------------------
// Kernel 7: grouped combine GEMM — single-pass f16, cp.async loads,
// f16 output scratch.
// ---------------------------------------------------------------------------
constexpr int CA_STR = 68;
constexpr int CB_STR = 136;

__global__ __launch_bounds__(256, 2) void cgemm_kernel()
{
    extern __shared__ __half2 csm[];
    __half2* A2 = csm;                  // 128*68
    __half2* B2 = A2 + TQ * CA_STR;     // 64*136
    int*   s_slot = reinterpret_cast<int*>(B2 + 64 * CB_STR);
    float* s_gate = reinterpret_cast<float*>(s_slot + TQ);

    int t = blockIdx.x;
    if (t >= g_ntiles) return;
    int n0 = blockIdx.y * 128;
    int e = g_tile_e[t], r0 = g_tile_r0[t];
    int rend = g_eoff[e + 1];
    int tid = threadIdx.x;

    if (tid < TQ) {
        int gr = r0 + tid;
        if (gr >= rend) gr = r0;
        int s = g_slots[gr];
        s_slot[tid] = s;
        s_gate[tid] = g_gates[s];
    }
    __syncthreads();

    // A: cp.async copies from f16 attn-out
    for (int idx = tid; idx < TQ * 16; idx += 256) {
        int r = idx >> 4, pq = (idx & 15) * 4;
        cp16(A2 + r * CA_STR + pq, g_attno2 + (size_t)s_slot[r] * (HD / 2) + pq);
    }
    // B: cp.async copies from pre-converted Wo
    for (int idx = tid; idx < 64 * 32; idx += 256) {
        int p = idx >> 5, nq = (idx & 31) * 4;
        cp16(B2 + p * CB_STR + nq, g_woh2 + ((size_t)e * (HD / 2) + p) * D + n0 + nq);
    }
    cp_commit();
    cp_wait0();
    __syncthreads();

    int warp = tid >> 5, lane = tid & 31;
    int g = lane >> 2, tg = lane & 3;
    int r_a = warp * 16 + g, r_b = r_a + 8;

    float acc[16][4] = {};

#pragma unroll
    for (int ks = 0; ks < 8; ks++) {
        const __half2* a0 = A2 + r_a * CA_STR + 8 * ks + tg;
        const __half2* a1 = A2 + r_b * CA_STR + 8 * ks + tg;
        uint32_t a[4] = { *reinterpret_cast<const uint32_t*>(a0),
                          *reinterpret_cast<const uint32_t*>(a1),
                          *reinterpret_cast<const uint32_t*>(a0 + 4),
                          *reinterpret_cast<const uint32_t*>(a1 + 4) };
        const __half2* b0 = B2 + (8 * ks + tg) * CB_STR + g;
        const __half2* b1 = B2 + (8 * ks + 4 + tg) * CB_STR + g;
#pragma unroll
        for (int nc = 0; nc < 16; nc++) {
            uint32_t bb[2] = { *reinterpret_cast<const uint32_t*>(b0 + 8 * nc),
                               *reinterpret_cast<const uint32_t*>(b1 + 8 * nc) };
            mma_f16(acc[nc], a, bb);
        }
    }

    bool va = (r0 + r_a < rend), vb = (r0 + r_b < rend);
    float ga = s_gate[r_a], gb = s_gate[r_b];
    __half2* da = g_ws2 + (size_t)s_slot[r_a] * (D / 2) + (n0 >> 1);
    __half2* db = g_ws2 + (size_t)s_slot[r_b] * (D / 2) + (n0 >> 1);
#pragma unroll
    for (int nc = 0; nc < 16; nc++) {
        int p = 4 * nc + tg;
        if (va) da[p] = __floats2half2_rn(acc[nc][0] * ga, acc[nc][1] * ga);
        if (vb) db[p] = __floats2half2_rn(acc[nc][2] * gb, acc[nc][3] * gb);
    }
}

// ---------------------------------------------------------------------------
// Kernel 8: reduce 8 slot rows per token → y  (f16 in, f32 out)
// ---------------------------------------------------------------------------
__global__ __launch_bounds__(256) void reduce_kernel(float* __restrict__ y)
{
    int t = blockIdx.x;
    int p = threadIdx.x * 2;       // pair index (2 half2 = 4 floats per thread)
    float4 s = make_float4(0.f, 0.f, 0.f, 0.f);
#pragma unroll
    for (int h = 0; h < H; h++) {
        const __half2* w = g_ws2 + ((size_t)(t * H + h)) * (D / 2) + p;
        float2 a = __half22float2(w[0]);
        float2 b2 = __half22float2(w[1]);
        s.x += a.x; s.y += a.y; s.z += b2.x; s.w += b2.y;
    }
    *reinterpret_cast<float4*>(y + (size_t)t * D + p * 2) = s;
}

// ---------------------------------------------------------------------------
// Kernel 9: finalize aux loss
// ---------------------------------------------------------------------------
__global__ void aux_final_kernel(float* __restrict__ out) {
    if (threadIdx.x == 0) {
        const float inv_bn = 1.0f / (float)BN_TOK;
        float sw = 0.f;
        for (int e = 0; e < E; e++)
            sw += (g_aux[e] * inv_bn) * (g_aux[E + e] * inv_bn);
        float aux = 0.1f * (float)E * sw + 0.001f * (g_aux[2 * E] * inv_bn);
        out[(size_t)BN_TOK * D] = aux;
    }
}

// ---------------------------------------------------------------------------
// Launch
// ---------------------------------------------------------------------------
extern "C" void kernel_launch(void* const* d_in, const int* in_sizes, int n_in,
                              void* d_out, int out_size)
{
    const float* x    = (const float*)d_in[0];
    const int* task_bh = (const int*)d_in[1];
    const float* Wg   = (const float*)d_in[2];
    const float* Wq   = (const float*)d_in[3];
    const float* Wo   = (const float*)d_in[4];
    const float* Wkv  = (const float*)d_in[5];
    const float* bkv  = (const float*)d_in[6];
    float* out = (float*)d_out;

    const int attn_smem = (2 * QT * QH_STR + 4 * KBUF + 2 * VBUF + QT * PS2_STR) * 4;
    const int qg_smem = (4 * QABUF + 4 * QBBUF) * 4 + 2 * TQ * 4;
    const int cg_smem = (TQ * CA_STR + 64 * CB_STR) * 4 + 2 * TQ * 4;
    cudaFuncSetAttribute(attn_kernel,  cudaFuncAttributeMaxDynamicSharedMemorySize, attn_smem);
    cudaFuncSetAttribute(qgemm_kernel, cudaFuncAttributeMaxDynamicSharedMemorySize, qg_smem);
    cudaFuncSetAttribute(cgemm_kernel, cudaFuncAttributeMaxDynamicSharedMemorySize, cg_smem);

    init_aux_kernel<<<1, 64>>>();
    xsplit_kernel<<<BN_TOK, 256>>>(x);
    wqsplit_kernel<<<dim3(D / 2, E), 128>>>(Wq);
    wosplit_kernel<<<dim3(HD / 2, E), 256>>>(Wo);
    gating_kernel<<<BN_TOK / 8, 256>>>(x, task_bh, Wg);
    scan_kernel<<<1, 32>>>();
    scatter_kernel<<<NSLOT / 256, 256>>>();
    kv_kernel<<<dim3(BN_TOK / 64, (2 * HD) / 64), 256>>>(x, Wkv, bkv);
    qgemm_kernel<<<NT_MAX, 512, qg_smem>>>();
    attn_kernel<<<dim3(N / QT, H, B), 256, attn_smem>>>();
    cgemm_kernel<<<dim3(NT_MAX, 8), 256, cg_smem>>>();
    reduce_kernel<<<BN_TOK, 256>>>(out);
    aux_final_kernel<<<1, 32>>>(out);
}

// round 14
// speedup vs baseline: 2.1568x; 1.0080x over previous
#include <cuda_runtime.h>
#include <cuda_fp16.h>
#include <math.h>
#include <stdint.h>

// ---------------------------------------------------------------------------
// Problem constants
// ---------------------------------------------------------------------------
constexpr int B    = 4;
constexpr int N    = 2048;
constexpr int D    = 1024;
constexpr int E    = 24;
constexpr int H    = 8;
constexpr int HD   = 128;
constexpr int BN_TOK = B * N;          // 8192 tokens
constexpr int NSLOT  = BN_TOK * H;     // 65536 (token,slot) pairs

// Grouped-GEMM tiling
constexpr int TQ = 128;                // rows per expert tile
constexpr int NT_MAX = NSLOT / TQ + E; // 536 max tiles

// ---------------------------------------------------------------------------
// Scratch (device globals — no allocations allowed)
// ---------------------------------------------------------------------------
__device__ __half2 g_kh2[(HD / 2) * BN_TOK];   // 2 MB  K hi,  pair-major [hd-pair][token]
__device__ __half2 g_kl2[(HD / 2) * BN_TOK];   // 2 MB  K lo*2^10
__device__ __half2 g_vh2[HD * (BN_TOK / 2)];   // 2 MB  V f16 transposed [hd][token-pair]
__device__ float   g_q[NSLOT * HD];            // 32 MB [slot][hd]
__device__ __half2 g_attno2[NSLOT * (HD / 2)]; // 16 MB attn out f16 [slot][hd-pair]
__device__ __half2 g_ws2[(size_t)NSLOT * (D / 2)]; // 134 MB combine scratch f16 [slot][pair]
// pre-split inputs (convert-once)
__device__ __half2 g_xh2[BN_TOK * (D / 2)];    // 16 MB x hi [token][pair]
__device__ __half2 g_xl2[BN_TOK * (D / 2)];    // 16 MB x lo*2^10
__device__ __half2 g_wqh2[(size_t)E * (D / 2) * HD];  // 6.3 MB Wq hi [e][kpair][n]
__device__ __half2 g_wql2[(size_t)E * (D / 2) * HD];  // 6.3 MB Wq lo*2^10
__device__ __half2 g_woh2[(size_t)E * (HD / 2) * D];  // 6.3 MB Wo f16 [e][kpair][n]
__device__ int   g_topi[NSLOT];
__device__ float g_gates[NSLOT];
__device__ float g_aux[2 * E + 1];
// expert bucketing
__device__ int g_ecnt[E];
__device__ int g_eoff[E + 1];
__device__ int g_ecursor[E];
__device__ int g_slots[NSLOT];
__device__ int g_tile_e[NT_MAX];
__device__ int g_tile_r0[NT_MAX];
__device__ int g_ntiles;

// ---------------------------------------------------------------------------
// helpers
// ---------------------------------------------------------------------------
__device__ __forceinline__ void mma_f16(float* d, const uint32_t* a, const uint32_t* b) {
    asm volatile(
        "mma.sync.aligned.m16n8k16.row.col.f32.f16.f16.f32 "
        "{%0,%1,%2,%3}, {%4,%5,%6,%7}, {%8,%9}, {%0,%1,%2,%3};\n"
        : "+f"(d[0]), "+f"(d[1]), "+f"(d[2]), "+f"(d[3])
        : "r"(a[0]), "r"(a[1]), "r"(a[2]), "r"(a[3]), "r"(b[0]), "r"(b[1]));
}
__device__ __forceinline__ void h2split(float x, float y, __half2& hi, __half2& lo) {
    hi = __floats2half2_rn(x, y);
    float2 hf = __half22float2(hi);
    lo = __floats2half2_rn((x - hf.x) * 1024.f, (y - hf.y) * 1024.f);
}
constexpr float LO_INV = 1.f / 1024.f;

__device__ __forceinline__ void cp16(void* smem, const void* gmem) {
    uint32_t s = (uint32_t)__cvta_generic_to_shared(smem);
    asm volatile("cp.async.cg.shared.global [%0], [%1], 16;\n" :: "r"(s), "l"(gmem));
}
__device__ __forceinline__ void cp_commit() {
    asm volatile("cp.async.commit_group;\n");
}
__device__ __forceinline__ void cp_wait0() {
    asm volatile("cp.async.wait_group 0;\n" ::: "memory");
}

// ---------------------------------------------------------------------------
// Kernel 0: zero aux + expert histogram
// ---------------------------------------------------------------------------
__global__ void init_aux_kernel() {
    int tid = threadIdx.x;
    if (tid < 2 * E + 1) g_aux[tid] = 0.f;
    if (tid < E) g_ecnt[tid] = 0;
}

// ---------------------------------------------------------------------------
// Pre-split kernels (convert-once)
// ---------------------------------------------------------------------------
__global__ __launch_bounds__(256) void xsplit_kernel(const float* __restrict__ x) {
    int t = blockIdx.x;
    int c = threadIdx.x * 4;
    float4 v = *reinterpret_cast<const float4*>(x + (size_t)t * D + c);
    __half2 h0, l0, h1, l1;
    h2split(v.x, v.y, h0, l0);
    h2split(v.z, v.w, h1, l1);
    int p = c >> 1;
    g_xh2[(size_t)t * (D / 2) + p]     = h0;
    g_xh2[(size_t)t * (D / 2) + p + 1] = h1;
    g_xl2[(size_t)t * (D / 2) + p]     = l0;
    g_xl2[(size_t)t * (D / 2) + p + 1] = l1;
}

__global__ __launch_bounds__(128) void wqsplit_kernel(const float* __restrict__ Wq) {
    int p = blockIdx.x;      // kpair 0..511
    int e = blockIdx.y;
    int n = threadIdx.x;     // 0..127
    const float* w = Wq + (size_t)e * D * HD;
    float a = w[(size_t)(2 * p) * HD + n];
    float b2 = w[(size_t)(2 * p + 1) * HD + n];
    __half2 hh, ll;
    h2split(a, b2, hh, ll);
    size_t o = ((size_t)e * (D / 2) + p) * HD + n;
    g_wqh2[o] = hh;
    g_wql2[o] = ll;
}

__global__ __launch_bounds__(256) void wosplit_kernel(const float* __restrict__ Wo) {
    int p = blockIdx.x;      // kpair 0..63
    int e = blockIdx.y;
    const float* w = Wo + (size_t)e * HD * D;
    for (int n = threadIdx.x; n < D; n += 256) {
        g_woh2[((size_t)e * (HD / 2) + p) * D + n] =
            __floats2half2_rn(w[(size_t)(2 * p) * D + n], w[(size_t)(2 * p + 1) * D + n]);
    }
}

// ---------------------------------------------------------------------------
// Kernel 1: gating — Wg[task] cached in smem (all 8 tokens share the task)
// ---------------------------------------------------------------------------
__global__ __launch_bounds__(256) void gating_kernel(
    const float* __restrict__ x, const int* __restrict__ task_bh,
    const float* __restrict__ Wg)
{
    extern __shared__ float s_wg[];            // D * E floats = 96 KB
    __shared__ float s_aux[2 * E + 1];
    __shared__ int   s_ecnt[E];
    int tid = threadIdx.x;
    if (tid < 2 * E + 1) s_aux[tid] = 0.f;
    if (tid < E) s_ecnt[tid] = 0;

    int warp = tid >> 5, lane = tid & 31;
    int t = blockIdx.x * 8 + warp;
    int b = t >> 11;
    int task = task_bh[b];
    const float* wg = Wg + (size_t)task * D * E;

    // cache Wg[task] in smem (coalesced float4)
    for (int idx = tid; idx < D * E / 4; idx += 256) {
        reinterpret_cast<float4*>(s_wg)[idx] =
            reinterpret_cast<const float4*>(wg)[idx];
    }
    __syncthreads();

    const float* xrow = x + (size_t)t * D;

    float acc[E];
#pragma unroll
    for (int e = 0; e < E; e++) acc[e] = 0.f;

    for (int i = lane; i < D; i += 32) {
        float xv = xrow[i];
        const float4* w4 = reinterpret_cast<const float4*>(s_wg + (size_t)i * E);
#pragma unroll
        for (int j = 0; j < 6; j++) {
            float4 v = w4[j];
            acc[4*j+0] += xv * v.x; acc[4*j+1] += xv * v.y;
            acc[4*j+2] += xv * v.z; acc[4*j+3] += xv * v.w;
        }
    }
#pragma unroll
    for (int e = 0; e < E; e++) {
#pragma unroll
        for (int off = 16; off >= 1; off >>= 1)
            acc[e] += __shfl_xor_sync(0xffffffffu, acc[e], off);
    }
    float mx = acc[0];
#pragma unroll
    for (int e = 1; e < E; e++) mx = fmaxf(mx, acc[e]);
    float p[E]; float s = 0.f;
#pragma unroll
    for (int e = 0; e < E; e++) { p[e] = __expf(acc[e] - mx); s += p[e]; }
    float inv_s = 1.f / s;
    float lse = mx + __logf(s);

    if (lane < E) atomicAdd(&s_aux[E + lane], p[lane] * inv_s);
    if (lane == 0) {
        atomicAdd(&s_aux[2 * E], lse * lse);
        float tv[H]; int ti[H]; float gsum = 0.f;
#pragma unroll
        for (int h = 0; h < H; h++) {
            float best = -1.f; int bi = 0;
#pragma unroll
            for (int e = 0; e < E; e++)
                if (p[e] > best) { best = p[e]; bi = e; }
            tv[h] = best * inv_s; ti[h] = bi; p[bi] = -2.f;
            gsum += tv[h];
            atomicAdd(&s_aux[bi], 1.0f);
            atomicAdd(&s_ecnt[bi], 1);
        }
        float ig = 1.f / gsum;
#pragma unroll
        for (int h = 0; h < H; h++) {
            g_topi[t * H + h]  = ti[h];
            g_gates[t * H + h] = tv[h] * ig;
        }
    }
    __syncthreads();
    if (tid < 2 * E + 1) atomicAdd(&g_aux[tid], s_aux[tid]);
    if (tid < E) atomicAdd(&g_ecnt[tid], s_ecnt[tid]);
}

// ---------------------------------------------------------------------------
// Kernel 2: serial scan over experts → offsets + tile table
// ---------------------------------------------------------------------------
__global__ void scan_kernel() {
    if (threadIdx.x == 0) {
        int off = 0, nt = 0;
        for (int e = 0; e < E; e++) {
            g_eoff[e] = off;
            g_ecursor[e] = 0;
            int c = g_ecnt[e];
            for (int r = 0; r < c; r += TQ) {
                g_tile_e[nt]  = e;
                g_tile_r0[nt] = off + r;
                nt++;
            }
            off += c;
        }
        g_eoff[E] = off;
        g_ntiles = nt;
    }
}

// ---------------------------------------------------------------------------
// Kernel 3: scatter slot ids into expert buckets
// ---------------------------------------------------------------------------
__global__ void scatter_kernel() {
    int i = blockIdx.x * 256 + threadIdx.x;
    int e = g_topi[i];
    int pos = atomicAdd(&g_ecursor[e], 1);
    g_slots[g_eoff[e] + pos] = i;
}

// ---------------------------------------------------------------------------
// Kernel 4: kv = x @ Wkv + bkv → K as f16 hi/lo pair-major, V as f16 transposed
// ---------------------------------------------------------------------------
__global__ __launch_bounds__(256) void kv_kernel(
    const float* __restrict__ x, const float* __restrict__ Wkv,
    const float* __restrict__ bkv)
{
    __shared__ float As[64][17];
    __shared__ float Bs[16][64];
    int tid = threadIdx.x;
    int tx = tid & 15, ty = tid >> 4;
    int t0 = blockIdx.x * 64;
    int n0 = blockIdx.y * 64;

    float acc[4][4] = {};

    for (int k0 = 0; k0 < D; k0 += 16) {
#pragma unroll
        for (int i = 0; i < 4; i++) {
            int idx = tid + i * 256;
            int r = idx >> 4, kk = idx & 15;
            As[r][kk] = x[(size_t)(t0 + r) * D + k0 + kk];
        }
#pragma unroll
        for (int i = 0; i < 4; i++) {
            int idx = tid + i * 256;
            int kr = idx >> 6, nn = idx & 63;
            Bs[kr][nn] = Wkv[(size_t)(k0 + kr) * (2 * HD) + n0 + nn];
        }
        __syncthreads();
#pragma unroll
        for (int kk = 0; kk < 16; kk++) {
            float a[4];
#pragma unroll
            for (int i = 0; i < 4; i++) a[i] = As[ty * 4 + i][kk];
            float4 bv = *reinterpret_cast<const float4*>(&Bs[kk][tx * 4]);
            float bb[4] = {bv.x, bv.y, bv.z, bv.w};
#pragma unroll
            for (int i = 0; i < 4; i++)
#pragma unroll
                for (int j = 0; j < 4; j++)
                    acc[i][j] += a[i] * bb[j];
        }
        __syncthreads();
    }

    int c0 = n0 + tx * 4;
    float vv[4][4];
#pragma unroll
    for (int i = 0; i < 4; i++)
#pragma unroll
        for (int j = 0; j < 4; j++)
            vv[i][j] = acc[i][j] + bkv[c0 + j];

    if (c0 < HD) {
        int p0 = c0 >> 1;
#pragma unroll
        for (int i = 0; i < 4; i++) {
            int t = t0 + ty * 4 + i;
            __half2 hh, ll;
            h2split(vv[i][0], vv[i][1], hh, ll);
            g_kh2[(size_t)p0 * BN_TOK + t] = hh;
            g_kl2[(size_t)p0 * BN_TOK + t] = ll;
            h2split(vv[i][2], vv[i][3], hh, ll);
            g_kh2[(size_t)(p0 + 1) * BN_TOK + t] = hh;
            g_kl2[(size_t)(p0 + 1) * BN_TOK + t] = ll;
        }
    } else {
        int tp0 = (t0 + ty * 4) >> 1;
#pragma unroll
        for (int j = 0; j < 4; j++) {
            int k = c0 + j - HD;
            g_vh2[(size_t)k * (BN_TOK / 2) + tp0]     = __floats2half2_rn(vv[0][j], vv[1][j]);
            g_vh2[(size_t)k * (BN_TOK / 2) + tp0 + 1] = __floats2half2_rn(vv[2][j], vv[3][j]);
        }
    }
}

// ---------------------------------------------------------------------------
// Kernel 5: grouped q GEMM — f16 error-compensated mma, cp.async
// double-buffered chunk pipeline. 512 threads, M=128, N=128, K=1024.
// ---------------------------------------------------------------------------
constexpr int QG_K  = 64;    // floats per k-chunk (32 pairs)
constexpr int QA_STR = 36;   // Ahi/Alo [row 128][kpair 32 + pad]  (half2)
constexpr int QB_STR = 136;  // Bhi/Blo [kpair 32][n 128 + pad]    (half2)
constexpr int QABUF = TQ * QA_STR;   // 4608
constexpr int QBBUF = 32 * QB_STR;   // 4352
constexpr int QNCH  = D / QG_K;      // 16 chunks

__global__ __launch_bounds__(512, 1) void qgemm_kernel()
{
    extern __shared__ __half2 qsm[];
    __half2* Ahi = qsm;                     // 2 * 4608
    __half2* Alo = Ahi + 2 * QABUF;         // 2 * 4608
    __half2* Bhi = Alo + 2 * QABUF;         // 2 * 4352
    __half2* Blo = Bhi + 2 * QBBUF;         // 2 * 4352
    int* s_tok  = reinterpret_cast<int*>(Blo + 2 * QBBUF);   // 128
    int* s_slot = s_tok + TQ;                                 // 128

    int t = blockIdx.x;
    if (t >= g_ntiles) return;
    int e = g_tile_e[t], r0 = g_tile_r0[t];
    int rend = g_eoff[e + 1];
    int tid = threadIdx.x;

    if (tid < TQ) {
        int gr = r0 + tid;
        if (gr >= rend) gr = r0;
        int s = g_slots[gr];
        s_slot[tid] = s;
        s_tok[tid]  = s >> 3;
    }
    __syncthreads();

    int warp = tid >> 5, lane = tid & 31;
    int g = lane >> 2, tg = lane & 3;
    int rg = warp & 7, ch = warp >> 3;
    int r_a = rg * 16 + g, r_b = r_a + 8;
    const size_t wq_base = (size_t)e * (D / 2) * HD;

    // prefetch chunk 0 into buffer 0
    {
        for (int idx = tid; idx < TQ * 8; idx += 512) {
            int r = idx >> 3, pq = (idx & 7) * 4;
            size_t src = (size_t)s_tok[r] * (D / 2) + pq;
            cp16(Ahi + r * QA_STR + pq, g_xh2 + src);
            cp16(Alo + r * QA_STR + pq, g_xl2 + src);
        }
        for (int idx = tid; idx < 32 * 32; idx += 512) {
            int p = idx >> 5, nq = (idx & 31) * 4;
            size_t src = wq_base + (size_t)p * HD + nq;
            cp16(Bhi + p * QB_STR + nq, g_wqh2 + src);
            cp16(Blo + p * QB_STR + nq, g_wql2 + src);
        }
        cp_commit();
    }

    float scc[8][4] = {};
    float scl[8][4] = {};

    for (int it = 0; it < QNCH; it++) {
        int buf = it & 1;
        cp_wait0();
        __syncthreads();

        if (it + 1 < QNCH) {
            int kp0 = (it + 1) * (QG_K / 2);
            int bn = buf ^ 1;
            __half2* AhiN = Ahi + bn * QABUF;
            __half2* AloN = Alo + bn * QABUF;
            __half2* BhiN = Bhi + bn * QBBUF;
            __half2* BloN = Blo + bn * QBBUF;
            for (int idx = tid; idx < TQ * 8; idx += 512) {
                int r = idx >> 3, pq = (idx & 7) * 4;
                size_t src = (size_t)s_tok[r] * (D / 2) + kp0 + pq;
                cp16(AhiN + r * QA_STR + pq, g_xh2 + src);
                cp16(AloN + r * QA_STR + pq, g_xl2 + src);
            }
            for (int idx = tid; idx < 32 * 32; idx += 512) {
                int p = idx >> 5, nq = (idx & 31) * 4;
                size_t src = wq_base + (size_t)(kp0 + p) * HD + nq;
                cp16(BhiN + p * QB_STR + nq, g_wqh2 + src);
                cp16(BloN + p * QB_STR + nq, g_wql2 + src);
            }
            cp_commit();
        }

        __half2* AhiB = Ahi + buf * QABUF;
        __half2* AloB = Alo + buf * QABUF;
        __half2* BhiB = Bhi + buf * QBBUF;
        __half2* BloB = Blo + buf * QBBUF;

#pragma unroll
        for (int ks = 0; ks < 4; ks++) {
            const __half2* ah0 = AhiB + r_a * QA_STR + 8 * ks + tg;
            const __half2* ah1 = AhiB + r_b * QA_STR + 8 * ks + tg;
            const __half2* al0 = AloB + r_a * QA_STR + 8 * ks + tg;
            const __half2* al1 = AloB + r_b * QA_STR + 8 * ks + tg;
            uint32_t ah[4] = { *reinterpret_cast<const uint32_t*>(ah0),
                               *reinterpret_cast<const uint32_t*>(ah1),
                               *reinterpret_cast<const uint32_t*>(ah0 + 4),
                               *reinterpret_cast<const uint32_t*>(ah1 + 4) };
            uint32_t al[4] = { *reinterpret_cast<const uint32_t*>(al0),
                               *reinterpret_cast<const uint32_t*>(al1),
                               *reinterpret_cast<const uint32_t*>(al0 + 4),
                               *reinterpret_cast<const uint32_t*>(al1 + 4) };
            const __half2* bh0 = BhiB + (8 * ks + tg) * QB_STR + ch * 64 + g;
            const __half2* bh1 = BhiB + (8 * ks + 4 + tg) * QB_STR + ch * 64 + g;
            const __half2* bl0 = BloB + (8 * ks + tg) * QB_STR + ch * 64 + g;
            const __half2* bl1 = BloB + (8 * ks + 4 + tg) * QB_STR + ch * 64 + g;
#pragma unroll
            for (int nc = 0; nc < 8; nc++) {
                uint32_t bh[2] = { *reinterpret_cast<const uint32_t*>(bh0 + 8 * nc),
                                   *reinterpret_cast<const uint32_t*>(bh1 + 8 * nc) };
                uint32_t bl[2] = { *reinterpret_cast<const uint32_t*>(bl0 + 8 * nc),
                                   *reinterpret_cast<const uint32_t*>(bl1 + 8 * nc) };
                mma_f16(scc[nc], ah, bh);
                mma_f16(scl[nc], al, bh);
                mma_f16(scl[nc], ah, bl);
            }
        }
        __syncthreads();
    }

    bool va = (r0 + r_a < rend), vb = (r0 + r_b < rend);
    float* da = g_q + (size_t)s_slot[r_a] * HD + ch * 64;
    float* db = g_q + (size_t)s_slot[r_b] * HD + ch * 64;
#pragma unroll
    for (int nc = 0; nc < 8; nc++) {
        int c = 8 * nc + 2 * tg;
        float o0 = scc[nc][0] + scl[nc][0] * LO_INV;
        float o1 = scc[nc][1] + scl[nc][1] * LO_INV;
        float o2 = scc[nc][2] + scl[nc][2] * LO_INV;
        float o3 = scc[nc][3] + scl[nc][3] * LO_INV;
        if (va) *reinterpret_cast<float2*>(da + c) = make_float2(o0, o1);
        if (vb) *reinterpret_cast<float2*>(db + c) = make_float2(o2, o3);
    }
}

// ---------------------------------------------------------------------------
// Kernel 6: flash attention — cp.async double-buffered K/V, f16-compensated QK,
// log2-domain softmax (ex2.f16x2), P kept entirely in registers (exp outputs
// ARE the PV A-fragments), f16 PV, f16 attn-out.
// ---------------------------------------------------------------------------
constexpr int QT = 128;
constexpr int KT = 64;
constexpr int QH_STR  = 68;
constexpr int KH_STR  = 72;
constexpr int VT2_STR = 36;
constexpr int KBUF = 64 * KH_STR;
constexpr int VBUF = HD * VT2_STR;

__global__ __launch_bounds__(256, 1) void attn_kernel()
{
    extern __shared__ __half2 smh[];
    __half2* Qhi  = smh;                      // 128*68
    __half2* Qlo  = Qhi  + QT * QH_STR;       // 128*68
    __half2* Khi  = Qlo  + QT * QH_STR;       // 2 * 64*72
    __half2* Klo  = Khi  + 2 * KBUF;          // 2 * 64*72
    __half2* VhT2 = Klo  + 2 * KBUF;          // 2 * 128*36

    int tid  = threadIdx.x;
    int warp = tid >> 5, lane = tid & 31;
    int g = lane >> 2, tg = lane & 3;
    int n0 = blockIdx.x * QT;
    int h  = blockIdx.y;
    int b  = blockIdx.z;
    int bN0 = b * N;
    const float qsc = 0.08838834764831845f * 1.44269504088896340736f;

    // load Q once: scale, split into f16 hi / lo*2^10
    for (int idx = tid; idx < QT * (HD / 4); idx += 256) {
        int r = idx >> 5, kq = (idx & 31) * 4;
        float4 qv = *reinterpret_cast<const float4*>(
            g_q + (((size_t)(bN0 + n0 + r)) * H + h) * HD + kq);
        qv.x *= qsc; qv.y *= qsc; qv.z *= qsc; qv.w *= qsc;
        __half2 h0, l0, h1, l1;
        h2split(qv.x, qv.y, h0, l0);
        h2split(qv.z, qv.w, h1, l1);
        int p0 = kq >> 1;
        Qhi[r * QH_STR + p0]     = h0;
        Qhi[r * QH_STR + p0 + 1] = h1;
        Qlo[r * QH_STR + p0]     = l0;
        Qlo[r * QH_STR + p0 + 1] = l1;
    }

    // prefetch tile 0 into buffer 0
    {
        for (int idx = tid; idx < 64 * 16; idx += 256) {
            int p = idx >> 4, mq = (idx & 15) * 4;
            cp16(Khi + p * KH_STR + mq, g_kh2 + (size_t)p * BN_TOK + bN0 + mq);
            cp16(Klo + p * KH_STR + mq, g_kl2 + (size_t)p * BN_TOK + bN0 + mq);
        }
        int tp0 = bN0 >> 1;
        for (int idx = tid; idx < HD * 8; idx += 256) {
            int k = idx >> 3, tq = (idx & 7) * 4;
            cp16(VhT2 + k * VT2_STR + tq, g_vh2 + (size_t)k * (BN_TOK / 2) + tp0 + tq);
        }
        cp_commit();
    }

    const int r_a = warp * 16 + g;
    const int r_b = r_a + 8;

    float o[16][4];
#pragma unroll
    for (int nc = 0; nc < 16; nc++)
#pragma unroll
        for (int j = 0; j < 4; j++) o[nc][j] = 0.f;
    float m_a = -1e30f, m_b = -1e30f, l_a = 0.f, l_b = 0.f;

    for (int it = 0; it < N / KT; it++) {
        int buf = it & 1;
        cp_wait0();
        __syncthreads();

        if (it + 1 < N / KT) {
            int m0n = (it + 1) * KT;
            int bn = buf ^ 1;
            __half2* KhiN = Khi + bn * KBUF;
            __half2* KloN = Klo + bn * KBUF;
            __half2* VN   = VhT2 + bn * VBUF;
            for (int idx = tid; idx < 64 * 16; idx += 256) {
                int p = idx >> 4, mq = (idx & 15) * 4;
                cp16(KhiN + p * KH_STR + mq, g_kh2 + (size_t)p * BN_TOK + bN0 + m0n + mq);
                cp16(KloN + p * KH_STR + mq, g_kl2 + (size_t)p * BN_TOK + bN0 + m0n + mq);
            }
            int tp0 = (bN0 + m0n) >> 1;
            for (int idx = tid; idx < HD * 8; idx += 256) {
                int k = idx >> 3, tq = (idx & 7) * 4;
                cp16(VN + k * VT2_STR + tq, g_vh2 + (size_t)k * (BN_TOK / 2) + tp0 + tq);
            }
            cp_commit();
        }

        __half2* KhiB = Khi + buf * KBUF;
        __half2* KloB = Klo + buf * KBUF;
        __half2* VB   = VhT2 + buf * VBUF;

        // ---- S = Q K^T : f16 compensated, k16 steps ----
        float scc[8][4] = {};
        float scl[8][4] = {};
#pragma unroll
        for (int ks = 0; ks < 8; ks++) {
            const __half2* qh0 = Qhi + r_a * QH_STR + 8 * ks + tg;
            const __half2* qh1 = Qhi + r_b * QH_STR + 8 * ks + tg;
            const __half2* ql0 = Qlo + r_a * QH_STR + 8 * ks + tg;
            const __half2* ql1 = Qlo + r_b * QH_STR + 8 * ks + tg;
            uint32_t ah[4] = { *reinterpret_cast<const uint32_t*>(qh0),
                               *reinterpret_cast<const uint32_t*>(qh1),
                               *reinterpret_cast<const uint32_t*>(qh0 + 4),
                               *reinterpret_cast<const uint32_t*>(qh1 + 4) };
            uint32_t al[4] = { *reinterpret_cast<const uint32_t*>(ql0),
                               *reinterpret_cast<const uint32_t*>(ql1),
                               *reinterpret_cast<const uint32_t*>(ql0 + 4),
                               *reinterpret_cast<const uint32_t*>(ql1 + 4) };
            const __half2* kh0 = KhiB + (8 * ks + tg) * KH_STR + g;
            const __half2* kh1 = KhiB + (8 * ks + 4 + tg) * KH_STR + g;
            const __half2* kl0 = KloB + (8 * ks + tg) * KH_STR + g;
            const __half2* kl1 = KloB + (8 * ks + 4 + tg) * KH_STR + g;
#pragma unroll
            for (int nc = 0; nc < 8; nc++) {
                uint32_t bh[2] = { *reinterpret_cast<const uint32_t*>(kh0 + 8 * nc),
                                   *reinterpret_cast<const uint32_t*>(kh1 + 8 * nc) };
                uint32_t bl[2] = { *reinterpret_cast<const uint32_t*>(kl0 + 8 * nc),
                                   *reinterpret_cast<const uint32_t*>(kl1 + 8 * nc) };
                mma_f16(scc[nc], ah, bh);
                mma_f16(scl[nc], al, bh);
                mma_f16(scl[nc], ah, bl);
            }
        }
#pragma unroll
        for (int nc = 0; nc < 8; nc++)
#pragma unroll
            for (int j = 0; j < 4; j++)
                scc[nc][j] += scl[nc][j] * LO_INV;

        // ---- online softmax (log2 domain, f16x2 ex2); P stays in registers ----
        float lm_a = -1e30f, lm_b = -1e30f;
#pragma unroll
        for (int nc = 0; nc < 8; nc++) {
            lm_a = fmaxf(lm_a, fmaxf(scc[nc][0], scc[nc][1]));
            lm_b = fmaxf(lm_b, fmaxf(scc[nc][2], scc[nc][3]));
        }
#pragma unroll
        for (int off = 1; off <= 2; off <<= 1) {
            lm_a = fmaxf(lm_a, __shfl_xor_sync(0xffffffffu, lm_a, off));
            lm_b = fmaxf(lm_b, __shfl_xor_sync(0xffffffffu, lm_b, off));
        }
        float mn_a = fmaxf(m_a, lm_a), mn_b = fmaxf(m_b, lm_b);
        float al_a = exp2f(m_a - mn_a), al_b = exp2f(m_b - mn_b);
        m_a = mn_a; m_b = mn_b;

        uint32_t pha[8], phb[8];
        float rs_a = 0.f, rs_b = 0.f;
#pragma unroll
        for (int nc = 0; nc < 8; nc++) {
            __half2 ha = h2exp2(__floats2half2_rn(scc[nc][0] - mn_a, scc[nc][1] - mn_a));
            __half2 hb = h2exp2(__floats2half2_rn(scc[nc][2] - mn_b, scc[nc][3] - mn_b));
            pha[nc] = *reinterpret_cast<uint32_t*>(&ha);
            phb[nc] = *reinterpret_cast<uint32_t*>(&hb);
            float2 fa = __half22float2(ha);
            float2 fb = __half22float2(hb);
            rs_a += fa.x + fa.y;
            rs_b += fb.x + fb.y;
        }
#pragma unroll
        for (int off = 1; off <= 2; off <<= 1) {
            rs_a += __shfl_xor_sync(0xffffffffu, rs_a, off);
            rs_b += __shfl_xor_sync(0xffffffffu, rs_b, off);
        }
        l_a = l_a * al_a + rs_a;
        l_b = l_b * al_b + rs_b;
#pragma unroll
        for (int nc = 0; nc < 16; nc++) {
            o[nc][0] *= al_a; o[nc][1] *= al_a;
            o[nc][2] *= al_b; o[nc][3] *= al_b;
        }

        // ---- O += P V : A-fragments come straight from registers ----
#pragma unroll
        for (int ks = 0; ks < 4; ks++) {
            uint32_t a[4] = { pha[2 * ks], phb[2 * ks], pha[2 * ks + 1], phb[2 * ks + 1] };
#pragma unroll
            for (int nc = 0; nc < 16; nc++) {
                const __half2* vb = VB + (8 * nc + g) * VT2_STR + 8 * ks + tg;
                uint32_t bb[2];
                bb[0] = *reinterpret_cast<const uint32_t*>(vb);
                bb[1] = *reinterpret_cast<const uint32_t*>(vb + 4);
                mma_f16(o[nc], a, bb);
            }
        }
    }

    float inv_a = 1.f / l_a, inv_b = 1.f / l_b;
    __half2* dsta = g_attno2 + (((size_t)(bN0 + n0 + r_a)) * H + h) * (HD / 2);
    __half2* dstb = g_attno2 + (((size_t)(bN0 + n0 + r_b)) * H + h) * (HD / 2);
#pragma unroll
    for (int nc = 0; nc < 16; nc++) {
        int p = 4 * nc + tg;
        dsta[p] = __floats2half2_rn(o[nc][0] * inv_a, o[nc][1] * inv_a);
        dstb[p] = __floats2half2_rn(o[nc][2] * inv_b, o[nc][3] * inv_b);
    }
}

// ---------------------------------------------------------------------------
// Kernel 7: grouped combine GEMM — single-pass f16, cp.async loads,
// f16 output scratch.
// ---------------------------------------------------------------------------
constexpr int CA_STR = 68;
constexpr int CB_STR = 136;

__global__ __launch_bounds__(256, 2) void cgemm_kernel()
{
    extern __shared__ __half2 csm[];
    __half2* A2 = csm;                  // 128*68
    __half2* B2 = A2 + TQ * CA_STR;     // 64*136
    int*   s_slot = reinterpret_cast<int*>(B2 + 64 * CB_STR);
    float* s_gate = reinterpret_cast<float*>(s_slot + TQ);

    int t = blockIdx.x;
    if (t >= g_ntiles) return;
    int n0 = blockIdx.y * 128;
    int e = g_tile_e[t], r0 = g_tile_r0[t];
    int rend = g_eoff[e + 1];
    int tid = threadIdx.x;

    if (tid < TQ) {
        int gr = r0 + tid;
        if (gr >= rend) gr = r0;
        int s = g_slots[gr];
        s_slot[tid] = s;
        s_gate[tid] = g_gates[s];
    }
    __syncthreads();

    // A: cp.async copies from f16 attn-out
    for (int idx = tid; idx < TQ * 16; idx += 256) {
        int r = idx >> 4, pq = (idx & 15) * 4;
        cp16(A2 + r * CA_STR + pq, g_attno2 + (size_t)s_slot[r] * (HD / 2) + pq);
    }
    // B: cp.async copies from pre-converted Wo
    for (int idx = tid; idx < 64 * 32; idx += 256) {
        int p = idx >> 5, nq = (idx & 31) * 4;
        cp16(B2 + p * CB_STR + nq, g_woh2 + ((size_t)e * (HD / 2) + p) * D + n0 + nq);
    }
    cp_commit();
    cp_wait0();
    __syncthreads();

    int warp = tid >> 5, lane = tid & 31;
    int g = lane >> 2, tg = lane & 3;
    int r_a = warp * 16 + g, r_b = r_a + 8;

    float acc[16][4] = {};

#pragma unroll
    for (int ks = 0; ks < 8; ks++) {
        const __half2* a0 = A2 + r_a * CA_STR + 8 * ks + tg;
        const __half2* a1 = A2 + r_b * CA_STR + 8 * ks + tg;
        uint32_t a[4] = { *reinterpret_cast<const uint32_t*>(a0),
                          *reinterpret_cast<const uint32_t*>(a1),
                          *reinterpret_cast<const uint32_t*>(a0 + 4),
                          *reinterpret_cast<const uint32_t*>(a1 + 4) };
        const __half2* b0 = B2 + (8 * ks + tg) * CB_STR + g;
        const __half2* b1 = B2 + (8 * ks + 4 + tg) * CB_STR + g;
#pragma unroll
        for (int nc = 0; nc < 16; nc++) {
            uint32_t bb[2] = { *reinterpret_cast<const uint32_t*>(b0 + 8 * nc),
                               *reinterpret_cast<const uint32_t*>(b1 + 8 * nc) };
            mma_f16(acc[nc], a, bb);
        }
    }

    bool va = (r0 + r_a < rend), vb = (r0 + r_b < rend);
    float ga = s_gate[r_a], gb = s_gate[r_b];
    __half2* da = g_ws2 + (size_t)s_slot[r_a] * (D / 2) + (n0 >> 1);
    __half2* db = g_ws2 + (size_t)s_slot[r_b] * (D / 2) + (n0 >> 1);
#pragma unroll
    for (int nc = 0; nc < 16; nc++) {
        int p = 4 * nc + tg;
        if (va) da[p] = __floats2half2_rn(acc[nc][0] * ga, acc[nc][1] * ga);
        if (vb) db[p] = __floats2half2_rn(acc[nc][2] * gb, acc[nc][3] * gb);
    }
}

// ---------------------------------------------------------------------------
// Kernel 8: reduce 8 slot rows per token → y  (f16 in, f32 out)
// ---------------------------------------------------------------------------
__global__ __launch_bounds__(256) void reduce_kernel(float* __restrict__ y)
{
    int t = blockIdx.x;
    int p = threadIdx.x * 2;
    float4 s = make_float4(0.f, 0.f, 0.f, 0.f);
#pragma unroll
    for (int h = 0; h < H; h++) {
        const __half2* w = g_ws2 + ((size_t)(t * H + h)) * (D / 2) + p;
        float2 a = __half22float2(w[0]);
        float2 b2 = __half22float2(w[1]);
        s.x += a.x; s.y += a.y; s.z += b2.x; s.w += b2.y;
    }
    *reinterpret_cast<float4*>(y + (size_t)t * D + p * 2) = s;
}

// ---------------------------------------------------------------------------
// Kernel 9: finalize aux loss
// ---------------------------------------------------------------------------
__global__ void aux_final_kernel(float* __restrict__ out) {
    if (threadIdx.x == 0) {
        const float inv_bn = 1.0f / (float)BN_TOK;
        float sw = 0.f;
        for (int e = 0; e < E; e++)
            sw += (g_aux[e] * inv_bn) * (g_aux[E + e] * inv_bn);
        float aux = 0.1f * (float)E * sw + 0.001f * (g_aux[2 * E] * inv_bn);
        out[(size_t)BN_TOK * D] = aux;
    }
}

// ---------------------------------------------------------------------------
// Launch
// ---------------------------------------------------------------------------
extern "C" void kernel_launch(void* const* d_in, const int* in_sizes, int n_in,
                              void* d_out, int out_size)
{
    const float* x    = (const float*)d_in[0];
    const int* task_bh = (const int*)d_in[1];
    const float* Wg   = (const float*)d_in[2];
    const float* Wq   = (const float*)d_in[3];
    const float* Wo   = (const float*)d_in[4];
    const float* Wkv  = (const float*)d_in[5];
    const float* bkv  = (const float*)d_in[6];
    float* out = (float*)d_out;

    const int attn_smem = (2 * QT * QH_STR + 4 * KBUF + 2 * VBUF) * 4;
    const int qg_smem = (4 * QABUF + 4 * QBBUF) * 4 + 2 * TQ * 4;
    const int cg_smem = (TQ * CA_STR + 64 * CB_STR) * 4 + 2 * TQ * 4;
    const int gate_smem = D * E * 4;
    cudaFuncSetAttribute(attn_kernel,   cudaFuncAttributeMaxDynamicSharedMemorySize, attn_smem);
    cudaFuncSetAttribute(qgemm_kernel,  cudaFuncAttributeMaxDynamicSharedMemorySize, qg_smem);
    cudaFuncSetAttribute(cgemm_kernel,  cudaFuncAttributeMaxDynamicSharedMemorySize, cg_smem);
    cudaFuncSetAttribute(gating_kernel, cudaFuncAttributeMaxDynamicSharedMemorySize, gate_smem);

    init_aux_kernel<<<1, 64>>>();
    xsplit_kernel<<<BN_TOK, 256>>>(x);
    wqsplit_kernel<<<dim3(D / 2, E), 128>>>(Wq);
    wosplit_kernel<<<dim3(HD / 2, E), 256>>>(Wo);
    gating_kernel<<<BN_TOK / 8, 256, gate_smem>>>(x, task_bh, Wg);
    scan_kernel<<<1, 32>>>();
    scatter_kernel<<<NSLOT / 256, 256>>>();
    kv_kernel<<<dim3(BN_TOK / 64, (2 * HD) / 64), 256>>>(x, Wkv, bkv);
    qgemm_kernel<<<NT_MAX, 512, qg_smem>>>();
    attn_kernel<<<dim3(N / QT, H, B), 256, attn_smem>>>();
    cgemm_kernel<<<dim3(NT_MAX, 8), 256, cg_smem>>>();
    reduce_kernel<<<BN_TOK, 256>>>(out);
    aux_final_kernel<<<1, 32>>>(out);
}

// round 15
// speedup vs baseline: 2.4290x; 1.1262x over previous
#include <cuda_runtime.h>
#include <cuda_fp16.h>
#include <math.h>
#include <stdint.h>

// ---------------------------------------------------------------------------
// Problem constants
// ---------------------------------------------------------------------------
constexpr int B    = 4;
constexpr int N    = 2048;
constexpr int D    = 1024;
constexpr int E    = 24;
constexpr int H    = 8;
constexpr int HD   = 128;
constexpr int BN_TOK = B * N;          // 8192 tokens
constexpr int NSLOT  = BN_TOK * H;     // 65536 (token,slot) pairs

// Grouped-GEMM tiling
constexpr int TQ = 128;                // rows per expert tile
constexpr int NT_MAX = NSLOT / TQ + E; // 536 max tiles

// ---------------------------------------------------------------------------
// Scratch (device globals — no allocations allowed)
// ---------------------------------------------------------------------------
__device__ __half2 g_kh2[(HD / 2) * BN_TOK];   // 2 MB  K hi,  pair-major [hd-pair][token]
__device__ __half2 g_kl2[(HD / 2) * BN_TOK];   // 2 MB  K lo*2^10
__device__ __half2 g_vh2[HD * (BN_TOK / 2)];   // 2 MB  V f16 transposed [hd][token-pair]
__device__ __half2 g_qh2[NSLOT * (HD / 2)];    // 16 MB Q hi (pre-scaled) [slot][pair]
__device__ __half2 g_ql2[NSLOT * (HD / 2)];    // 16 MB Q lo*2^10
__device__ __half2 g_attno2[NSLOT * (HD / 2)]; // 16 MB attn out f16 [slot][hd-pair]
__device__ __half2 g_ws2[(size_t)NSLOT * (D / 2)]; // 134 MB combine scratch f16 [slot][pair]
// pre-split inputs (convert-once)
__device__ __half2 g_xh2[BN_TOK * (D / 2)];    // 16 MB x hi [token][pair]
__device__ __half2 g_xl2[BN_TOK * (D / 2)];    // 16 MB x lo*2^10
__device__ __half2 g_wqh2[(size_t)E * (D / 2) * HD];  // 6.3 MB Wq hi [e][kpair][n]
__device__ __half2 g_wql2[(size_t)E * (D / 2) * HD];  // 6.3 MB Wq lo*2^10
__device__ __half2 g_woh2[(size_t)E * (HD / 2) * D];  // 6.3 MB Wo f16 [e][kpair][n]
__device__ __half2 g_wkvh2[(D / 2) * (2 * HD)];       // 0.5 MB Wkv hi [kpair][n]
__device__ __half2 g_wkvl2[(D / 2) * (2 * HD)];       // 0.5 MB Wkv lo*2^10
__device__ int   g_topi[NSLOT];
__device__ float g_gates[NSLOT];
__device__ float g_aux[2 * E + 1];
// expert bucketing
__device__ int g_ecnt[E];
__device__ int g_eoff[E + 1];
__device__ int g_ecursor[E];
__device__ int g_slots[NSLOT];
__device__ int g_tile_e[NT_MAX];
__device__ int g_tile_r0[NT_MAX];
__device__ int g_ntiles;

// ---------------------------------------------------------------------------
// helpers
// ---------------------------------------------------------------------------
__device__ __forceinline__ void mma_f16(float* d, const uint32_t* a, const uint32_t* b) {
    asm volatile(
        "mma.sync.aligned.m16n8k16.row.col.f32.f16.f16.f32 "
        "{%0,%1,%2,%3}, {%4,%5,%6,%7}, {%8,%9}, {%0,%1,%2,%3};\n"
        : "+f"(d[0]), "+f"(d[1]), "+f"(d[2]), "+f"(d[3])
        : "r"(a[0]), "r"(a[1]), "r"(a[2]), "r"(a[3]), "r"(b[0]), "r"(b[1]));
}
__device__ __forceinline__ void h2split(float x, float y, __half2& hi, __half2& lo) {
    hi = __floats2half2_rn(x, y);
    float2 hf = __half22float2(hi);
    lo = __floats2half2_rn((x - hf.x) * 1024.f, (y - hf.y) * 1024.f);
}
constexpr float LO_INV = 1.f / 1024.f;
constexpr float QSC = 0.08838834764831845f * 1.44269504088896340736f; // scale*log2e

__device__ __forceinline__ void cp16(void* smem, const void* gmem) {
    uint32_t s = (uint32_t)__cvta_generic_to_shared(smem);
    asm volatile("cp.async.cg.shared.global [%0], [%1], 16;\n" :: "r"(s), "l"(gmem));
}
__device__ __forceinline__ void cp_commit() {
    asm volatile("cp.async.commit_group;\n");
}
__device__ __forceinline__ void cp_wait0() {
    asm volatile("cp.async.wait_group 0;\n" ::: "memory");
}

// ---------------------------------------------------------------------------
// Kernel 0: zero aux + expert histogram
// ---------------------------------------------------------------------------
__global__ void init_aux_kernel() {
    int tid = threadIdx.x;
    if (tid < 2 * E + 1) g_aux[tid] = 0.f;
    if (tid < E) g_ecnt[tid] = 0;
}

// ---------------------------------------------------------------------------
// Pre-split kernels (convert-once)
// ---------------------------------------------------------------------------
__global__ __launch_bounds__(256) void xsplit_kernel(const float* __restrict__ x) {
    int t = blockIdx.x;
    int c = threadIdx.x * 4;
    float4 v = *reinterpret_cast<const float4*>(x + (size_t)t * D + c);
    __half2 h0, l0, h1, l1;
    h2split(v.x, v.y, h0, l0);
    h2split(v.z, v.w, h1, l1);
    int p = c >> 1;
    g_xh2[(size_t)t * (D / 2) + p]     = h0;
    g_xh2[(size_t)t * (D / 2) + p + 1] = h1;
    g_xl2[(size_t)t * (D / 2) + p]     = l0;
    g_xl2[(size_t)t * (D / 2) + p + 1] = l1;
}

__global__ __launch_bounds__(128) void wqsplit_kernel(const float* __restrict__ Wq) {
    int p = blockIdx.x;      // kpair 0..511
    int e = blockIdx.y;
    int n = threadIdx.x;     // 0..127
    const float* w = Wq + (size_t)e * D * HD;
    float a = w[(size_t)(2 * p) * HD + n];
    float b2 = w[(size_t)(2 * p + 1) * HD + n];
    __half2 hh, ll;
    h2split(a, b2, hh, ll);
    size_t o = ((size_t)e * (D / 2) + p) * HD + n;
    g_wqh2[o] = hh;
    g_wql2[o] = ll;
}

__global__ __launch_bounds__(256) void wosplit_kernel(const float* __restrict__ Wo) {
    int p = blockIdx.x;      // kpair 0..63
    int e = blockIdx.y;
    const float* w = Wo + (size_t)e * HD * D;
    for (int n = threadIdx.x; n < D; n += 256) {
        g_woh2[((size_t)e * (HD / 2) + p) * D + n] =
            __floats2half2_rn(w[(size_t)(2 * p) * D + n], w[(size_t)(2 * p + 1) * D + n]);
    }
}

__global__ __launch_bounds__(256) void wkvsplit_kernel(const float* __restrict__ Wkv) {
    int p = blockIdx.x;      // kpair 0..511
    int n = threadIdx.x;     // 0..255
    float a = Wkv[(size_t)(2 * p) * (2 * HD) + n];
    float b2 = Wkv[(size_t)(2 * p + 1) * (2 * HD) + n];
    __half2 hh, ll;
    h2split(a, b2, hh, ll);
    g_wkvh2[(size_t)p * (2 * HD) + n] = hh;
    g_wkvl2[(size_t)p * (2 * HD) + n] = ll;
}

// ---------------------------------------------------------------------------
// Kernel 1: gating — Wg[task] cached in smem
// ---------------------------------------------------------------------------
__global__ __launch_bounds__(256) void gating_kernel(
    const float* __restrict__ x, const int* __restrict__ task_bh,
    const float* __restrict__ Wg)
{
    extern __shared__ float s_wg[];            // D * E floats = 96 KB
    __shared__ float s_aux[2 * E + 1];
    __shared__ int   s_ecnt[E];
    int tid = threadIdx.x;
    if (tid < 2 * E + 1) s_aux[tid] = 0.f;
    if (tid < E) s_ecnt[tid] = 0;

    int warp = tid >> 5, lane = tid & 31;
    int t = blockIdx.x * 8 + warp;
    int b = t >> 11;
    int task = task_bh[b];
    const float* wg = Wg + (size_t)task * D * E;

    for (int idx = tid; idx < D * E / 4; idx += 256) {
        reinterpret_cast<float4*>(s_wg)[idx] =
            reinterpret_cast<const float4*>(wg)[idx];
    }
    __syncthreads();

    const float* xrow = x + (size_t)t * D;

    float acc[E];
#pragma unroll
    for (int e = 0; e < E; e++) acc[e] = 0.f;

    for (int i = lane; i < D; i += 32) {
        float xv = xrow[i];
        const float4* w4 = reinterpret_cast<const float4*>(s_wg + (size_t)i * E);
#pragma unroll
        for (int j = 0; j < 6; j++) {
            float4 v = w4[j];
            acc[4*j+0] += xv * v.x; acc[4*j+1] += xv * v.y;
            acc[4*j+2] += xv * v.z; acc[4*j+3] += xv * v.w;
        }
    }
#pragma unroll
    for (int e = 0; e < E; e++) {
#pragma unroll
        for (int off = 16; off >= 1; off >>= 1)
            acc[e] += __shfl_xor_sync(0xffffffffu, acc[e], off);
    }
    float mx = acc[0];
#pragma unroll
    for (int e = 1; e < E; e++) mx = fmaxf(mx, acc[e]);
    float p[E]; float s = 0.f;
#pragma unroll
    for (int e = 0; e < E; e++) { p[e] = __expf(acc[e] - mx); s += p[e]; }
    float inv_s = 1.f / s;
    float lse = mx + __logf(s);

    if (lane < E) atomicAdd(&s_aux[E + lane], p[lane] * inv_s);
    if (lane == 0) {
        atomicAdd(&s_aux[2 * E], lse * lse);
        float tv[H]; int ti[H]; float gsum = 0.f;
#pragma unroll
        for (int h = 0; h < H; h++) {
            float best = -1.f; int bi = 0;
#pragma unroll
            for (int e = 0; e < E; e++)
                if (p[e] > best) { best = p[e]; bi = e; }
            tv[h] = best * inv_s; ti[h] = bi; p[bi] = -2.f;
            gsum += tv[h];
            atomicAdd(&s_aux[bi], 1.0f);
            atomicAdd(&s_ecnt[bi], 1);
        }
        float ig = 1.f / gsum;
#pragma unroll
        for (int h = 0; h < H; h++) {
            g_topi[t * H + h]  = ti[h];
            g_gates[t * H + h] = tv[h] * ig;
        }
    }
    __syncthreads();
    if (tid < 2 * E + 1) atomicAdd(&g_aux[tid], s_aux[tid]);
    if (tid < E) atomicAdd(&g_ecnt[tid], s_ecnt[tid]);
}

// ---------------------------------------------------------------------------
// Kernel 2: serial scan over experts → offsets + tile table
// ---------------------------------------------------------------------------
__global__ void scan_kernel() {
    if (threadIdx.x == 0) {
        int off = 0, nt = 0;
        for (int e = 0; e < E; e++) {
            g_eoff[e] = off;
            g_ecursor[e] = 0;
            int c = g_ecnt[e];
            for (int r = 0; r < c; r += TQ) {
                g_tile_e[nt]  = e;
                g_tile_r0[nt] = off + r;
                nt++;
            }
            off += c;
        }
        g_eoff[E] = off;
        g_ntiles = nt;
    }
}

// ---------------------------------------------------------------------------
// Kernel 3: scatter slot ids into expert buckets
// ---------------------------------------------------------------------------
__global__ void scatter_kernel() {
    int i = blockIdx.x * 256 + threadIdx.x;
    int e = g_topi[i];
    int pos = atomicAdd(&g_ecursor[e], 1);
    g_slots[g_eoff[e] + pos] = i;
}

// ---------------------------------------------------------------------------
// Shared tiling constants for f16-compensated GEMM pipelines
// ---------------------------------------------------------------------------
constexpr int QG_K  = 64;    // floats per k-chunk (32 pairs)
constexpr int QA_STR = 36;   // Ahi/Alo [row 128][kpair 32 + pad]  (half2)
constexpr int QB_STR = 136;  // Bhi/Blo [kpair 32][n 128 + pad]    (half2)
constexpr int QABUF = TQ * QA_STR;   // 4608
constexpr int QBBUF = 32 * QB_STR;   // 4352
constexpr int QNCH  = D / QG_K;      // 16 chunks

// ---------------------------------------------------------------------------
// Kernel 4: kv = x @ Wkv + bkv — f16-compensated tensor GEMM (qgemm clone).
// grid (64, 2): y=0 → K cols (writes hi/lo pair-major), y=1 → V cols
// (stages in smem, writes f16 transposed).
// ---------------------------------------------------------------------------
__global__ __launch_bounds__(512, 1) void kvmma_kernel(const float* __restrict__ bkv)
{
    extern __shared__ __half2 qsm[];
    __half2* Ahi = qsm;
    __half2* Alo = Ahi + 2 * QABUF;
    __half2* Bhi = Alo + 2 * QABUF;
    __half2* Blo = Bhi + 2 * QBBUF;

    int tid = threadIdx.x;
    int t0 = blockIdx.x * TQ;          // token base
    int colbase = blockIdx.y * 128;    // 0 = K, 128 = V

    int warp = tid >> 5, lane = tid & 31;
    int g = lane >> 2, tg = lane & 3;
    int rg = warp & 7, ch = warp >> 3;
    int r_a = rg * 16 + g, r_b = r_a + 8;

    // prefetch chunk 0
    {
        for (int idx = tid; idx < TQ * 8; idx += 512) {
            int r = idx >> 3, pq = (idx & 7) * 4;
            size_t src = (size_t)(t0 + r) * (D / 2) + pq;
            cp16(Ahi + r * QA_STR + pq, g_xh2 + src);
            cp16(Alo + r * QA_STR + pq, g_xl2 + src);
        }
        for (int idx = tid; idx < 32 * 32; idx += 512) {
            int p = idx >> 5, nq = (idx & 31) * 4;
            size_t src = (size_t)p * (2 * HD) + colbase + nq;
            cp16(Bhi + p * QB_STR + nq, g_wkvh2 + src);
            cp16(Blo + p * QB_STR + nq, g_wkvl2 + src);
        }
        cp_commit();
    }

    float scc[8][4] = {};
    float scl[8][4] = {};

    for (int it = 0; it < QNCH; it++) {
        int buf = it & 1;
        cp_wait0();
        __syncthreads();

        if (it + 1 < QNCH) {
            int kp0 = (it + 1) * (QG_K / 2);
            int bn = buf ^ 1;
            __half2* AhiN = Ahi + bn * QABUF;
            __half2* AloN = Alo + bn * QABUF;
            __half2* BhiN = Bhi + bn * QBBUF;
            __half2* BloN = Blo + bn * QBBUF;
            for (int idx = tid; idx < TQ * 8; idx += 512) {
                int r = idx >> 3, pq = (idx & 7) * 4;
                size_t src = (size_t)(t0 + r) * (D / 2) + kp0 + pq;
                cp16(AhiN + r * QA_STR + pq, g_xh2 + src);
                cp16(AloN + r * QA_STR + pq, g_xl2 + src);
            }
            for (int idx = tid; idx < 32 * 32; idx += 512) {
                int p = idx >> 5, nq = (idx & 31) * 4;
                size_t src = (size_t)(kp0 + p) * (2 * HD) + colbase + nq;
                cp16(BhiN + p * QB_STR + nq, g_wkvh2 + src);
                cp16(BloN + p * QB_STR + nq, g_wkvl2 + src);
            }
            cp_commit();
        }

        __half2* AhiB = Ahi + buf * QABUF;
        __half2* AloB = Alo + buf * QABUF;
        __half2* BhiB = Bhi + buf * QBBUF;
        __half2* BloB = Blo + buf * QBBUF;

#pragma unroll
        for (int ks = 0; ks < 4; ks++) {
            const __half2* ah0 = AhiB + r_a * QA_STR + 8 * ks + tg;
            const __half2* ah1 = AhiB + r_b * QA_STR + 8 * ks + tg;
            const __half2* al0 = AloB + r_a * QA_STR + 8 * ks + tg;
            const __half2* al1 = AloB + r_b * QA_STR + 8 * ks + tg;
            uint32_t ah[4] = { *reinterpret_cast<const uint32_t*>(ah0),
                               *reinterpret_cast<const uint32_t*>(ah1),
                               *reinterpret_cast<const uint32_t*>(ah0 + 4),
                               *reinterpret_cast<const uint32_t*>(ah1 + 4) };
            uint32_t al[4] = { *reinterpret_cast<const uint32_t*>(al0),
                               *reinterpret_cast<const uint32_t*>(al1),
                               *reinterpret_cast<const uint32_t*>(al0 + 4),
                               *reinterpret_cast<const uint32_t*>(al1 + 4) };
            const __half2* bh0 = BhiB + (8 * ks + tg) * QB_STR + ch * 64 + g;
            const __half2* bh1 = BhiB + (8 * ks + 4 + tg) * QB_STR + ch * 64 + g;
            const __half2* bl0 = BloB + (8 * ks + tg) * QB_STR + ch * 64 + g;
            const __half2* bl1 = BloB + (8 * ks + 4 + tg) * QB_STR + ch * 64 + g;
#pragma unroll
            for (int nc = 0; nc < 8; nc++) {
                uint32_t bh[2] = { *reinterpret_cast<const uint32_t*>(bh0 + 8 * nc),
                                   *reinterpret_cast<const uint32_t*>(bh1 + 8 * nc) };
                uint32_t bl[2] = { *reinterpret_cast<const uint32_t*>(bl0 + 8 * nc),
                                   *reinterpret_cast<const uint32_t*>(bl1 + 8 * nc) };
                mma_f16(scc[nc], ah, bh);
                mma_f16(scl[nc], al, bh);
                mma_f16(scl[nc], ah, bl);
            }
        }
        __syncthreads();
    }

    if (colbase == 0) {
        // K epilogue: hi/lo pair-major [hd-pair][token]
#pragma unroll
        for (int nc = 0; nc < 8; nc++) {
            int c = ch * 64 + 8 * nc + 2 * tg;       // local col = hd
            float b0 = bkv[c], b1 = bkv[c + 1];
            float v0 = scc[nc][0] + scl[nc][0] * LO_INV + b0;
            float v1 = scc[nc][1] + scl[nc][1] * LO_INV + b1;
            float v2 = scc[nc][2] + scl[nc][2] * LO_INV + b0;
            float v3 = scc[nc][3] + scl[nc][3] * LO_INV + b1;
            int p = c >> 1;
            __half2 hh, ll;
            h2split(v0, v1, hh, ll);
            g_kh2[(size_t)p * BN_TOK + t0 + r_a] = hh;
            g_kl2[(size_t)p * BN_TOK + t0 + r_a] = ll;
            h2split(v2, v3, hh, ll);
            g_kh2[(size_t)p * BN_TOK + t0 + r_b] = hh;
            g_kl2[(size_t)p * BN_TOK + t0 + r_b] = ll;
        }
    } else {
        // V epilogue: stage f16 [token][hd] in smem, then transposed write
        __half* Vs = reinterpret_cast<__half*>(qsm);   // [128][130] halves
        __syncthreads();   // pipeline buffers fully consumed
#pragma unroll
        for (int nc = 0; nc < 8; nc++) {
            int c = ch * 64 + 8 * nc + 2 * tg;       // local col = hd
            float b0 = bkv[128 + c], b1 = bkv[128 + c + 1];
            float v0 = scc[nc][0] + scl[nc][0] * LO_INV + b0;
            float v1 = scc[nc][1] + scl[nc][1] * LO_INV + b1;
            float v2 = scc[nc][2] + scl[nc][2] * LO_INV + b0;
            float v3 = scc[nc][3] + scl[nc][3] * LO_INV + b1;
            Vs[r_a * 130 + c]     = __float2half_rn(v0);
            Vs[r_a * 130 + c + 1] = __float2half_rn(v1);
            Vs[r_b * 130 + c]     = __float2half_rn(v2);
            Vs[r_b * 130 + c + 1] = __float2half_rn(v3);
        }
        __syncthreads();
        int tpbase = t0 >> 1;
        for (int idx = tid; idx < HD * 64; idx += 512) {
            int tp = idx & 63, k = idx >> 6;
            __half2 val = __halves2half2(Vs[(2 * tp) * 130 + k], Vs[(2 * tp + 1) * 130 + k]);
            g_vh2[(size_t)k * (BN_TOK / 2) + tpbase + tp] = val;
        }
    }
}

// ---------------------------------------------------------------------------
// Kernel 5: grouped q GEMM — f16 error-compensated mma, cp.async pipeline;
// epilogue applies attention scale and writes pre-split Q hi/lo.
// ---------------------------------------------------------------------------
__global__ __launch_bounds__(512, 1) void qgemm_kernel()
{
    extern __shared__ __half2 qsm[];
    __half2* Ahi = qsm;
    __half2* Alo = Ahi + 2 * QABUF;
    __half2* Bhi = Alo + 2 * QABUF;
    __half2* Blo = Bhi + 2 * QBBUF;
    int* s_tok  = reinterpret_cast<int*>(Blo + 2 * QBBUF);
    int* s_slot = s_tok + TQ;

    int t = blockIdx.x;
    if (t >= g_ntiles) return;
    int e = g_tile_e[t], r0 = g_tile_r0[t];
    int rend = g_eoff[e + 1];
    int tid = threadIdx.x;

    if (tid < TQ) {
        int gr = r0 + tid;
        if (gr >= rend) gr = r0;
        int s = g_slots[gr];
        s_slot[tid] = s;
        s_tok[tid]  = s >> 3;
    }
    __syncthreads();

    int warp = tid >> 5, lane = tid & 31;
    int g = lane >> 2, tg = lane & 3;
    int rg = warp & 7, ch = warp >> 3;
    int r_a = rg * 16 + g, r_b = r_a + 8;
    const size_t wq_base = (size_t)e * (D / 2) * HD;

    {
        for (int idx = tid; idx < TQ * 8; idx += 512) {
            int r = idx >> 3, pq = (idx & 7) * 4;
            size_t src = (size_t)s_tok[r] * (D / 2) + pq;
            cp16(Ahi + r * QA_STR + pq, g_xh2 + src);
            cp16(Alo + r * QA_STR + pq, g_xl2 + src);
        }
        for (int idx = tid; idx < 32 * 32; idx += 512) {
            int p = idx >> 5, nq = (idx & 31) * 4;
            size_t src = wq_base + (size_t)p * HD + nq;
            cp16(Bhi + p * QB_STR + nq, g_wqh2 + src);
            cp16(Blo + p * QB_STR + nq, g_wql2 + src);
        }
        cp_commit();
    }

    float scc[8][4] = {};
    float scl[8][4] = {};

    for (int it = 0; it < QNCH; it++) {
        int buf = it & 1;
        cp_wait0();
        __syncthreads();

        if (it + 1 < QNCH) {
            int kp0 = (it + 1) * (QG_K / 2);
            int bn = buf ^ 1;
            __half2* AhiN = Ahi + bn * QABUF;
            __half2* AloN = Alo + bn * QABUF;
            __half2* BhiN = Bhi + bn * QBBUF;
            __half2* BloN = Blo + bn * QBBUF;
            for (int idx = tid; idx < TQ * 8; idx += 512) {
                int r = idx >> 3, pq = (idx & 7) * 4;
                size_t src = (size_t)s_tok[r] * (D / 2) + kp0 + pq;
                cp16(AhiN + r * QA_STR + pq, g_xh2 + src);
                cp16(AloN + r * QA_STR + pq, g_xl2 + src);
            }
            for (int idx = tid; idx < 32 * 32; idx += 512) {
                int p = idx >> 5, nq = (idx & 31) * 4;
                size_t src = wq_base + (size_t)(kp0 + p) * HD + nq;
                cp16(BhiN + p * QB_STR + nq, g_wqh2 + src);
                cp16(BloN + p * QB_STR + nq, g_wql2 + src);
            }
            cp_commit();
        }

        __half2* AhiB = Ahi + buf * QABUF;
        __half2* AloB = Alo + buf * QABUF;
        __half2* BhiB = Bhi + buf * QBBUF;
        __half2* BloB = Blo + buf * QBBUF;

#pragma unroll
        for (int ks = 0; ks < 4; ks++) {
            const __half2* ah0 = AhiB + r_a * QA_STR + 8 * ks + tg;
            const __half2* ah1 = AhiB + r_b * QA_STR + 8 * ks + tg;
            const __half2* al0 = AloB + r_a * QA_STR + 8 * ks + tg;
            const __half2* al1 = AloB + r_b * QA_STR + 8 * ks + tg;
            uint32_t ah[4] = { *reinterpret_cast<const uint32_t*>(ah0),
                               *reinterpret_cast<const uint32_t*>(ah1),
                               *reinterpret_cast<const uint32_t*>(ah0 + 4),
                               *reinterpret_cast<const uint32_t*>(ah1 + 4) };
            uint32_t al[4] = { *reinterpret_cast<const uint32_t*>(al0),
                               *reinterpret_cast<const uint32_t*>(al1),
                               *reinterpret_cast<const uint32_t*>(al0 + 4),
                               *reinterpret_cast<const uint32_t*>(al1 + 4) };
            const __half2* bh0 = BhiB + (8 * ks + tg) * QB_STR + ch * 64 + g;
            const __half2* bh1 = BhiB + (8 * ks + 4 + tg) * QB_STR + ch * 64 + g;
            const __half2* bl0 = BloB + (8 * ks + tg) * QB_STR + ch * 64 + g;
            const __half2* bl1 = BloB + (8 * ks + 4 + tg) * QB_STR + ch * 64 + g;
#pragma unroll
            for (int nc = 0; nc < 8; nc++) {
                uint32_t bh[2] = { *reinterpret_cast<const uint32_t*>(bh0 + 8 * nc),
                                   *reinterpret_cast<const uint32_t*>(bh1 + 8 * nc) };
                uint32_t bl[2] = { *reinterpret_cast<const uint32_t*>(bl0 + 8 * nc),
                                   *reinterpret_cast<const uint32_t*>(bl1 + 8 * nc) };
                mma_f16(scc[nc], ah, bh);
                mma_f16(scl[nc], al, bh);
                mma_f16(scl[nc], ah, bl);
            }
        }
        __syncthreads();
    }

    // epilogue: apply attention scale (log2 domain) and write pre-split Q
    bool va = (r0 + r_a < rend), vb = (r0 + r_b < rend);
    size_t sa = (size_t)s_slot[r_a] * (HD / 2);
    size_t sb = (size_t)s_slot[r_b] * (HD / 2);
#pragma unroll
    for (int nc = 0; nc < 8; nc++) {
        int p = ch * 32 + 4 * nc + tg;
        float o0 = (scc[nc][0] + scl[nc][0] * LO_INV) * QSC;
        float o1 = (scc[nc][1] + scl[nc][1] * LO_INV) * QSC;
        float o2 = (scc[nc][2] + scl[nc][2] * LO_INV) * QSC;
        float o3 = (scc[nc][3] + scl[nc][3] * LO_INV) * QSC;
        __half2 hh, ll;
        if (va) {
            h2split(o0, o1, hh, ll);
            g_qh2[sa + p] = hh;
            g_ql2[sa + p] = ll;
        }
        if (vb) {
            h2split(o2, o3, hh, ll);
            g_qh2[sb + p] = hh;
            g_ql2[sb + p] = ll;
        }
    }
}

// ---------------------------------------------------------------------------
// Kernel 6: flash attention — cp.async double-buffered K/V, Q pre-split in
// global (pure copy load), f16-compensated QK, log2 softmax, P in registers,
// f16 PV, f16 attn-out.
// ---------------------------------------------------------------------------
constexpr int QT = 128;
constexpr int KT = 64;
constexpr int QH_STR  = 68;
constexpr int KH_STR  = 72;
constexpr int VT2_STR = 36;
constexpr int KBUF = 64 * KH_STR;
constexpr int VBUF = HD * VT2_STR;

__global__ __launch_bounds__(256, 1) void attn_kernel()
{
    extern __shared__ __half2 smh[];
    __half2* Qhi  = smh;                      // 128*68
    __half2* Qlo  = Qhi  + QT * QH_STR;       // 128*68
    __half2* Khi  = Qlo  + QT * QH_STR;       // 2 * 64*72
    __half2* Klo  = Khi  + 2 * KBUF;          // 2 * 64*72
    __half2* VhT2 = Klo  + 2 * KBUF;          // 2 * 128*36

    int tid  = threadIdx.x;
    int warp = tid >> 5, lane = tid & 31;
    int g = lane >> 2, tg = lane & 3;
    int n0 = blockIdx.x * QT;
    int h  = blockIdx.y;
    int b  = blockIdx.z;
    int bN0 = b * N;

    // Q tile: pure cp.async copies from pre-split, pre-scaled global
    for (int idx = tid; idx < QT * 16; idx += 256) {
        int r = idx >> 4, pq = (idx & 15) * 4;
        size_t src = ((size_t)(bN0 + n0 + r) * H + h) * (HD / 2) + pq;
        cp16(Qhi + r * QH_STR + pq, g_qh2 + src);
        cp16(Qlo + r * QH_STR + pq, g_ql2 + src);
    }

    // prefetch tile 0 into buffer 0 (same commit group as Q)
    {
        for (int idx = tid; idx < 64 * 16; idx += 256) {
            int p = idx >> 4, mq = (idx & 15) * 4;
            cp16(Khi + p * KH_STR + mq, g_kh2 + (size_t)p * BN_TOK + bN0 + mq);
            cp16(Klo + p * KH_STR + mq, g_kl2 + (size_t)p * BN_TOK + bN0 + mq);
        }
        int tp0 = bN0 >> 1;
        for (int idx = tid; idx < HD * 8; idx += 256) {
            int k = idx >> 3, tq = (idx & 7) * 4;
            cp16(VhT2 + k * VT2_STR + tq, g_vh2 + (size_t)k * (BN_TOK / 2) + tp0 + tq);
        }
        cp_commit();
    }

    const int r_a = warp * 16 + g;
    const int r_b = r_a + 8;

    float o[16][4];
#pragma unroll
    for (int nc = 0; nc < 16; nc++)
#pragma unroll
        for (int j = 0; j < 4; j++) o[nc][j] = 0.f;
    float m_a = -1e30f, m_b = -1e30f, l_a = 0.f, l_b = 0.f;

    for (int it = 0; it < N / KT; it++) {
        int buf = it & 1;
        cp_wait0();
        __syncthreads();

        if (it + 1 < N / KT) {
            int m0n = (it + 1) * KT;
            int bn = buf ^ 1;
            __half2* KhiN = Khi + bn * KBUF;
            __half2* KloN = Klo + bn * KBUF;
            __half2* VN   = VhT2 + bn * VBUF;
            for (int idx = tid; idx < 64 * 16; idx += 256) {
                int p = idx >> 4, mq = (idx & 15) * 4;
                cp16(KhiN + p * KH_STR + mq, g_kh2 + (size_t)p * BN_TOK + bN0 + m0n + mq);
                cp16(KloN + p * KH_STR + mq, g_kl2 + (size_t)p * BN_TOK + bN0 + m0n + mq);
            }
            int tp0 = (bN0 + m0n) >> 1;
            for (int idx = tid; idx < HD * 8; idx += 256) {
                int k = idx >> 3, tq = (idx & 7) * 4;
                cp16(VN + k * VT2_STR + tq, g_vh2 + (size_t)k * (BN_TOK / 2) + tp0 + tq);
            }
            cp_commit();
        }

        __half2* KhiB = Khi + buf * KBUF;
        __half2* KloB = Klo + buf * KBUF;
        __half2* VB   = VhT2 + buf * VBUF;

        // ---- S = Q K^T : f16 compensated, k16 steps ----
        float scc[8][4] = {};
        float scl[8][4] = {};
#pragma unroll
        for (int ks = 0; ks < 8; ks++) {
            const __half2* qh0 = Qhi + r_a * QH_STR + 8 * ks + tg;
            const __half2* qh1 = Qhi + r_b * QH_STR + 8 * ks + tg;
            const __half2* ql0 = Qlo + r_a * QH_STR + 8 * ks + tg;
            const __half2* ql1 = Qlo + r_b * QH_STR + 8 * ks + tg;
            uint32_t ah[4] = { *reinterpret_cast<const uint32_t*>(qh0),
                               *reinterpret_cast<const uint32_t*>(qh1),
                               *reinterpret_cast<const uint32_t*>(qh0 + 4),
                               *reinterpret_cast<const uint32_t*>(qh1 + 4) };
            uint32_t al[4] = { *reinterpret_cast<const uint32_t*>(ql0),
                               *reinterpret_cast<const uint32_t*>(ql1),
                               *reinterpret_cast<const uint32_t*>(ql0 + 4),
                               *reinterpret_cast<const uint32_t*>(ql1 + 4) };
            const __half2* kh0 = KhiB + (8 * ks + tg) * KH_STR + g;
            const __half2* kh1 = KhiB + (8 * ks + 4 + tg) * KH_STR + g;
            const __half2* kl0 = KloB + (8 * ks + tg) * KH_STR + g;
            const __half2* kl1 = KloB + (8 * ks + 4 + tg) * KH_STR + g;
#pragma unroll
            for (int nc = 0; nc < 8; nc++) {
                uint32_t bh[2] = { *reinterpret_cast<const uint32_t*>(kh0 + 8 * nc),
                                   *reinterpret_cast<const uint32_t*>(kh1 + 8 * nc) };
                uint32_t bl[2] = { *reinterpret_cast<const uint32_t*>(kl0 + 8 * nc),
                                   *reinterpret_cast<const uint32_t*>(kl1 + 8 * nc) };
                mma_f16(scc[nc], ah, bh);
                mma_f16(scl[nc], al, bh);
                mma_f16(scl[nc], ah, bl);
            }
        }
#pragma unroll
        for (int nc = 0; nc < 8; nc++)
#pragma unroll
            for (int j = 0; j < 4; j++)
                scc[nc][j] += scl[nc][j] * LO_INV;

        // ---- online softmax (log2 domain, f16x2 ex2); P in registers ----
        float lm_a = -1e30f, lm_b = -1e30f;
#pragma unroll
        for (int nc = 0; nc < 8; nc++) {
            lm_a = fmaxf(lm_a, fmaxf(scc[nc][0], scc[nc][1]));
            lm_b = fmaxf(lm_b, fmaxf(scc[nc][2], scc[nc][3]));
        }
#pragma unroll
        for (int off = 1; off <= 2; off <<= 1) {
            lm_a = fmaxf(lm_a, __shfl_xor_sync(0xffffffffu, lm_a, off));
            lm_b = fmaxf(lm_b, __shfl_xor_sync(0xffffffffu, lm_b, off));
        }
        float mn_a = fmaxf(m_a, lm_a), mn_b = fmaxf(m_b, lm_b);
        float al_a = exp2f(m_a - mn_a), al_b = exp2f(m_b - mn_b);
        m_a = mn_a; m_b = mn_b;

        uint32_t pha[8], phb[8];
        float rs_a = 0.f, rs_b = 0.f;
#pragma unroll
        for (int nc = 0; nc < 8; nc++) {
            __half2 ha = h2exp2(__floats2half2_rn(scc[nc][0] - mn_a, scc[nc][1] - mn_a));
            __half2 hb = h2exp2(__floats2half2_rn(scc[nc][2] - mn_b, scc[nc][3] - mn_b));
            pha[nc] = *reinterpret_cast<uint32_t*>(&ha);
            phb[nc] = *reinterpret_cast<uint32_t*>(&hb);
            float2 fa = __half22float2(ha);
            float2 fb = __half22float2(hb);
            rs_a += fa.x + fa.y;
            rs_b += fb.x + fb.y;
        }
#pragma unroll
        for (int off = 1; off <= 2; off <<= 1) {
            rs_a += __shfl_xor_sync(0xffffffffu, rs_a, off);
            rs_b += __shfl_xor_sync(0xffffffffu, rs_b, off);
        }
        l_a = l_a * al_a + rs_a;
        l_b = l_b * al_b + rs_b;
#pragma unroll
        for (int nc = 0; nc < 16; nc++) {
            o[nc][0] *= al_a; o[nc][1] *= al_a;
            o[nc][2] *= al_b; o[nc][3] *= al_b;
        }

        // ---- O += P V ----
#pragma unroll
        for (int ks = 0; ks < 4; ks++) {
            uint32_t a[4] = { pha[2 * ks], phb[2 * ks], pha[2 * ks + 1], phb[2 * ks + 1] };
#pragma unroll
            for (int nc = 0; nc < 16; nc++) {
                const __half2* vb = VB + (8 * nc + g) * VT2_STR + 8 * ks + tg;
                uint32_t bb[2];
                bb[0] = *reinterpret_cast<const uint32_t*>(vb);
                bb[1] = *reinterpret_cast<const uint32_t*>(vb + 4);
                mma_f16(o[nc], a, bb);
            }
        }
    }

    float inv_a = 1.f / l_a, inv_b = 1.f / l_b;
    __half2* dsta = g_attno2 + (((size_t)(bN0 + n0 + r_a)) * H + h) * (HD / 2);
    __half2* dstb = g_attno2 + (((size_t)(bN0 + n0 + r_b)) * H + h) * (HD / 2);
#pragma unroll
    for (int nc = 0; nc < 16; nc++) {
        int p = 4 * nc + tg;
        dsta[p] = __floats2half2_rn(o[nc][0] * inv_a, o[nc][1] * inv_a);
        dstb[p] = __floats2half2_rn(o[nc][2] * inv_b, o[nc][3] * inv_b);
    }
}

// ---------------------------------------------------------------------------
// Kernel 7: grouped combine GEMM — single-pass f16, cp.async loads,
// f16 output scratch.
// ---------------------------------------------------------------------------
constexpr int CA_STR = 68;
constexpr int CB_STR = 136;

__global__ __launch_bounds__(256, 2) void cgemm_kernel()
{
    extern __shared__ __half2 csm[];
    __half2* A2 = csm;                  // 128*68
    __half2* B2 = A2 + TQ * CA_STR;     // 64*136
    int*   s_slot = reinterpret_cast<int*>(B2 + 64 * CB_STR);
    float* s_gate = reinterpret_cast<float*>(s_slot + TQ);

    int t = blockIdx.x;
    if (t >= g_ntiles) return;
    int n0 = blockIdx.y * 128;
    int e = g_tile_e[t], r0 = g_tile_r0[t];
    int rend = g_eoff[e + 1];
    int tid = threadIdx.x;

    if (tid < TQ) {
        int gr = r0 + tid;
        if (gr >= rend) gr = r0;
        int s = g_slots[gr];
        s_slot[tid] = s;
        s_gate[tid] = g_gates[s];
    }
    __syncthreads();

    for (int idx = tid; idx < TQ * 16; idx += 256) {
        int r = idx >> 4, pq = (idx & 15) * 4;
        cp16(A2 + r * CA_STR + pq, g_attno2 + (size_t)s_slot[r] * (HD / 2) + pq);
    }
    for (int idx = tid; idx < 64 * 32; idx += 256) {
        int p = idx >> 5, nq = (idx & 31) * 4;
        cp16(B2 + p * CB_STR + nq, g_woh2 + ((size_t)e * (HD / 2) + p) * D + n0 + nq);
    }
    cp_commit();
    cp_wait0();
    __syncthreads();

    int warp = tid >> 5, lane = tid & 31;
    int g = lane >> 2, tg = lane & 3;
    int r_a = warp * 16 + g, r_b = r_a + 8;

    float acc[16][4] = {};

#pragma unroll
    for (int ks = 0; ks < 8; ks++) {
        const __half2* a0 = A2 + r_a * CA_STR + 8 * ks + tg;
        const __half2* a1 = A2 + r_b * CA_STR + 8 * ks + tg;
        uint32_t a[4] = { *reinterpret_cast<const uint32_t*>(a0),
                          *reinterpret_cast<const uint32_t*>(a1),
                          *reinterpret_cast<const uint32_t*>(a0 + 4),
                          *reinterpret_cast<const uint32_t*>(a1 + 4) };
        const __half2* b0 = B2 + (8 * ks + tg) * CB_STR + g;
        const __half2* b1 = B2 + (8 * ks + 4 + tg) * CB_STR + g;
#pragma unroll
        for (int nc = 0; nc < 16; nc++) {
            uint32_t bb[2] = { *reinterpret_cast<const uint32_t*>(b0 + 8 * nc),
                               *reinterpret_cast<const uint32_t*>(b1 + 8 * nc) };
            mma_f16(acc[nc], a, bb);
        }
    }

    bool va = (r0 + r_a < rend), vb = (r0 + r_b < rend);
    float ga = s_gate[r_a], gb = s_gate[r_b];
    __half2* da = g_ws2 + (size_t)s_slot[r_a] * (D / 2) + (n0 >> 1);
    __half2* db = g_ws2 + (size_t)s_slot[r_b] * (D / 2) + (n0 >> 1);
#pragma unroll
    for (int nc = 0; nc < 16; nc++) {
        int p = 4 * nc + tg;
        if (va) da[p] = __floats2half2_rn(acc[nc][0] * ga, acc[nc][1] * ga);
        if (vb) db[p] = __floats2half2_rn(acc[nc][2] * gb, acc[nc][3] * gb);
    }
}

// ---------------------------------------------------------------------------
// Kernel 8: reduce 8 slot rows per token → y  (f16 in, f32 out)
// ---------------------------------------------------------------------------
__global__ __launch_bounds__(256) void reduce_kernel(float* __restrict__ y)
{
    int t = blockIdx.x;
    int p = threadIdx.x * 2;
    float4 s = make_float4(0.f, 0.f, 0.f, 0.f);
#pragma unroll
    for (int h = 0; h < H; h++) {
        const __half2* w = g_ws2 + ((size_t)(t * H + h)) * (D / 2) + p;
        float2 a = __half22float2(w[0]);
        float2 b2 = __half22float2(w[1]);
        s.x += a.x; s.y += a.y; s.z += b2.x; s.w += b2.y;
    }
    *reinterpret_cast<float4*>(y + (size_t)t * D + p * 2) = s;
}

// ---------------------------------------------------------------------------
// Kernel 9: finalize aux loss
// ---------------------------------------------------------------------------
__global__ void aux_final_kernel(float* __restrict__ out) {
    if (threadIdx.x == 0) {
        const float inv_bn = 1.0f / (float)BN_TOK;
        float sw = 0.f;
        for (int e = 0; e < E; e++)
            sw += (g_aux[e] * inv_bn) * (g_aux[E + e] * inv_bn);
        float aux = 0.1f * (float)E * sw + 0.001f * (g_aux[2 * E] * inv_bn);
        out[(size_t)BN_TOK * D] = aux;
    }
}

// ---------------------------------------------------------------------------
// Launch
// ---------------------------------------------------------------------------
extern "C" void kernel_launch(void* const* d_in, const int* in_sizes, int n_in,
                              void* d_out, int out_size)
{
    const float* x    = (const float*)d_in[0];
    const int* task_bh = (const int*)d_in[1];
    const float* Wg   = (const float*)d_in[2];
    const float* Wq   = (const float*)d_in[3];
    const float* Wo   = (const float*)d_in[4];
    const float* Wkv  = (const float*)d_in[5];
    const float* bkv  = (const float*)d_in[6];
    float* out = (float*)d_out;

    const int attn_smem = (2 * QT * QH_STR + 4 * KBUF + 2 * VBUF) * 4;
    const int qg_smem = (4 * QABUF + 4 * QBBUF) * 4 + 2 * TQ * 4;
    const int cg_smem = (TQ * CA_STR + 64 * CB_STR) * 4 + 2 * TQ * 4;
    const int gate_smem = D * E * 4;
    cudaFuncSetAttribute(attn_kernel,   cudaFuncAttributeMaxDynamicSharedMemorySize, attn_smem);
    cudaFuncSetAttribute(qgemm_kernel,  cudaFuncAttributeMaxDynamicSharedMemorySize, qg_smem);
    cudaFuncSetAttribute(kvmma_kernel,  cudaFuncAttributeMaxDynamicSharedMemorySize, qg_smem);
    cudaFuncSetAttribute(cgemm_kernel,  cudaFuncAttributeMaxDynamicSharedMemorySize, cg_smem);
    cudaFuncSetAttribute(gating_kernel, cudaFuncAttributeMaxDynamicSharedMemorySize, gate_smem);

    init_aux_kernel<<<1, 64>>>();
    xsplit_kernel<<<BN_TOK, 256>>>(x);
    wqsplit_kernel<<<dim3(D / 2, E), 128>>>(Wq);
    wosplit_kernel<<<dim3(HD / 2, E), 256>>>(Wo);
    wkvsplit_kernel<<<D / 2, 256>>>(Wkv);
    gating_kernel<<<BN_TOK / 8, 256, gate_smem>>>(x, task_bh, Wg);
    scan_kernel<<<1, 32>>>();
    scatter_kernel<<<NSLOT / 256, 256>>>();
    kvmma_kernel<<<dim3(BN_TOK / TQ, 2), 512, qg_smem>>>(bkv);
    qgemm_kernel<<<NT_MAX, 512, qg_smem>>>();
    attn_kernel<<<dim3(N / QT, H, B), 256, attn_smem>>>();
    cgemm_kernel<<<dim3(NT_MAX, 8), 256, cg_smem>>>();
    reduce_kernel<<<BN_TOK, 256>>>(out);
    aux_final_kernel<<<1, 32>>>(out);
}